// round 6
// baseline (speedup 1.0000x reference)
#include <cuda_runtime.h>
#include <math.h>

#define SQ   512
#define HD   768
#define NHH  12
#define DHH  64
#define BHH  48          // B * NH
#define FFD  3072
#define NCLS 9
#define NLAYER 12
#define NTOK 2048        // B * S
#define SCALEF 0.07216878364870323f   // 1/sqrt(64*3)

// ---------------- scratch (allocation-free: __device__ globals) ----------------
__device__ float g_x[NTOK * HD];
__device__ float g_q[BHH * SQ * DHH];
__device__ float g_k[BHH * SQ * DHH];
__device__ float g_v[BHH * SQ * DHH];
__device__ float g_pk[NHH * SQ * DHH];
__device__ float g_pq[NHH * SQ * DHH];
__device__ float g_rel[SQ * HD];
__device__ float g_s0[BHH * SQ * SQ];
__device__ float g_c2p[BHH * SQ * SQ];
__device__ float g_p2c[BHH * SQ * SQ];
__device__ float g_t1[NTOK * FFD];
__device__ float g_t2[NTOK * HD];
__device__ int   g_ic2p[SQ * SQ];
__device__ int   g_ip2c[SQ * SQ];

// Buffer selector so host code never needs cudaGetSymbolAddress.
#define BUF_X   0
#define BUF_Q   1
#define BUF_K   2
#define BUF_V   3
#define BUF_PK  4
#define BUF_PQ  5
#define BUF_REL 6
#define BUF_T1  10
#define BUF_T2  11
#define BUF_EXT (-1)

__device__ __forceinline__ float* bufptr(int c) {
    switch (c) {
        case BUF_X:   return g_x;
        case BUF_Q:   return g_q;
        case BUF_K:   return g_k;
        case BUF_V:   return g_v;
        case BUF_PK:  return g_pk;
        case BUF_PQ:  return g_pq;
        case BUF_REL: return g_rel;
        case BUF_T1:  return g_t1;
        case BUF_T2:  return g_t2;
    }
    return 0;
}

// ---------------- block reductions (256 threads) ----------------
__device__ __forceinline__ float blk_reduce_sum(float v) {
    __shared__ float red[256];
    int tid = threadIdx.x;
    red[tid] = v; __syncthreads();
    for (int s = 128; s > 0; s >>= 1) {
        if (tid < s) red[tid] += red[tid + s];
        __syncthreads();
    }
    float r = red[0]; __syncthreads();
    return r;
}

__device__ __forceinline__ float blk_reduce_max(float v) {
    __shared__ float redm[256];
    int tid = threadIdx.x;
    redm[tid] = v; __syncthreads();
    for (int s = 128; s > 0; s >>= 1) {
        if (tid < s) redm[tid] = fmaxf(redm[tid], redm[tid + s]);
        __syncthreads();
    }
    float r = redm[0]; __syncthreads();
    return r;
}

// ---------------- relative position bucket indices ----------------
__global__ void relidx_kernel() {
    int idx = blockIdx.x * blockDim.x + threadIdx.x;
    if (idx >= SQ * SQ) return;
    int i = idx >> 9, j = idx & 511;
    int rel = i - j;
    int bucket;
    if (rel >= -128 && rel <= 128) {
        bucket = rel;
    } else {
        float abs_pos = fabsf((float)rel);
        float log_pos = ceilf(logf(abs_pos / 128.0f) / logf(511.0f / 128.0f) * 127.0f) + 128.0f;
        bucket = (int)(rel > 0 ? log_pos : -log_pos);
    }
    int c = bucket + 256; c = c < 0 ? 0 : (c > 511 ? 511 : c);
    int p = -bucket + 256; p = p < 0 ? 0 : (p > 511 ? 511 : p);
    g_ic2p[idx] = c;
    g_ip2c[idx] = p;
}

// ---------------- embedding gather + LN * mask ----------------
__global__ void embed_ln_kernel(const int* __restrict__ ids, const int* __restrict__ mask,
                                const float* __restrict__ we, const float* __restrict__ te,
                                const float* __restrict__ lns, const float* __restrict__ lnb) {
    int r = blockIdx.x, tid = threadIdx.x;
    size_t id = (size_t)ids[r];
    float v[3];
#pragma unroll
    for (int t = 0; t < 3; t++) {
        int c = tid + t * 256;
        v[t] = we[id * HD + c] + te[c];
    }
    float mu = blk_reduce_sum(v[0] + v[1] + v[2]) * (1.0f / HD);
    float sq = 0.f;
#pragma unroll
    for (int t = 0; t < 3; t++) { float d = v[t] - mu; sq += d * d; }
    float var = blk_reduce_sum(sq) * (1.0f / HD);
    float inv = rsqrtf(var + 1e-7f);
    float mf = (float)mask[r];
#pragma unroll
    for (int t = 0; t < 3; t++) {
        int c = tid + t * 256;
        g_x[(size_t)r * HD + c] = ((v[t] - mu) * inv * lns[c] + lnb[c]) * mf;
    }
}

// ---------------- LN of relative embeddings ----------------
__global__ void rel_ln_kernel(const float* __restrict__ re,
                              const float* __restrict__ lns, const float* __restrict__ lnb) {
    int r = blockIdx.x, tid = threadIdx.x;
    float v[3];
#pragma unroll
    for (int t = 0; t < 3; t++) v[t] = re[(size_t)r * HD + tid + t * 256];
    float mu = blk_reduce_sum(v[0] + v[1] + v[2]) * (1.0f / HD);
    float sq = 0.f;
#pragma unroll
    for (int t = 0; t < 3; t++) { float d = v[t] - mu; sq += d * d; }
    float var = blk_reduce_sum(sq) * (1.0f / HD);
    float inv = rsqrtf(var + 1e-7f);
#pragma unroll
    for (int t = 0; t < 3; t++) {
        int c = tid + t * 256;
        g_rel[(size_t)r * HD + c] = (v[t] - mu) * inv * lns[c] + lnb[c];
    }
}

// ---------------- residual + LN (in place on g_x): x = LN(x + buf[tcode]) ----------------
__global__ void add_ln_kernel(int tcode,
                              const float* __restrict__ lns, const float* __restrict__ lnb) {
    const float* t = bufptr(tcode);
    int r = blockIdx.x, tid = threadIdx.x;
    float v[3];
#pragma unroll
    for (int c2 = 0; c2 < 3; c2++) {
        int c = tid + c2 * 256;
        v[c2] = g_x[(size_t)r * HD + c] + t[(size_t)r * HD + c];
    }
    float mu = blk_reduce_sum(v[0] + v[1] + v[2]) * (1.0f / HD);
    float sq = 0.f;
#pragma unroll
    for (int c2 = 0; c2 < 3; c2++) { float d = v[c2] - mu; sq += d * d; }
    float var = blk_reduce_sum(sq) * (1.0f / HD);
    float inv = rsqrtf(var + 1e-7f);
#pragma unroll
    for (int c2 = 0; c2 < 3; c2++) {
        int c = tid + c2 * 256;
        g_x[(size_t)r * HD + c] = (v[c2] - mu) * inv * lns[c] + lnb[c];
    }
}

// ---------------- generic SGEMM: C = A[M,K] @ B[K,N] + bias ----------------
// A = buf[acode]; C = buf[ccode] or Cext when ccode < 0.
// MODE 0: plain store; MODE 1: exact GELU; MODE 2: head-major scatter
// (row m = b*512+s, col n = h*64+d -> out[((b*12+h)*512+s)*64+d])
template<int MODE>
__global__ void __launch_bounds__(256)
sgemm_kernel(int acode, const float* __restrict__ Bm,
             const float* __restrict__ bias, int ccode, float* __restrict__ Cext,
             int M, int N, int K) {
    const float* A = bufptr(acode);
    float* C = (ccode < 0) ? Cext : bufptr(ccode);
    __shared__ float As[16][68];
    __shared__ float Bs[16][68];
    int bm = blockIdx.y * 64, bn = blockIdx.x * 64;
    int tid = threadIdx.x;
    int tr = tid >> 4, tc = tid & 15;
    float acc[4][4] = {};
#pragma unroll 1
    for (int k0 = 0; k0 < K; k0 += 16) {
#pragma unroll
        for (int i = tid; i < 1024; i += 256) {
            int m = i >> 4, kk = i & 15;
            As[kk][m] = A[(size_t)(bm + m) * K + k0 + kk];
        }
#pragma unroll
        for (int i = tid; i < 1024; i += 256) {
            int kk = i >> 6, n = i & 63;
            Bs[kk][n] = (bn + n < N) ? Bm[(size_t)(k0 + kk) * N + bn + n] : 0.f;
        }
        __syncthreads();
#pragma unroll
        for (int kk = 0; kk < 16; kk++) {
            float4 a4 = *(const float4*)&As[kk][tr * 4];
            float4 b4 = *(const float4*)&Bs[kk][tc * 4];
            float a[4] = {a4.x, a4.y, a4.z, a4.w};
            float b[4] = {b4.x, b4.y, b4.z, b4.w};
#pragma unroll
            for (int i2 = 0; i2 < 4; i2++)
#pragma unroll
                for (int j = 0; j < 4; j++) acc[i2][j] += a[i2] * b[j];
        }
        __syncthreads();
    }
#pragma unroll
    for (int i2 = 0; i2 < 4; i2++) {
        int m = bm + tr * 4 + i2;
#pragma unroll
        for (int j = 0; j < 4; j++) {
            int n = bn + tc * 4 + j;
            if (n >= N) continue;
            float v = acc[i2][j] + bias[n];
            if (MODE == 1) v = 0.5f * v * (1.0f + erff(v * 0.70710678118654752f));
            if (MODE == 2) {
                int b = m >> 9, s2 = m & 511, h = n >> 6, d = n & 63;
                C[(((size_t)b * NHH + h) * SQ + s2) * DHH + d] = v;
            } else {
                C[(size_t)m * N + n] = v;
            }
        }
    }
}

// ---------------- batched NT GEMM: C[bh][m][n] = sum_d A[bh][m][d]*B[bh%bmod][n][d] ----------------
// acode/bcode select A,B buffers; ccode 0->g_s0, 1->g_c2p, 2->g_p2c
__global__ void __launch_bounds__(256)
bgemm_nt_kernel(int acode, int bcode, int ccode, int bmod) {
    int bh = blockIdx.z;
    const float* Ab = bufptr(acode) + (size_t)bh * SQ * DHH;
    const float* Bb = bufptr(bcode) + (size_t)(bh % bmod) * SQ * DHH;
    float* Cb = (ccode == 0 ? g_s0 : (ccode == 1 ? g_c2p : g_p2c)) + (size_t)bh * SQ * SQ;
    int bm = blockIdx.y * 64, bn = blockIdx.x * 64;
    __shared__ float As[16][68];
    __shared__ float Bs[16][68];
    int tid = threadIdx.x, tr = tid >> 4, tc = tid & 15;
    float acc[4][4] = {};
#pragma unroll 1
    for (int k0 = 0; k0 < DHH; k0 += 16) {
#pragma unroll
        for (int i = tid; i < 1024; i += 256) {
            int m = i >> 4, kk = i & 15;
            As[kk][m] = Ab[(size_t)(bm + m) * DHH + k0 + kk];
            Bs[kk][m] = Bb[(size_t)(bn + m) * DHH + k0 + kk];
        }
        __syncthreads();
#pragma unroll
        for (int kk = 0; kk < 16; kk++) {
            float4 a4 = *(const float4*)&As[kk][tr * 4];
            float4 b4 = *(const float4*)&Bs[kk][tc * 4];
            float a[4] = {a4.x, a4.y, a4.z, a4.w};
            float b[4] = {b4.x, b4.y, b4.z, b4.w};
#pragma unroll
            for (int i2 = 0; i2 < 4; i2++)
#pragma unroll
                for (int j = 0; j < 4; j++) acc[i2][j] += a[i2] * b[j];
        }
        __syncthreads();
    }
#pragma unroll
    for (int i2 = 0; i2 < 4; i2++) {
        float4 o = make_float4(acc[i2][0], acc[i2][1], acc[i2][2], acc[i2][3]);
        *(float4*)&Cb[(size_t)(bm + tr * 4 + i2) * SQ + bn + tc * 4] = o;
    }
}

// ---------------- attention combine + gather + mask + softmax (in place on g_s0) ----------------
__global__ void attn_softmax_kernel(const int* __restrict__ mask) {
    int q = blockIdx.x, bh = blockIdx.y, b = bh / NHH;
    int tid = threadIdx.x;
    float* row = g_s0 + ((size_t)bh * SQ + q) * SQ;
    const float* crow = g_c2p + ((size_t)bh * SQ + q) * SQ;
    const float* pbase = g_p2c + (size_t)bh * SQ * SQ;
    int mq = mask[b * SQ + q];
    float vals[2];
    float mx = -3.4028234663852886e38f;
#pragma unroll
    for (int t = 0; t < 2; t++) {
        int k = tid + t * 256;
        float v = -3.4028234663852886e38f;
        if (mq != 0 && mask[b * SQ + k] != 0) {
            v = (row[k] + crow[g_ic2p[q * SQ + k]] + pbase[(size_t)k * SQ + g_ip2c[k * SQ + q]]) * SCALEF;
        }
        vals[t] = v;
        mx = fmaxf(mx, v);
    }
    mx = blk_reduce_max(mx);
    float sum = 0.f;
#pragma unroll
    for (int t = 0; t < 2; t++) { vals[t] = expf(vals[t] - mx); sum += vals[t]; }
    sum = blk_reduce_sum(sum);
    float inv = 1.0f / sum;
#pragma unroll
    for (int t = 0; t < 2; t++) row[tid + t * 256] = vals[t] * inv;
}

// ---------------- batched NN GEMM: ctx = probs @ v, scatter to [B,S,H] in g_t2 ----------------
__global__ void __launch_bounds__(256)
bgemm_ctx_kernel() {
    int bh = blockIdx.z, b = bh / NHH, h = bh % NHH;
    const float* Pb = g_s0 + (size_t)bh * SQ * SQ;
    const float* Vb = g_v + (size_t)bh * SQ * DHH;
    int bm = blockIdx.y * 64;
    __shared__ float As[16][68];
    __shared__ float Bs[16][68];
    int tid = threadIdx.x, tr = tid >> 4, tc = tid & 15;
    float acc[4][4] = {};
#pragma unroll 1
    for (int k0 = 0; k0 < SQ; k0 += 16) {
#pragma unroll
        for (int i = tid; i < 1024; i += 256) {
            int m = i >> 4, kk = i & 15;
            As[kk][m] = Pb[(size_t)(bm + m) * SQ + k0 + kk];
        }
#pragma unroll
        for (int i = tid; i < 1024; i += 256) {
            int kk = i >> 6, n = i & 63;
            Bs[kk][n] = Vb[(size_t)(k0 + kk) * DHH + n];
        }
        __syncthreads();
#pragma unroll
        for (int kk = 0; kk < 16; kk++) {
            float4 a4 = *(const float4*)&As[kk][tr * 4];
            float4 b4 = *(const float4*)&Bs[kk][tc * 4];
            float a[4] = {a4.x, a4.y, a4.z, a4.w};
            float b[4] = {b4.x, b4.y, b4.z, b4.w};
#pragma unroll
            for (int i2 = 0; i2 < 4; i2++)
#pragma unroll
                for (int j = 0; j < 4; j++) acc[i2][j] += a[i2] * b[j];
        }
        __syncthreads();
    }
#pragma unroll
    for (int i2 = 0; i2 < 4; i2++) {
        int m = bm + tr * 4 + i2;
#pragma unroll
        for (int j = 0; j < 4; j++) {
            g_t2[((size_t)(b * SQ + m)) * HD + h * DHH + tc * 4 + j] = acc[i2][j];
        }
    }
}

// ---------------- launch ----------------
extern "C" void kernel_launch(void* const* d_in, const int* in_sizes, int n_in,
                              void* d_out, int out_size) {
    const int*   ids     = (const int*)d_in[0];
    const int*   mask    = (const int*)d_in[1];
    const float* we      = (const float*)d_in[2];
    const float* te      = (const float*)d_in[3];
    const float* elns    = (const float*)d_in[4];
    const float* elnb    = (const float*)d_in[5];
    const float* rel_emb = (const float*)d_in[6];
    const float* rlns    = (const float*)d_in[7];
    const float* rlnb    = (const float*)d_in[8];
    const float* qw      = (const float*)d_in[9];
    const float* qb      = (const float*)d_in[10];
    const float* kw      = (const float*)d_in[11];
    const float* kb      = (const float*)d_in[12];
    const float* vw      = (const float*)d_in[13];
    const float* vb      = (const float*)d_in[14];
    const float* aow     = (const float*)d_in[15];
    const float* aob     = (const float*)d_in[16];
    const float* alns    = (const float*)d_in[17];
    const float* alnb    = (const float*)d_in[18];
    const float* iw      = (const float*)d_in[19];
    const float* ib      = (const float*)d_in[20];
    const float* ow      = (const float*)d_in[21];
    const float* ob      = (const float*)d_in[22];
    const float* olns    = (const float*)d_in[23];
    const float* olnb    = (const float*)d_in[24];
    const float* clsw    = (const float*)d_in[25];
    const float* clsb    = (const float*)d_in[26];
    float* out = (float*)d_out;

    relidx_kernel<<<1024, 256>>>();
    rel_ln_kernel<<<SQ, 256>>>(rel_emb, rlns, rlnb);
    embed_ln_kernel<<<NTOK, 256>>>(ids, mask, we, te, elns, elnb);

    dim3 gProj(12, 32);   // 768x2048
    dim3 gPos(12, 8);     // 768x512
    dim3 gAttn(8, 8, BHH);
    dim3 gSm(SQ, BHH);
    dim3 gCtx(1, 8, BHH);
    dim3 gFF1(48, 32);    // 3072x2048
    dim3 gCls(1, 32);

    for (int l = 0; l < NLAYER; l++) {
        const float* qwl = qw + (size_t)l * HD * HD;
        const float* kwl = kw + (size_t)l * HD * HD;
        const float* vwl = vw + (size_t)l * HD * HD;
        const float* aowl = aow + (size_t)l * HD * HD;
        const float* iwl = iw + (size_t)l * HD * FFD;
        const float* owl = ow + (size_t)l * FFD * HD;
        const float* qbl = qb + (size_t)l * HD;
        const float* kbl = kb + (size_t)l * HD;
        const float* vbl = vb + (size_t)l * HD;
        const float* aobl = aob + (size_t)l * HD;
        const float* ibl = ib + (size_t)l * FFD;
        const float* obl = ob + (size_t)l * HD;

        sgemm_kernel<2><<<gProj, 256>>>(BUF_X, qwl, qbl, BUF_Q, 0, NTOK, HD, HD);
        sgemm_kernel<2><<<gProj, 256>>>(BUF_X, kwl, kbl, BUF_K, 0, NTOK, HD, HD);
        sgemm_kernel<2><<<gProj, 256>>>(BUF_X, vwl, vbl, BUF_V, 0, NTOK, HD, HD);
        sgemm_kernel<2><<<gPos, 256>>>(BUF_REL, kwl, kbl, BUF_PK, 0, SQ, HD, HD);
        sgemm_kernel<2><<<gPos, 256>>>(BUF_REL, qwl, qbl, BUF_PQ, 0, SQ, HD, HD);

        bgemm_nt_kernel<<<gAttn, 256>>>(BUF_Q, BUF_K, 0, BHH);   // q @ k^T  -> g_s0
        bgemm_nt_kernel<<<gAttn, 256>>>(BUF_Q, BUF_PK, 1, NHH);  // q @ pk^T -> g_c2p
        bgemm_nt_kernel<<<gAttn, 256>>>(BUF_K, BUF_PQ, 2, NHH);  // k @ pq^T -> g_p2c

        attn_softmax_kernel<<<gSm, 256>>>(mask);

        bgemm_ctx_kernel<<<gCtx, 256>>>();                       // -> g_t2 [B,S,H]

        sgemm_kernel<0><<<gProj, 256>>>(BUF_T2, aowl, aobl, BUF_T1, 0, NTOK, HD, HD);
        add_ln_kernel<<<NTOK, 256>>>(BUF_T1, alns + (size_t)l * HD, alnb + (size_t)l * HD);

        sgemm_kernel<1><<<gFF1, 256>>>(BUF_X, iwl, ibl, BUF_T1, 0, NTOK, FFD, HD);   // GELU
        sgemm_kernel<0><<<gProj, 256>>>(BUF_T1, owl, obl, BUF_T2, 0, NTOK, HD, FFD);
        add_ln_kernel<<<NTOK, 256>>>(BUF_T2, olns + (size_t)l * HD, olnb + (size_t)l * HD);
    }

    sgemm_kernel<0><<<gCls, 256>>>(BUF_X, clsw, clsb, BUF_EXT, out, NTOK, NCLS, HD);
}

// round 8
// speedup vs baseline: 1.0131x; 1.0131x over previous
#include <cuda_runtime.h>
#include <math.h>

#define SQ   512
#define HD   768
#define NHH  12
#define DHH  64
#define BHH  48          // B * NH
#define FFD  3072
#define NCLS 9
#define NLAYER 12
#define NTOK 2048        // B * S
#define SCALEF 0.07216878364870323f   // 1/sqrt(64*3)

// ---------------- scratch (allocation-free: __device__ globals) ----------------
__device__ float g_x[NTOK * HD];
__device__ float g_q[BHH * SQ * DHH];
__device__ float g_k[BHH * SQ * DHH];
__device__ float g_v[BHH * SQ * DHH];
__device__ float g_pk[NHH * SQ * DHH];
__device__ float g_pq[NHH * SQ * DHH];
__device__ float g_rel[SQ * HD];
__device__ float g_s0[BHH * SQ * SQ];
__device__ float g_c2p[BHH * SQ * SQ];
__device__ float g_p2c[BHH * SQ * SQ];
__device__ float g_t1[NTOK * FFD];
__device__ float g_t2[NTOK * HD];
__device__ int   g_ic2p[SQ * SQ];
__device__ int   g_ip2c[SQ * SQ];

// Buffer selector so host code never needs cudaGetSymbolAddress.
#define BUF_X   0
#define BUF_Q   1
#define BUF_K   2
#define BUF_V   3
#define BUF_PK  4
#define BUF_PQ  5
#define BUF_REL 6
#define BUF_T1  10
#define BUF_T2  11
#define BUF_EXT (-1)

__device__ __forceinline__ float* bufptr(int c) {
    switch (c) {
        case BUF_X:   return g_x;
        case BUF_Q:   return g_q;
        case BUF_K:   return g_k;
        case BUF_V:   return g_v;
        case BUF_PK:  return g_pk;
        case BUF_PQ:  return g_pq;
        case BUF_REL: return g_rel;
        case BUF_T1:  return g_t1;
        case BUF_T2:  return g_t2;
    }
    return 0;
}

// ---------------- block reductions (256 threads) ----------------
__device__ __forceinline__ float blk_reduce_sum(float v) {
    __shared__ float red[256];
    int tid = threadIdx.x;
    red[tid] = v; __syncthreads();
    for (int s = 128; s > 0; s >>= 1) {
        if (tid < s) red[tid] += red[tid + s];
        __syncthreads();
    }
    float r = red[0]; __syncthreads();
    return r;
}

__device__ __forceinline__ float blk_reduce_max(float v) {
    __shared__ float redm[256];
    int tid = threadIdx.x;
    redm[tid] = v; __syncthreads();
    for (int s = 128; s > 0; s >>= 1) {
        if (tid < s) redm[tid] = fmaxf(redm[tid], redm[tid + s]);
        __syncthreads();
    }
    float r = redm[0]; __syncthreads();
    return r;
}

// ---------------- relative position bucket indices ----------------
__global__ void relidx_kernel() {
    int idx = blockIdx.x * blockDim.x + threadIdx.x;
    if (idx >= SQ * SQ) return;
    int i = idx >> 9, j = idx & 511;
    int rel = i - j;
    int bucket;
    if (rel >= -128 && rel <= 128) {
        bucket = rel;
    } else {
        float abs_pos = fabsf((float)rel);
        float log_pos = ceilf(logf(abs_pos / 128.0f) / logf(511.0f / 128.0f) * 127.0f) + 128.0f;
        bucket = (int)(rel > 0 ? log_pos : -log_pos);
    }
    int c = bucket + 256; c = c < 0 ? 0 : (c > 511 ? 511 : c);
    int p = -bucket + 256; p = p < 0 ? 0 : (p > 511 ? 511 : p);
    g_ic2p[idx] = c;
    g_ip2c[idx] = p;
}

// ---------------- embedding gather + LN * mask ----------------
__global__ void embed_ln_kernel(const int* __restrict__ ids, const int* __restrict__ mask,
                                const float* __restrict__ we, const float* __restrict__ te,
                                const float* __restrict__ lns, const float* __restrict__ lnb) {
    int r = blockIdx.x, tid = threadIdx.x;
    size_t id = (size_t)ids[r];
    float v[3];
#pragma unroll
    for (int t = 0; t < 3; t++) {
        int c = tid + t * 256;
        v[t] = we[id * HD + c] + te[c];
    }
    float mu = blk_reduce_sum(v[0] + v[1] + v[2]) * (1.0f / HD);
    float sq = 0.f;
#pragma unroll
    for (int t = 0; t < 3; t++) { float d = v[t] - mu; sq += d * d; }
    float var = blk_reduce_sum(sq) * (1.0f / HD);
    float inv = rsqrtf(var + 1e-7f);
    float mf = (float)mask[r];
#pragma unroll
    for (int t = 0; t < 3; t++) {
        int c = tid + t * 256;
        g_x[(size_t)r * HD + c] = ((v[t] - mu) * inv * lns[c] + lnb[c]) * mf;
    }
}

// ---------------- LN of relative embeddings ----------------
__global__ void rel_ln_kernel(const float* __restrict__ re,
                              const float* __restrict__ lns, const float* __restrict__ lnb) {
    int r = blockIdx.x, tid = threadIdx.x;
    float v[3];
#pragma unroll
    for (int t = 0; t < 3; t++) v[t] = re[(size_t)r * HD + tid + t * 256];
    float mu = blk_reduce_sum(v[0] + v[1] + v[2]) * (1.0f / HD);
    float sq = 0.f;
#pragma unroll
    for (int t = 0; t < 3; t++) { float d = v[t] - mu; sq += d * d; }
    float var = blk_reduce_sum(sq) * (1.0f / HD);
    float inv = rsqrtf(var + 1e-7f);
#pragma unroll
    for (int t = 0; t < 3; t++) {
        int c = tid + t * 256;
        g_rel[(size_t)r * HD + c] = (v[t] - mu) * inv * lns[c] + lnb[c];
    }
}

// ---------------- residual + LN (in place on g_x): x = LN(x + buf[tcode]) ----------------
__global__ void add_ln_kernel(int tcode,
                              const float* __restrict__ lns, const float* __restrict__ lnb) {
    const float* t = bufptr(tcode);
    int r = blockIdx.x, tid = threadIdx.x;
    float v[3];
#pragma unroll
    for (int c2 = 0; c2 < 3; c2++) {
        int c = tid + c2 * 256;
        v[c2] = g_x[(size_t)r * HD + c] + t[(size_t)r * HD + c];
    }
    float mu = blk_reduce_sum(v[0] + v[1] + v[2]) * (1.0f / HD);
    float sq = 0.f;
#pragma unroll
    for (int c2 = 0; c2 < 3; c2++) { float d = v[c2] - mu; sq += d * d; }
    float var = blk_reduce_sum(sq) * (1.0f / HD);
    float inv = rsqrtf(var + 1e-7f);
#pragma unroll
    for (int c2 = 0; c2 < 3; c2++) {
        int c = tid + c2 * 256;
        g_x[(size_t)r * HD + c] = (v[c2] - mu) * inv * lns[c] + lnb[c];
    }
}

// ---------------- SGEMM: C = A[M,K] @ B[K,N] + bias ----------------
// 128x64 tile, 8x4 per thread, double-buffered smem, 1 barrier per K-step.
// MODE 0: plain store; MODE 1: exact GELU; MODE 2: head-major scatter
// (row m = b*512+s, col n = h*64+d -> out[((b*12+h)*512+s)*64+d])
template<int MODE>
__global__ void __launch_bounds__(256)
sgemm_kernel(int acode, const float* __restrict__ Bm,
             const float* __restrict__ bias, int ccode, float* __restrict__ Cext,
             int M, int N, int K) {
    const float* __restrict__ A = bufptr(acode);
    float* __restrict__ C = (ccode < 0) ? Cext : bufptr(ccode);
    __shared__ float As[2][16][132];
    __shared__ float Bs[2][16][68];
    const int bm = blockIdx.y * 128, bn = blockIdx.x * 64;
    const int tid = threadIdx.x;
    const int tr = tid >> 4, tc = tid & 15;        // 16x16 thread grid
    const int ar = tid >> 2;                       // A rows 0..63 (+64 for 2nd frag)
    const int ak = (tid & 3) * 4;                  // A k-offset (float4)
    const int bk = tid >> 4;                       // B row 0..15
    const int bn0 = (tid & 15) * 4;                // B n-offset (float4)
    const bool nfull = (bn + 64 <= N);

    const float* Ap0 = A + (size_t)(bm + ar) * K + ak;
    const float* Ap1 = Ap0 + (size_t)64 * K;

    float4 ra0, ra1, rb;
    const int nk = K >> 4;

    // ---- prologue: tile 0 ----
    ra0 = *(const float4*)Ap0;
    ra1 = *(const float4*)Ap1;
    if (nfull) {
        rb = *(const float4*)(Bm + (size_t)bk * N + bn + bn0);
    } else {
        rb.x = (bn + bn0 + 0 < N) ? Bm[(size_t)bk * N + bn + bn0 + 0] : 0.f;
        rb.y = (bn + bn0 + 1 < N) ? Bm[(size_t)bk * N + bn + bn0 + 1] : 0.f;
        rb.z = (bn + bn0 + 2 < N) ? Bm[(size_t)bk * N + bn + bn0 + 2] : 0.f;
        rb.w = (bn + bn0 + 3 < N) ? Bm[(size_t)bk * N + bn + bn0 + 3] : 0.f;
    }
    As[0][ak + 0][ar] = ra0.x;  As[0][ak + 1][ar] = ra0.y;
    As[0][ak + 2][ar] = ra0.z;  As[0][ak + 3][ar] = ra0.w;
    As[0][ak + 0][64 + ar] = ra1.x;  As[0][ak + 1][64 + ar] = ra1.y;
    As[0][ak + 2][64 + ar] = ra1.z;  As[0][ak + 3][64 + ar] = ra1.w;
    *(float4*)&Bs[0][bk][bn0] = rb;
    __syncthreads();

    float acc[8][4] = {};
    int buf = 0;
#pragma unroll 1
    for (int t = 0; t < nk; t++) {
        const int k0n = (t + 1) << 4;
        if (t + 1 < nk) {
            ra0 = *(const float4*)(Ap0 + k0n);
            ra1 = *(const float4*)(Ap1 + k0n);
            if (nfull) {
                rb = *(const float4*)(Bm + (size_t)(k0n + bk) * N + bn + bn0);
            } else {
                rb.x = (bn + bn0 + 0 < N) ? Bm[(size_t)(k0n + bk) * N + bn + bn0 + 0] : 0.f;
                rb.y = (bn + bn0 + 1 < N) ? Bm[(size_t)(k0n + bk) * N + bn + bn0 + 1] : 0.f;
                rb.z = (bn + bn0 + 2 < N) ? Bm[(size_t)(k0n + bk) * N + bn + bn0 + 2] : 0.f;
                rb.w = (bn + bn0 + 3 < N) ? Bm[(size_t)(k0n + bk) * N + bn + bn0 + 3] : 0.f;
            }
        }
#pragma unroll
        for (int kk = 0; kk < 16; kk++) {
            float4 a0 = *(const float4*)&As[buf][kk][tr * 8];
            float4 a1 = *(const float4*)&As[buf][kk][tr * 8 + 4];
            float4 b0 = *(const float4*)&Bs[buf][kk][tc * 4];
            float a[8] = {a0.x, a0.y, a0.z, a0.w, a1.x, a1.y, a1.z, a1.w};
            float b[4] = {b0.x, b0.y, b0.z, b0.w};
#pragma unroll
            for (int i = 0; i < 8; i++)
#pragma unroll
                for (int j = 0; j < 4; j++) acc[i][j] += a[i] * b[j];
        }
        if (t + 1 < nk) {
            buf ^= 1;
            As[buf][ak + 0][ar] = ra0.x;  As[buf][ak + 1][ar] = ra0.y;
            As[buf][ak + 2][ar] = ra0.z;  As[buf][ak + 3][ar] = ra0.w;
            As[buf][ak + 0][64 + ar] = ra1.x;  As[buf][ak + 1][64 + ar] = ra1.y;
            As[buf][ak + 2][64 + ar] = ra1.z;  As[buf][ak + 3][64 + ar] = ra1.w;
            *(float4*)&Bs[buf][bk][bn0] = rb;
            __syncthreads();
        }
    }

    // ---- epilogue ----
#pragma unroll
    for (int i = 0; i < 8; i++) {
        int m = bm + tr * 8 + i;
#pragma unroll
        for (int j = 0; j < 4; j++) {
            int n = bn + tc * 4 + j;
            if (n >= N) continue;
            float v = acc[i][j] + bias[n];
            if (MODE == 1) v = 0.5f * v * (1.0f + erff(v * 0.70710678118654752f));
            if (MODE == 2) {
                int b = m >> 9, s2 = m & 511, h = n >> 6, d = n & 63;
                C[(((size_t)b * NHH + h) * SQ + s2) * DHH + d] = v;
            } else {
                C[(size_t)m * N + n] = v;
            }
        }
    }
}

// ---------------- batched NT GEMM: C[bh][m][n] = sum_d A[bh][m][d]*B[bh%bmod][n][d] ----------------
// acode/bcode select A,B buffers; ccode 0->g_s0, 1->g_c2p, 2->g_p2c
__global__ void __launch_bounds__(256)
bgemm_nt_kernel(int acode, int bcode, int ccode, int bmod) {
    int bh = blockIdx.z;
    const float* Ab = bufptr(acode) + (size_t)bh * SQ * DHH;
    const float* Bb = bufptr(bcode) + (size_t)(bh % bmod) * SQ * DHH;
    float* Cb = (ccode == 0 ? g_s0 : (ccode == 1 ? g_c2p : g_p2c)) + (size_t)bh * SQ * SQ;
    int bm = blockIdx.y * 64, bn = blockIdx.x * 64;
    __shared__ float As[16][68];
    __shared__ float Bs[16][68];
    int tid = threadIdx.x, tr = tid >> 4, tc = tid & 15;
    float acc[4][4] = {};
#pragma unroll 1
    for (int k0 = 0; k0 < DHH; k0 += 16) {
#pragma unroll
        for (int i = tid; i < 1024; i += 256) {
            int m = i >> 4, kk = i & 15;
            As[kk][m] = Ab[(size_t)(bm + m) * DHH + k0 + kk];
            Bs[kk][m] = Bb[(size_t)(bn + m) * DHH + k0 + kk];
        }
        __syncthreads();
#pragma unroll
        for (int kk = 0; kk < 16; kk++) {
            float4 a4 = *(const float4*)&As[kk][tr * 4];
            float4 b4 = *(const float4*)&Bs[kk][tc * 4];
            float a[4] = {a4.x, a4.y, a4.z, a4.w};
            float b[4] = {b4.x, b4.y, b4.z, b4.w};
#pragma unroll
            for (int i2 = 0; i2 < 4; i2++)
#pragma unroll
                for (int j = 0; j < 4; j++) acc[i2][j] += a[i2] * b[j];
        }
        __syncthreads();
    }
#pragma unroll
    for (int i2 = 0; i2 < 4; i2++) {
        float4 o = make_float4(acc[i2][0], acc[i2][1], acc[i2][2], acc[i2][3]);
        *(float4*)&Cb[(size_t)(bm + tr * 4 + i2) * SQ + bn + tc * 4] = o;
    }
}

// ---------------- attention combine + gather + mask + softmax (in place on g_s0) ----------------
__global__ void attn_softmax_kernel(const int* __restrict__ mask) {
    int q = blockIdx.x, bh = blockIdx.y, b = bh / NHH;
    int tid = threadIdx.x;
    float* row = g_s0 + ((size_t)bh * SQ + q) * SQ;
    const float* crow = g_c2p + ((size_t)bh * SQ + q) * SQ;
    const float* pbase = g_p2c + (size_t)bh * SQ * SQ;
    int mq = mask[b * SQ + q];
    float vals[2];
    float mx = -3.4028234663852886e38f;
#pragma unroll
    for (int t = 0; t < 2; t++) {
        int k = tid + t * 256;
        float v = -3.4028234663852886e38f;
        if (mq != 0 && mask[b * SQ + k] != 0) {
            v = (row[k] + crow[g_ic2p[q * SQ + k]] + pbase[(size_t)k * SQ + g_ip2c[k * SQ + q]]) * SCALEF;
        }
        vals[t] = v;
        mx = fmaxf(mx, v);
    }
    mx = blk_reduce_max(mx);
    float sum = 0.f;
#pragma unroll
    for (int t = 0; t < 2; t++) { vals[t] = expf(vals[t] - mx); sum += vals[t]; }
    sum = blk_reduce_sum(sum);
    float inv = 1.0f / sum;
#pragma unroll
    for (int t = 0; t < 2; t++) row[tid + t * 256] = vals[t] * inv;
}

// ---------------- batched NN GEMM: ctx = probs @ v, scatter to [B,S,H] in g_t2 ----------------
__global__ void __launch_bounds__(256)
bgemm_ctx_kernel() {
    int bh = blockIdx.z, b = bh / NHH, h = bh % NHH;
    const float* Pb = g_s0 + (size_t)bh * SQ * SQ;
    const float* Vb = g_v + (size_t)bh * SQ * DHH;
    int bm = blockIdx.y * 64;
    __shared__ float As[16][68];
    __shared__ float Bs[16][68];
    int tid = threadIdx.x, tr = tid >> 4, tc = tid & 15;
    float acc[4][4] = {};
#pragma unroll 1
    for (int k0 = 0; k0 < SQ; k0 += 16) {
#pragma unroll
        for (int i = tid; i < 1024; i += 256) {
            int m = i >> 4, kk = i & 15;
            As[kk][m] = Pb[(size_t)(bm + m) * SQ + k0 + kk];
        }
#pragma unroll
        for (int i = tid; i < 1024; i += 256) {
            int kk = i >> 6, n = i & 63;
            Bs[kk][n] = Vb[(size_t)(k0 + kk) * DHH + n];
        }
        __syncthreads();
#pragma unroll
        for (int kk = 0; kk < 16; kk++) {
            float4 a4 = *(const float4*)&As[kk][tr * 4];
            float4 b4 = *(const float4*)&Bs[kk][tc * 4];
            float a[4] = {a4.x, a4.y, a4.z, a4.w};
            float b[4] = {b4.x, b4.y, b4.z, b4.w};
#pragma unroll
            for (int i2 = 0; i2 < 4; i2++)
#pragma unroll
                for (int j = 0; j < 4; j++) acc[i2][j] += a[i2] * b[j];
        }
        __syncthreads();
    }
#pragma unroll
    for (int i2 = 0; i2 < 4; i2++) {
        int m = bm + tr * 4 + i2;
#pragma unroll
        for (int j = 0; j < 4; j++) {
            g_t2[((size_t)(b * SQ + m)) * HD + h * DHH + tc * 4 + j] = acc[i2][j];
        }
    }
}

// ---------------- launch ----------------
extern "C" void kernel_launch(void* const* d_in, const int* in_sizes, int n_in,
                              void* d_out, int out_size) {
    const int*   ids     = (const int*)d_in[0];
    const int*   mask    = (const int*)d_in[1];
    const float* we      = (const float*)d_in[2];
    const float* te      = (const float*)d_in[3];
    const float* elns    = (const float*)d_in[4];
    const float* elnb    = (const float*)d_in[5];
    const float* rel_emb = (const float*)d_in[6];
    const float* rlns    = (const float*)d_in[7];
    const float* rlnb    = (const float*)d_in[8];
    const float* qw      = (const float*)d_in[9];
    const float* qb      = (const float*)d_in[10];
    const float* kw      = (const float*)d_in[11];
    const float* kb      = (const float*)d_in[12];
    const float* vw      = (const float*)d_in[13];
    const float* vb      = (const float*)d_in[14];
    const float* aow     = (const float*)d_in[15];
    const float* aob     = (const float*)d_in[16];
    const float* alns    = (const float*)d_in[17];
    const float* alnb    = (const float*)d_in[18];
    const float* iw      = (const float*)d_in[19];
    const float* ib      = (const float*)d_in[20];
    const float* ow      = (const float*)d_in[21];
    const float* ob      = (const float*)d_in[22];
    const float* olns    = (const float*)d_in[23];
    const float* olnb    = (const float*)d_in[24];
    const float* clsw    = (const float*)d_in[25];
    const float* clsb    = (const float*)d_in[26];
    float* out = (float*)d_out;

    relidx_kernel<<<1024, 256>>>();
    rel_ln_kernel<<<SQ, 256>>>(rel_emb, rlns, rlnb);
    embed_ln_kernel<<<NTOK, 256>>>(ids, mask, we, te, elns, elnb);

    dim3 gProj(12, 16);   // N=768/64, M=2048/128
    dim3 gPos(12, 4);     // N=768/64, M=512/128
    dim3 gFF1(48, 16);    // N=3072/64, M=2048/128
    dim3 gFF2(12, 16);    // N=768/64, M=2048/128
    dim3 gCls(1, 16);     // N=9 (guarded), M=2048/128
    dim3 gAttn(8, 8, BHH);
    dim3 gSm(SQ, BHH);
    dim3 gCtx(1, 8, BHH);

    for (int l = 0; l < NLAYER; l++) {
        const float* qwl = qw + (size_t)l * HD * HD;
        const float* kwl = kw + (size_t)l * HD * HD;
        const float* vwl = vw + (size_t)l * HD * HD;
        const float* aowl = aow + (size_t)l * HD * HD;
        const float* iwl = iw + (size_t)l * HD * FFD;
        const float* owl = ow + (size_t)l * FFD * HD;
        const float* qbl = qb + (size_t)l * HD;
        const float* kbl = kb + (size_t)l * HD;
        const float* vbl = vb + (size_t)l * HD;
        const float* aobl = aob + (size_t)l * HD;
        const float* ibl = ib + (size_t)l * FFD;
        const float* obl = ob + (size_t)l * HD;

        sgemm_kernel<2><<<gProj, 256>>>(BUF_X, qwl, qbl, BUF_Q, 0, NTOK, HD, HD);
        sgemm_kernel<2><<<gProj, 256>>>(BUF_X, kwl, kbl, BUF_K, 0, NTOK, HD, HD);
        sgemm_kernel<2><<<gProj, 256>>>(BUF_X, vwl, vbl, BUF_V, 0, NTOK, HD, HD);
        sgemm_kernel<2><<<gPos, 256>>>(BUF_REL, kwl, kbl, BUF_PK, 0, SQ, HD, HD);
        sgemm_kernel<2><<<gPos, 256>>>(BUF_REL, qwl, qbl, BUF_PQ, 0, SQ, HD, HD);

        bgemm_nt_kernel<<<gAttn, 256>>>(BUF_Q, BUF_K, 0, BHH);   // q @ k^T  -> g_s0
        bgemm_nt_kernel<<<gAttn, 256>>>(BUF_Q, BUF_PK, 1, NHH);  // q @ pk^T -> g_c2p
        bgemm_nt_kernel<<<gAttn, 256>>>(BUF_K, BUF_PQ, 2, NHH);  // k @ pq^T -> g_p2c

        attn_softmax_kernel<<<gSm, 256>>>(mask);

        bgemm_ctx_kernel<<<gCtx, 256>>>();                       // -> g_t2 [B,S,H]

        sgemm_kernel<0><<<gProj, 256>>>(BUF_T2, aowl, aobl, BUF_T1, 0, NTOK, HD, HD);
        add_ln_kernel<<<NTOK, 256>>>(BUF_T1, alns + (size_t)l * HD, alnb + (size_t)l * HD);

        sgemm_kernel<1><<<gFF1, 256>>>(BUF_X, iwl, ibl, BUF_T1, 0, NTOK, FFD, HD);   // GELU
        sgemm_kernel<0><<<gFF2, 256>>>(BUF_T1, owl, obl, BUF_T2, 0, NTOK, HD, FFD);
        add_ln_kernel<<<NTOK, 256>>>(BUF_T2, olns + (size_t)l * HD, olnb + (size_t)l * HD);
    }

    sgemm_kernel<0><<<gCls, 256>>>(BUF_X, clsw, clsb, BUF_EXT, out, NTOK, NCLS, HD);
}

// round 10
// speedup vs baseline: 1.4797x; 1.4606x over previous
#include <cuda_runtime.h>
#include <cuda_bf16.h>
#include <math.h>

#define SQ   512
#define HD   768
#define NHH  12
#define DHH  64
#define BHH  48          // B * NH
#define FFD  3072
#define NCLS 9
#define NLAYER 12
#define NTOK 2048        // B * S
#define SCALEF 0.07216878364870323f   // 1/sqrt(64*3)

// ---------------- scratch (allocation-free: __device__ globals) ----------------
__device__ float g_x[NTOK * HD];
__device__ float g_q[BHH * SQ * DHH];
__device__ float g_k[BHH * SQ * DHH];
__device__ float g_v[BHH * SQ * DHH];
__device__ float g_pk[NHH * SQ * DHH];
__device__ float g_pq[NHH * SQ * DHH];
__device__ float g_rel[SQ * HD];
__device__ float g_s0[BHH * SQ * SQ];
__device__ float g_c2p[BHH * SQ * SQ];
__device__ float g_p2c[BHH * SQ * SQ];
__device__ float g_t1[NTOK * FFD];
__device__ float g_t2[NTOK * HD];
__device__ int   g_ic2p[SQ * SQ];
__device__ int   g_ip2c[SQ * SQ];

// bf16 hi/lo converted operands (uint4 arrays for 16B alignment)
__device__ uint4 g_ah4[NTOK * FFD / 8];     // A hi  (max 2048x3072)
__device__ uint4 g_al4[NTOK * FFD / 8];     // A lo
__device__ uint4 g_relh4[SQ * HD / 8];      // rel hi
__device__ uint4 g_rell4[SQ * HD / 8];      // rel lo
__device__ uint4 g_bth4[FFD * HD / 8];      // B^T hi (max 3072x768)
__device__ uint4 g_btl4[FFD * HD / 8];      // B^T lo

// Buffer selector so host code never needs cudaGetSymbolAddress.
#define BUF_X   0
#define BUF_Q   1
#define BUF_K   2
#define BUF_V   3
#define BUF_PK  4
#define BUF_PQ  5
#define BUF_REL 6
#define BUF_T1  10
#define BUF_T2  11
#define BUF_EXT (-1)

__device__ __forceinline__ float* bufptr(int c) {
    switch (c) {
        case BUF_X:   return g_x;
        case BUF_Q:   return g_q;
        case BUF_K:   return g_k;
        case BUF_V:   return g_v;
        case BUF_PK:  return g_pk;
        case BUF_PQ:  return g_pq;
        case BUF_REL: return g_rel;
        case BUF_T1:  return g_t1;
        case BUF_T2:  return g_t2;
    }
    return 0;
}

// ---------------- block reductions (256 threads) ----------------
__device__ __forceinline__ float blk_reduce_sum(float v) {
    __shared__ float red[256];
    int tid = threadIdx.x;
    red[tid] = v; __syncthreads();
    for (int s = 128; s > 0; s >>= 1) {
        if (tid < s) red[tid] += red[tid + s];
        __syncthreads();
    }
    float r = red[0]; __syncthreads();
    return r;
}

__device__ __forceinline__ float blk_reduce_max(float v) {
    __shared__ float redm[256];
    int tid = threadIdx.x;
    redm[tid] = v; __syncthreads();
    for (int s = 128; s > 0; s >>= 1) {
        if (tid < s) redm[tid] = fmaxf(redm[tid], redm[tid + s]);
        __syncthreads();
    }
    float r = redm[0]; __syncthreads();
    return r;
}

// ---------------- relative position bucket indices ----------------
__global__ void relidx_kernel() {
    int idx = blockIdx.x * blockDim.x + threadIdx.x;
    if (idx >= SQ * SQ) return;
    int i = idx >> 9, j = idx & 511;
    int rel = i - j;
    int bucket;
    if (rel >= -128 && rel <= 128) {
        bucket = rel;
    } else {
        float abs_pos = fabsf((float)rel);
        float log_pos = ceilf(logf(abs_pos / 128.0f) / logf(511.0f / 128.0f) * 127.0f) + 128.0f;
        bucket = (int)(rel > 0 ? log_pos : -log_pos);
    }
    int c = bucket + 256; c = c < 0 ? 0 : (c > 511 ? 511 : c);
    int p = -bucket + 256; p = p < 0 ? 0 : (p > 511 ? 511 : p);
    g_ic2p[idx] = c;
    g_ip2c[idx] = p;
}

// ---------------- embedding gather + LN * mask ----------------
__global__ void embed_ln_kernel(const int* __restrict__ ids, const int* __restrict__ mask,
                                const float* __restrict__ we, const float* __restrict__ te,
                                const float* __restrict__ lns, const float* __restrict__ lnb) {
    int r = blockIdx.x, tid = threadIdx.x;
    size_t id = (size_t)ids[r];
    float v[3];
#pragma unroll
    for (int t = 0; t < 3; t++) {
        int c = tid + t * 256;
        v[t] = we[id * HD + c] + te[c];
    }
    float mu = blk_reduce_sum(v[0] + v[1] + v[2]) * (1.0f / HD);
    float sq = 0.f;
#pragma unroll
    for (int t = 0; t < 3; t++) { float d = v[t] - mu; sq += d * d; }
    float var = blk_reduce_sum(sq) * (1.0f / HD);
    float inv = rsqrtf(var + 1e-7f);
    float mf = (float)mask[r];
#pragma unroll
    for (int t = 0; t < 3; t++) {
        int c = tid + t * 256;
        g_x[(size_t)r * HD + c] = ((v[t] - mu) * inv * lns[c] + lnb[c]) * mf;
    }
}

// ---------------- LN of relative embeddings ----------------
__global__ void rel_ln_kernel(const float* __restrict__ re,
                              const float* __restrict__ lns, const float* __restrict__ lnb) {
    int r = blockIdx.x, tid = threadIdx.x;
    float v[3];
#pragma unroll
    for (int t = 0; t < 3; t++) v[t] = re[(size_t)r * HD + tid + t * 256];
    float mu = blk_reduce_sum(v[0] + v[1] + v[2]) * (1.0f / HD);
    float sq = 0.f;
#pragma unroll
    for (int t = 0; t < 3; t++) { float d = v[t] - mu; sq += d * d; }
    float var = blk_reduce_sum(sq) * (1.0f / HD);
    float inv = rsqrtf(var + 1e-7f);
#pragma unroll
    for (int t = 0; t < 3; t++) {
        int c = tid + t * 256;
        g_rel[(size_t)r * HD + c] = (v[t] - mu) * inv * lns[c] + lnb[c];
    }
}

// ---------------- residual + LN (in place on g_x): x = LN(x + buf[tcode]) ----------------
__global__ void add_ln_kernel(int tcode,
                              const float* __restrict__ lns, const float* __restrict__ lnb) {
    const float* t = bufptr(tcode);
    int r = blockIdx.x, tid = threadIdx.x;
    float v[3];
#pragma unroll
    for (int c2 = 0; c2 < 3; c2++) {
        int c = tid + c2 * 256;
        v[c2] = g_x[(size_t)r * HD + c] + t[(size_t)r * HD + c];
    }
    float mu = blk_reduce_sum(v[0] + v[1] + v[2]) * (1.0f / HD);
    float sq = 0.f;
#pragma unroll
    for (int c2 = 0; c2 < 3; c2++) { float d = v[c2] - mu; sq += d * d; }
    float var = blk_reduce_sum(sq) * (1.0f / HD);
    float inv = rsqrtf(var + 1e-7f);
#pragma unroll
    for (int c2 = 0; c2 < 3; c2++) {
        int c = tid + c2 * 256;
        g_x[(size_t)r * HD + c] = (v[c2] - mu) * inv * lns[c] + lnb[c];
    }
}

// ---------------- fp32 -> bf16 hi/lo conversion helpers ----------------
__device__ __forceinline__ void split_bf16(float x, unsigned short& h, unsigned short& l) {
    __nv_bfloat16 hh = __float2bfloat16(x);
    float r = x - __bfloat162float(hh);
    __nv_bfloat16 ll = __float2bfloat16(r);
    h = __bfloat16_as_ushort(hh);
    l = __bfloat16_as_ushort(ll);
}

// convert A activations: src = buf[scode] fp32, dst: which==0 -> g_ah4/g_al4, which==1 -> rel bufs
__global__ void conva_kernel(int scode, int which, int n4) {
    int idx = blockIdx.x * blockDim.x + threadIdx.x;
    if (idx >= n4) return;
    const float* src = bufptr(scode);
    float4 v = ((const float4*)src)[idx];
    unsigned short h0, h1, h2, h3, l0, l1, l2, l3;
    split_bf16(v.x, h0, l0); split_bf16(v.y, h1, l1);
    split_bf16(v.z, h2, l2); split_bf16(v.w, h3, l3);
    uint2 hw = make_uint2((unsigned)h0 | ((unsigned)h1 << 16), (unsigned)h2 | ((unsigned)h3 << 16));
    uint2 lw = make_uint2((unsigned)l0 | ((unsigned)l1 << 16), (unsigned)l2 | ((unsigned)l3 << 16));
    uint2* dh = which ? (uint2*)g_relh4 : (uint2*)g_ah4;
    uint2* dl = which ? (uint2*)g_rell4 : (uint2*)g_al4;
    dh[idx] = hw;
    dl[idx] = lw;
}

// transpose + convert weights: W[K][N] fp32 -> BT[N][K] bf16 hi/lo in g_bth4/g_btl4
__global__ void transb_kernel(const float* __restrict__ W, int K, int N) {
    __shared__ float tile[32][33];
    int k0 = blockIdx.y * 32, n0 = blockIdx.x * 32;
    int tx = threadIdx.x, ty = threadIdx.y;   // (32, 8)
#pragma unroll
    for (int i = 0; i < 4; i++)
        tile[ty + i * 8][tx] = W[(size_t)(k0 + ty + i * 8) * N + n0 + tx];
    __syncthreads();
    __nv_bfloat16* oh = (__nv_bfloat16*)g_bth4;
    __nv_bfloat16* ol = (__nv_bfloat16*)g_btl4;
#pragma unroll
    for (int i = 0; i < 4; i++) {
        int n = n0 + ty + i * 8;
        float v = tile[tx][ty + i * 8];
        __nv_bfloat16 hh = __float2bfloat16(v);
        oh[(size_t)n * K + k0 + tx] = hh;
        ol[(size_t)n * K + k0 + tx] = __float2bfloat16(v - __bfloat162float(hh));
    }
}

// ---------------- tensor-core GEMM: C = A @ B + bias (split bf16, fp32 accum) ----------------
// A: g_ah4/g_al4 (acode=0) or g_relh4/g_rell4 (acode=1), row-major [M][K] bf16.
// B: g_bth4/g_btl4, BT layout [N][K] bf16.
// Block tile 64(M) x 128(N) x 32(K); 8 warps (2x4), warp tile 32x32.
// smem rows are 20 words (40 bf16) wide; words [0..16) of each row hold the
// 32 bf16 of the K-tile; stride 20 makes the fragment reads conflict-free.
// MODE 0: plain; 1: exact GELU; 2: head-major scatter
#define SW_A_HI 0
#define SW_A_LO 1280
#define SW_B_HI 2560
#define SW_B_LO 5120

__device__ __forceinline__ void mma16816(float* c, const unsigned* a, const unsigned* b) {
    asm volatile(
        "mma.sync.aligned.m16n8k16.row.col.f32.bf16.bf16.f32 "
        "{%0,%1,%2,%3}, {%4,%5,%6,%7}, {%8,%9}, {%0,%1,%2,%3};"
        : "+f"(c[0]), "+f"(c[1]), "+f"(c[2]), "+f"(c[3])
        : "r"(a[0]), "r"(a[1]), "r"(a[2]), "r"(a[3]), "r"(b[0]), "r"(b[1]));
}

template<int MODE>
__global__ void __launch_bounds__(256)
tc_gemm_kernel(int acode, const float* __restrict__ bias, int ccode,
               float* __restrict__ Cext, int M, int N, int K) {
    const __nv_bfloat16* Ah = (const __nv_bfloat16*)(acode ? g_relh4 : g_ah4);
    const __nv_bfloat16* Al = (const __nv_bfloat16*)(acode ? g_rell4 : g_al4);
    const __nv_bfloat16* Bh = (const __nv_bfloat16*)g_bth4;
    const __nv_bfloat16* Bl = (const __nv_bfloat16*)g_btl4;
    float* __restrict__ C = (ccode < 0) ? Cext : bufptr(ccode);

    __shared__ unsigned S[7680];   // 30 KB: Ahi[64x20w] Alo Bhi[128x20w] Blo

    const int bm = blockIdx.y * 64, bn = blockIdx.x * 128;
    const int tid = threadIdx.x;

    // ---- global->smem loader assignments ----
    // A: 64 rows x 16 words (hi + lo) = 512 uint4; 2 per thread.
    const __nv_bfloat16* a_src[2];
    int a_dst[2];
#pragma unroll
    for (int it = 0; it < 2; it++) {
        int flat = tid + it * 256;          // 0..511
        int hl = flat >> 8;                 // 0 hi, 1 lo
        int rem = flat & 255;
        int r = rem >> 2;                   // 0..63
        int qq = rem & 3;                   // word quarter (4 words = 8 bf16)
        a_src[it] = (hl ? Al : Ah) + (size_t)(bm + r) * K + qq * 8;
        a_dst[it] = (hl ? SW_A_LO : SW_A_HI) + r * 20 + qq * 4;
    }
    // B: 128 rows x 16 words (hi + lo) = 1024 uint4; 4 per thread.
    const __nv_bfloat16* b_src[4];
    int b_dst[4];
#pragma unroll
    for (int it = 0; it < 4; it++) {
        int flat = tid + it * 256;          // 0..1023
        int hl = flat >> 9;
        int rem = flat & 511;
        int r = rem >> 2;                   // 0..127
        int qq = rem & 3;
        b_src[it] = (hl ? Bl : Bh) + (size_t)(bn + r) * K + qq * 8;
        b_dst[it] = (hl ? SW_B_LO : SW_B_HI) + r * 20 + qq * 4;
    }

    // fragment coords
    const int lane = tid & 31, g = lane >> 2, tig = lane & 3;
    const int warp = tid >> 5;
    const int wm = (warp & 1) * 32, wn = (warp >> 1) * 32;

    float acc[2][4][4] = {};
    const int nt = K >> 5;

    uint4 pa[2], pb[4];
#pragma unroll
    for (int it = 0; it < 2; it++) pa[it] = *(const uint4*)a_src[it];
#pragma unroll
    for (int it = 0; it < 4; it++) pb[it] = *(const uint4*)b_src[it];

#pragma unroll 1
    for (int t = 0; t < nt; t++) {
#pragma unroll
        for (int it = 0; it < 2; it++) *(uint4*)&S[a_dst[it]] = pa[it];
#pragma unroll
        for (int it = 0; it < 4; it++) *(uint4*)&S[b_dst[it]] = pb[it];
        __syncthreads();
        if (t + 1 < nt) {
            int ko = (t + 1) * 32;
#pragma unroll
            for (int it = 0; it < 2; it++) pa[it] = *(const uint4*)(a_src[it] + ko);
#pragma unroll
            for (int it = 0; it < 4; it++) pb[it] = *(const uint4*)(b_src[it] + ko);
        }
#pragma unroll
        for (int step = 0; step < 2; step++) {
            const int so = step * 8 + tig;
            unsigned ah[2][4], bh[4][2];
#pragma unroll
            for (int mi = 0; mi < 2; mi++) {
                unsigned base = SW_A_HI + (wm + mi * 16 + g) * 20 + so;
                ah[mi][0] = S[base];        ah[mi][1] = S[base + 160];
                ah[mi][2] = S[base + 4];    ah[mi][3] = S[base + 164];
            }
#pragma unroll
            for (int nj = 0; nj < 4; nj++) {
                unsigned base = SW_B_HI + (wn + nj * 8 + g) * 20 + so;
                bh[nj][0] = S[base];  bh[nj][1] = S[base + 4];
            }
#pragma unroll
            for (int mi = 0; mi < 2; mi++)
#pragma unroll
                for (int nj = 0; nj < 4; nj++) mma16816(acc[mi][nj], ah[mi], bh[nj]);
            // A_hi x B_lo
            {
                unsigned bl[4][2];
#pragma unroll
                for (int nj = 0; nj < 4; nj++) {
                    unsigned base = SW_B_LO + (wn + nj * 8 + g) * 20 + so;
                    bl[nj][0] = S[base];  bl[nj][1] = S[base + 4];
                }
#pragma unroll
                for (int mi = 0; mi < 2; mi++)
#pragma unroll
                    for (int nj = 0; nj < 4; nj++) mma16816(acc[mi][nj], ah[mi], bl[nj]);
            }
            // A_lo x B_hi
            {
                unsigned al[2][4];
#pragma unroll
                for (int mi = 0; mi < 2; mi++) {
                    unsigned base = SW_A_LO + (wm + mi * 16 + g) * 20 + so;
                    al[mi][0] = S[base];        al[mi][1] = S[base + 160];
                    al[mi][2] = S[base + 4];    al[mi][3] = S[base + 164];
                }
#pragma unroll
                for (int mi = 0; mi < 2; mi++)
#pragma unroll
                    for (int nj = 0; nj < 4; nj++) mma16816(acc[mi][nj], al[mi], bh[nj]);
            }
        }
        __syncthreads();
    }

    // ---- epilogue ----
#pragma unroll
    for (int mi = 0; mi < 2; mi++) {
#pragma unroll
        for (int nj = 0; nj < 4; nj++) {
#pragma unroll
            for (int rr = 0; rr < 4; rr++) {
                int m = bm + wm + mi * 16 + g + (rr >> 1) * 8;
                int n = bn + wn + nj * 8 + tig * 2 + (rr & 1);
                float v = acc[mi][nj][rr] + bias[n];
                if (MODE == 1) v = 0.5f * v * (1.0f + erff(v * 0.70710678118654752f));
                if (MODE == 2) {
                    int b = m >> 9, s2 = m & 511, h = n >> 6, d = n & 63;
                    C[(((size_t)b * NHH + h) * SQ + s2) * DHH + d] = v;
                } else {
                    C[(size_t)m * N + n] = v;
                }
            }
        }
    }
}

// ---------------- SIMT SGEMM (kept only for cls head, N=9) ----------------
template<int MODE>
__global__ void __launch_bounds__(256)
sgemm_kernel(int acode, const float* __restrict__ Bm,
             const float* __restrict__ bias, int ccode, float* __restrict__ Cext,
             int M, int N, int K) {
    const float* A = bufptr(acode);
    float* C = (ccode < 0) ? Cext : bufptr(ccode);
    __shared__ float As[16][68];
    __shared__ float Bs[16][68];
    int bm = blockIdx.y * 64, bn = blockIdx.x * 64;
    int tid = threadIdx.x;
    int tr = tid >> 4, tc = tid & 15;
    float acc[4][4] = {};
#pragma unroll 1
    for (int k0 = 0; k0 < K; k0 += 16) {
#pragma unroll
        for (int i = tid; i < 1024; i += 256) {
            int m = i >> 4, kk = i & 15;
            As[kk][m] = A[(size_t)(bm + m) * K + k0 + kk];
        }
#pragma unroll
        for (int i = tid; i < 1024; i += 256) {
            int kk = i >> 6, n = i & 63;
            Bs[kk][n] = (bn + n < N) ? Bm[(size_t)(k0 + kk) * N + bn + n] : 0.f;
        }
        __syncthreads();
#pragma unroll
        for (int kk = 0; kk < 16; kk++) {
            float4 a4 = *(const float4*)&As[kk][tr * 4];
            float4 b4 = *(const float4*)&Bs[kk][tc * 4];
            float a[4] = {a4.x, a4.y, a4.z, a4.w};
            float b[4] = {b4.x, b4.y, b4.z, b4.w};
#pragma unroll
            for (int i2 = 0; i2 < 4; i2++)
#pragma unroll
                for (int j = 0; j < 4; j++) acc[i2][j] += a[i2] * b[j];
        }
        __syncthreads();
    }
#pragma unroll
    for (int i2 = 0; i2 < 4; i2++) {
        int m = bm + tr * 4 + i2;
#pragma unroll
        for (int j = 0; j < 4; j++) {
            int n = bn + tc * 4 + j;
            if (n >= N) continue;
            float v = acc[i2][j] + bias[n];
            if (MODE == 1) v = 0.5f * v * (1.0f + erff(v * 0.70710678118654752f));
            if (MODE == 2) {
                int b = m >> 9, s2 = m & 511, h = n >> 6, d = n & 63;
                C[(((size_t)b * NHH + h) * SQ + s2) * DHH + d] = v;
            } else {
                C[(size_t)m * N + n] = v;
            }
        }
    }
}

// ---------------- batched NT GEMM: C[bh][m][n] = sum_d A[bh][m][d]*B[bh%bmod][n][d] ----------------
__global__ void __launch_bounds__(256)
bgemm_nt_kernel(int acode, int bcode, int ccode, int bmod) {
    int bh = blockIdx.z;
    const float* Ab = bufptr(acode) + (size_t)bh * SQ * DHH;
    const float* Bb = bufptr(bcode) + (size_t)(bh % bmod) * SQ * DHH;
    float* Cb = (ccode == 0 ? g_s0 : (ccode == 1 ? g_c2p : g_p2c)) + (size_t)bh * SQ * SQ;
    int bm = blockIdx.y * 64, bn = blockIdx.x * 64;
    __shared__ float As[16][68];
    __shared__ float Bs[16][68];
    int tid = threadIdx.x, tr = tid >> 4, tc = tid & 15;
    float acc[4][4] = {};
#pragma unroll 1
    for (int k0 = 0; k0 < DHH; k0 += 16) {
#pragma unroll
        for (int i = tid; i < 1024; i += 256) {
            int m = i >> 4, kk = i & 15;
            As[kk][m] = Ab[(size_t)(bm + m) * DHH + k0 + kk];
            Bs[kk][m] = Bb[(size_t)(bn + m) * DHH + k0 + kk];
        }
        __syncthreads();
#pragma unroll
        for (int kk = 0; kk < 16; kk++) {
            float4 a4 = *(const float4*)&As[kk][tr * 4];
            float4 b4 = *(const float4*)&Bs[kk][tc * 4];
            float a[4] = {a4.x, a4.y, a4.z, a4.w};
            float b[4] = {b4.x, b4.y, b4.z, b4.w};
#pragma unroll
            for (int i2 = 0; i2 < 4; i2++)
#pragma unroll
                for (int j = 0; j < 4; j++) acc[i2][j] += a[i2] * b[j];
        }
        __syncthreads();
    }
#pragma unroll
    for (int i2 = 0; i2 < 4; i2++) {
        float4 o = make_float4(acc[i2][0], acc[i2][1], acc[i2][2], acc[i2][3]);
        *(float4*)&Cb[(size_t)(bm + tr * 4 + i2) * SQ + bn + tc * 4] = o;
    }
}

// ---------------- attention combine + gather + mask + softmax (in place on g_s0) ----------------
__global__ void attn_softmax_kernel(const int* __restrict__ mask) {
    int q = blockIdx.x, bh = blockIdx.y, b = bh / NHH;
    int tid = threadIdx.x;
    float* row = g_s0 + ((size_t)bh * SQ + q) * SQ;
    const float* crow = g_c2p + ((size_t)bh * SQ + q) * SQ;
    const float* pbase = g_p2c + (size_t)bh * SQ * SQ;
    int mq = mask[b * SQ + q];
    float vals[2];
    float mx = -3.4028234663852886e38f;
#pragma unroll
    for (int t = 0; t < 2; t++) {
        int k = tid + t * 256;
        float v = -3.4028234663852886e38f;
        if (mq != 0 && mask[b * SQ + k] != 0) {
            v = (row[k] + crow[g_ic2p[q * SQ + k]] + pbase[(size_t)k * SQ + g_ip2c[k * SQ + q]]) * SCALEF;
        }
        vals[t] = v;
        mx = fmaxf(mx, v);
    }
    mx = blk_reduce_max(mx);
    float sum = 0.f;
#pragma unroll
    for (int t = 0; t < 2; t++) { vals[t] = expf(vals[t] - mx); sum += vals[t]; }
    sum = blk_reduce_sum(sum);
    float inv = 1.0f / sum;
#pragma unroll
    for (int t = 0; t < 2; t++) row[tid + t * 256] = vals[t] * inv;
}

// ---------------- batched NN GEMM: ctx = probs @ v, scatter to [B,S,H] in g_t2 ----------------
__global__ void __launch_bounds__(256)
bgemm_ctx_kernel() {
    int bh = blockIdx.z, b = bh / NHH, h = bh % NHH;
    const float* Pb = g_s0 + (size_t)bh * SQ * SQ;
    const float* Vb = g_v + (size_t)bh * SQ * DHH;
    int bm = blockIdx.y * 64;
    __shared__ float As[16][68];
    __shared__ float Bs[16][68];
    int tid = threadIdx.x, tr = tid >> 4, tc = tid & 15;
    float acc[4][4] = {};
#pragma unroll 1
    for (int k0 = 0; k0 < SQ; k0 += 16) {
#pragma unroll
        for (int i = tid; i < 1024; i += 256) {
            int m = i >> 4, kk = i & 15;
            As[kk][m] = Pb[(size_t)(bm + m) * SQ + k0 + kk];
        }
#pragma unroll
        for (int i = tid; i < 1024; i += 256) {
            int kk = i >> 6, n = i & 63;
            Bs[kk][n] = Vb[(size_t)(k0 + kk) * DHH + n];
        }
        __syncthreads();
#pragma unroll
        for (int kk = 0; kk < 16; kk++) {
            float4 a4 = *(const float4*)&As[kk][tr * 4];
            float4 b4 = *(const float4*)&Bs[kk][tc * 4];
            float a[4] = {a4.x, a4.y, a4.z, a4.w};
            float b[4] = {b4.x, b4.y, b4.z, b4.w};
#pragma unroll
            for (int i2 = 0; i2 < 4; i2++)
#pragma unroll
                for (int j = 0; j < 4; j++) acc[i2][j] += a[i2] * b[j];
        }
        __syncthreads();
    }
#pragma unroll
    for (int i2 = 0; i2 < 4; i2++) {
        int m = bm + tr * 4 + i2;
#pragma unroll
        for (int j = 0; j < 4; j++) {
            g_t2[((size_t)(b * SQ + m)) * HD + h * DHH + tc * 4 + j] = acc[i2][j];
        }
    }
}

// ---------------- launch ----------------
extern "C" void kernel_launch(void* const* d_in, const int* in_sizes, int n_in,
                              void* d_out, int out_size) {
    const int*   ids     = (const int*)d_in[0];
    const int*   mask    = (const int*)d_in[1];
    const float* we      = (const float*)d_in[2];
    const float* te      = (const float*)d_in[3];
    const float* elns    = (const float*)d_in[4];
    const float* elnb    = (const float*)d_in[5];
    const float* rel_emb = (const float*)d_in[6];
    const float* rlns    = (const float*)d_in[7];
    const float* rlnb    = (const float*)d_in[8];
    const float* qw      = (const float*)d_in[9];
    const float* qb      = (const float*)d_in[10];
    const float* kw      = (const float*)d_in[11];
    const float* kb      = (const float*)d_in[12];
    const float* vw      = (const float*)d_in[13];
    const float* vb      = (const float*)d_in[14];
    const float* aow     = (const float*)d_in[15];
    const float* aob     = (const float*)d_in[16];
    const float* alns    = (const float*)d_in[17];
    const float* alnb    = (const float*)d_in[18];
    const float* iw      = (const float*)d_in[19];
    const float* ib      = (const float*)d_in[20];
    const float* ow      = (const float*)d_in[21];
    const float* ob      = (const float*)d_in[22];
    const float* olns    = (const float*)d_in[23];
    const float* olnb    = (const float*)d_in[24];
    const float* clsw    = (const float*)d_in[25];
    const float* clsb    = (const float*)d_in[26];
    float* out = (float*)d_out;

    relidx_kernel<<<1024, 256>>>();
    rel_ln_kernel<<<SQ, 256>>>(rel_emb, rlns, rlnb);
    embed_ln_kernel<<<NTOK, 256>>>(ids, mask, we, te, elns, elnb);

    // convert rel embeddings once (static across layers)
    conva_kernel<<<(SQ * HD / 4 + 255) / 256, 256>>>(BUF_REL, 1, SQ * HD / 4);

    dim3 tb(32, 8);
    dim3 gTransHH(HD / 32, HD / 32);       // 768x768 weights
    dim3 gTransIF(FFD / 32, HD / 32);      // W[768][3072]
    dim3 gTransOF(HD / 32, FFD / 32);      // W[3072][768]

    dim3 gTcProj(HD / 128, NTOK / 64);     // (6, 32)
    dim3 gTcPos(HD / 128, SQ / 64);        // (6, 8)
    dim3 gTcFF1(FFD / 128, NTOK / 64);     // (24, 32)
    dim3 gTcFF2(HD / 128, NTOK / 64);      // (6, 32)

    dim3 gAttn(8, 8, BHH);
    dim3 gSm(SQ, BHH);
    dim3 gCtx(1, 8, BHH);
    dim3 gCls(1, 32);

    const int nX4  = NTOK * HD / 4;
    const int nT14 = NTOK * FFD / 4;

    for (int l = 0; l < NLAYER; l++) {
        const float* qwl = qw + (size_t)l * HD * HD;
        const float* kwl = kw + (size_t)l * HD * HD;
        const float* vwl = vw + (size_t)l * HD * HD;
        const float* aowl = aow + (size_t)l * HD * HD;
        const float* iwl = iw + (size_t)l * HD * FFD;
        const float* owl = ow + (size_t)l * FFD * HD;
        const float* qbl = qb + (size_t)l * HD;
        const float* kbl = kb + (size_t)l * HD;
        const float* vbl = vb + (size_t)l * HD;
        const float* aobl = aob + (size_t)l * HD;
        const float* ibl = ib + (size_t)l * FFD;
        const float* obl = ob + (size_t)l * HD;

        // x -> bf16 hi/lo
        conva_kernel<<<(nX4 + 255) / 256, 256>>>(BUF_X, 0, nX4);

        transb_kernel<<<gTransHH, tb>>>(qwl, HD, HD);
        tc_gemm_kernel<2><<<gTcProj, 256>>>(0, qbl, BUF_Q, 0, NTOK, HD, HD);
        tc_gemm_kernel<2><<<gTcPos, 256>>>(1, qbl, BUF_PQ, 0, SQ, HD, HD);

        transb_kernel<<<gTransHH, tb>>>(kwl, HD, HD);
        tc_gemm_kernel<2><<<gTcProj, 256>>>(0, kbl, BUF_K, 0, NTOK, HD, HD);
        tc_gemm_kernel<2><<<gTcPos, 256>>>(1, kbl, BUF_PK, 0, SQ, HD, HD);

        transb_kernel<<<gTransHH, tb>>>(vwl, HD, HD);
        tc_gemm_kernel<2><<<gTcProj, 256>>>(0, vbl, BUF_V, 0, NTOK, HD, HD);

        bgemm_nt_kernel<<<gAttn, 256>>>(BUF_Q, BUF_K, 0, BHH);   // q @ k^T  -> g_s0
        bgemm_nt_kernel<<<gAttn, 256>>>(BUF_Q, BUF_PK, 1, NHH);  // q @ pk^T -> g_c2p
        bgemm_nt_kernel<<<gAttn, 256>>>(BUF_K, BUF_PQ, 2, NHH);  // k @ pq^T -> g_p2c

        attn_softmax_kernel<<<gSm, 256>>>(mask);

        bgemm_ctx_kernel<<<gCtx, 256>>>();                       // -> g_t2 [B,S,H]

        // attn out projection
        conva_kernel<<<(nX4 + 255) / 256, 256>>>(BUF_T2, 0, nX4);
        transb_kernel<<<gTransHH, tb>>>(aowl, HD, HD);
        tc_gemm_kernel<0><<<gTcProj, 256>>>(0, aobl, BUF_T1, 0, NTOK, HD, HD);
        add_ln_kernel<<<NTOK, 256>>>(BUF_T1, alns + (size_t)l * HD, alnb + (size_t)l * HD);

        // FFN
        conva_kernel<<<(nX4 + 255) / 256, 256>>>(BUF_X, 0, nX4);
        transb_kernel<<<gTransIF, tb>>>(iwl, HD, FFD);
        tc_gemm_kernel<1><<<gTcFF1, 256>>>(0, ibl, BUF_T1, 0, NTOK, FFD, HD);   // GELU

        conva_kernel<<<(nT14 + 255) / 256, 256>>>(BUF_T1, 0, nT14);
        transb_kernel<<<gTransOF, tb>>>(owl, FFD, HD);
        tc_gemm_kernel<0><<<gTcFF2, 256>>>(0, obl, BUF_T2, 0, NTOK, HD, FFD);
        add_ln_kernel<<<NTOK, 256>>>(BUF_T2, olns + (size_t)l * HD, olnb + (size_t)l * HD);
    }

    sgemm_kernel<0><<<gCls, 256>>>(BUF_X, clsw, clsb, BUF_EXT, out, NTOK, NCLS, HD);
}

// round 11
// speedup vs baseline: 1.5681x; 1.0597x over previous
#include <cuda_runtime.h>
#include <cuda_bf16.h>
#include <math.h>

#define SQ   512
#define HD   768
#define NHH  12
#define DHH  64
#define BHH  48          // B * NH
#define FFD  3072
#define NCLS 9
#define NLAYER 12
#define NTOK 2048        // B * S
#define SCALEF 0.07216878364870323f   // 1/sqrt(64*3)

// ---------------- scratch (allocation-free: __device__ globals) ----------------
__device__ float g_x[NTOK * HD];
__device__ float g_rel[SQ * HD];
__device__ float g_s0[BHH * SQ * SQ];
__device__ float g_c2p[BHH * SQ * SQ];
__device__ float g_p2c[BHH * SQ * SQ];
__device__ float g_t1[NTOK * HD];
__device__ float g_t2[NTOK * HD];
__device__ int   g_ic2p[SQ * SQ];
__device__ int   g_ip2c[SQ * SQ];

// split-bf16 operand buffers (uint4 for 16B alignment)
__device__ uint4 g_ah4[NTOK * HD / 8];      // A hi (activations 2048x768)
__device__ uint4 g_al4[NTOK * HD / 8];
__device__ uint4 g_a2h4[NTOK * FFD / 8];    // FFN1 output (2048x3072)
__device__ uint4 g_a2l4[NTOK * FFD / 8];
__device__ uint4 g_relh4[SQ * HD / 8];
__device__ uint4 g_rell4[SQ * HD / 8];
__device__ uint4 g_bth4[FFD * HD / 8];      // B^T (weights)
__device__ uint4 g_btl4[FFD * HD / 8];
__device__ uint4 g_qh4[BHH * SQ * DHH / 8]; // q [bh][s][d]
__device__ uint4 g_ql4[BHH * SQ * DHH / 8];
__device__ uint4 g_kh4[BHH * SQ * DHH / 8];
__device__ uint4 g_kl4[BHH * SQ * DHH / 8];
__device__ uint4 g_pkh4[NHH * SQ * DHH / 8];
__device__ uint4 g_pkl4[NHH * SQ * DHH / 8];
__device__ uint4 g_pqh4[NHH * SQ * DHH / 8];
__device__ uint4 g_pql4[NHH * SQ * DHH / 8];
__device__ uint4 g_vth4[BHH * DHH * SQ / 8]; // vT [bh][d][s]
__device__ uint4 g_vtl4[BHH * DHH * SQ / 8];
__device__ uint4 g_ph4[BHH * SQ * SQ / 8];   // probs [bh][q][k]
__device__ uint4 g_pl4[BHH * SQ * SQ / 8];

#define BUF_X   0
#define BUF_REL 6
#define BUF_T1  10
#define BUF_T2  11
#define BUF_EXT (-1)

__device__ __forceinline__ float* bufptr(int c) {
    switch (c) {
        case BUF_X:   return g_x;
        case BUF_REL: return g_rel;
        case BUF_T1:  return g_t1;
        case BUF_T2:  return g_t2;
    }
    return 0;
}

// bf16 pair selectors: 0 q, 1 k, 2 pk, 3 pq, 4 vT, 5 probs
__device__ __forceinline__ __nv_bfloat16* phi(int p) {
    switch (p) {
        case 0: return (__nv_bfloat16*)g_qh4;
        case 1: return (__nv_bfloat16*)g_kh4;
        case 2: return (__nv_bfloat16*)g_pkh4;
        case 3: return (__nv_bfloat16*)g_pqh4;
        case 4: return (__nv_bfloat16*)g_vth4;
        case 5: return (__nv_bfloat16*)g_ph4;
    }
    return 0;
}
__device__ __forceinline__ __nv_bfloat16* plo(int p) {
    switch (p) {
        case 0: return (__nv_bfloat16*)g_ql4;
        case 1: return (__nv_bfloat16*)g_kl4;
        case 2: return (__nv_bfloat16*)g_pkl4;
        case 3: return (__nv_bfloat16*)g_pql4;
        case 4: return (__nv_bfloat16*)g_vtl4;
        case 5: return (__nv_bfloat16*)g_pl4;
    }
    return 0;
}
// A-operand selectors: 0 act, 1 rel, 2 ffn1-out
__device__ __forceinline__ const __nv_bfloat16* ahi(int a) {
    return (const __nv_bfloat16*)(a == 0 ? g_ah4 : (a == 1 ? g_relh4 : g_a2h4));
}
__device__ __forceinline__ const __nv_bfloat16* alo(int a) {
    return (const __nv_bfloat16*)(a == 0 ? g_al4 : (a == 1 ? g_rell4 : g_a2l4));
}

// ---------------- block reductions (256 threads) ----------------
__device__ __forceinline__ float blk_reduce_sum(float v) {
    __shared__ float red[256];
    int tid = threadIdx.x;
    red[tid] = v; __syncthreads();
    for (int s = 128; s > 0; s >>= 1) {
        if (tid < s) red[tid] += red[tid + s];
        __syncthreads();
    }
    float r = red[0]; __syncthreads();
    return r;
}

__device__ __forceinline__ float blk_reduce_max(float v) {
    __shared__ float redm[256];
    int tid = threadIdx.x;
    redm[tid] = v; __syncthreads();
    for (int s = 128; s > 0; s >>= 1) {
        if (tid < s) redm[tid] = fmaxf(redm[tid], redm[tid + s]);
        __syncthreads();
    }
    float r = redm[0]; __syncthreads();
    return r;
}

// ---------------- relative position bucket indices ----------------
__global__ void relidx_kernel() {
    int idx = blockIdx.x * blockDim.x + threadIdx.x;
    if (idx >= SQ * SQ) return;
    int i = idx >> 9, j = idx & 511;
    int rel = i - j;
    int bucket;
    if (rel >= -128 && rel <= 128) {
        bucket = rel;
    } else {
        float abs_pos = fabsf((float)rel);
        float log_pos = ceilf(logf(abs_pos / 128.0f) / logf(511.0f / 128.0f) * 127.0f) + 128.0f;
        bucket = (int)(rel > 0 ? log_pos : -log_pos);
    }
    int c = bucket + 256; c = c < 0 ? 0 : (c > 511 ? 511 : c);
    int p = -bucket + 256; p = p < 0 ? 0 : (p > 511 ? 511 : p);
    g_ic2p[idx] = c;
    g_ip2c[idx] = p;
}

// ---------------- embedding gather + LN * mask ----------------
__global__ void embed_ln_kernel(const int* __restrict__ ids, const int* __restrict__ mask,
                                const float* __restrict__ we, const float* __restrict__ te,
                                const float* __restrict__ lns, const float* __restrict__ lnb) {
    int r = blockIdx.x, tid = threadIdx.x;
    size_t id = (size_t)ids[r];
    float v[3];
#pragma unroll
    for (int t = 0; t < 3; t++) {
        int c = tid + t * 256;
        v[t] = we[id * HD + c] + te[c];
    }
    float mu = blk_reduce_sum(v[0] + v[1] + v[2]) * (1.0f / HD);
    float sq = 0.f;
#pragma unroll
    for (int t = 0; t < 3; t++) { float d = v[t] - mu; sq += d * d; }
    float var = blk_reduce_sum(sq) * (1.0f / HD);
    float inv = rsqrtf(var + 1e-7f);
    float mf = (float)mask[r];
#pragma unroll
    for (int t = 0; t < 3; t++) {
        int c = tid + t * 256;
        g_x[(size_t)r * HD + c] = ((v[t] - mu) * inv * lns[c] + lnb[c]) * mf;
    }
}

// ---------------- LN of relative embeddings ----------------
__global__ void rel_ln_kernel(const float* __restrict__ re,
                              const float* __restrict__ lns, const float* __restrict__ lnb) {
    int r = blockIdx.x, tid = threadIdx.x;
    float v[3];
#pragma unroll
    for (int t = 0; t < 3; t++) v[t] = re[(size_t)r * HD + tid + t * 256];
    float mu = blk_reduce_sum(v[0] + v[1] + v[2]) * (1.0f / HD);
    float sq = 0.f;
#pragma unroll
    for (int t = 0; t < 3; t++) { float d = v[t] - mu; sq += d * d; }
    float var = blk_reduce_sum(sq) * (1.0f / HD);
    float inv = rsqrtf(var + 1e-7f);
#pragma unroll
    for (int t = 0; t < 3; t++) {
        int c = tid + t * 256;
        g_rel[(size_t)r * HD + c] = (v[t] - mu) * inv * lns[c] + lnb[c];
    }
}

// ---------------- residual + LN (in place on g_x): x = LN(x + buf[tcode]) ----------------
__global__ void add_ln_kernel(int tcode,
                              const float* __restrict__ lns, const float* __restrict__ lnb) {
    const float* t = bufptr(tcode);
    int r = blockIdx.x, tid = threadIdx.x;
    float v[3];
#pragma unroll
    for (int c2 = 0; c2 < 3; c2++) {
        int c = tid + c2 * 256;
        v[c2] = g_x[(size_t)r * HD + c] + t[(size_t)r * HD + c];
    }
    float mu = blk_reduce_sum(v[0] + v[1] + v[2]) * (1.0f / HD);
    float sq = 0.f;
#pragma unroll
    for (int c2 = 0; c2 < 3; c2++) { float d = v[c2] - mu; sq += d * d; }
    float var = blk_reduce_sum(sq) * (1.0f / HD);
    float inv = rsqrtf(var + 1e-7f);
#pragma unroll
    for (int c2 = 0; c2 < 3; c2++) {
        int c = tid + c2 * 256;
        g_x[(size_t)r * HD + c] = (v[c2] - mu) * inv * lns[c] + lnb[c];
    }
}

// ---------------- fp32 -> bf16 hi/lo helpers ----------------
__device__ __forceinline__ void split_store(float x, __nv_bfloat16* dh, __nv_bfloat16* dl, size_t i) {
    __nv_bfloat16 hh = __float2bfloat16(x);
    dh[i] = hh;
    dl[i] = __float2bfloat16(x - __bfloat162float(hh));
}

// convert activations: buf[scode] fp32 -> (which==0: g_ah4/g_al4, 1: rel)
__global__ void conva_kernel(int scode, int which, int n4) {
    int idx = blockIdx.x * blockDim.x + threadIdx.x;
    if (idx >= n4) return;
    const float* src = bufptr(scode);
    float4 v = ((const float4*)src)[idx];
    unsigned short h[4], l[4];
    float vv[4] = {v.x, v.y, v.z, v.w};
#pragma unroll
    for (int t = 0; t < 4; t++) {
        __nv_bfloat16 hh = __float2bfloat16(vv[t]);
        h[t] = __bfloat16_as_ushort(hh);
        l[t] = __bfloat16_as_ushort(__float2bfloat16(vv[t] - __bfloat162float(hh)));
    }
    uint2 hw = make_uint2((unsigned)h[0] | ((unsigned)h[1] << 16), (unsigned)h[2] | ((unsigned)h[3] << 16));
    uint2 lw = make_uint2((unsigned)l[0] | ((unsigned)l[1] << 16), (unsigned)l[2] | ((unsigned)l[3] << 16));
    uint2* dh = which ? (uint2*)g_relh4 : (uint2*)g_ah4;
    uint2* dl = which ? (uint2*)g_rell4 : (uint2*)g_al4;
    dh[idx] = hw;
    dl[idx] = lw;
}

// transpose + convert weights: W[K][N] fp32 -> BT[N][K] bf16 hi/lo
__global__ void transb_kernel(const float* __restrict__ W, int K, int N) {
    __shared__ float tile[32][33];
    int k0 = blockIdx.y * 32, n0 = blockIdx.x * 32;
    int tx = threadIdx.x, ty = threadIdx.y;   // (32, 8)
#pragma unroll
    for (int i = 0; i < 4; i++)
        tile[ty + i * 8][tx] = W[(size_t)(k0 + ty + i * 8) * N + n0 + tx];
    __syncthreads();
    __nv_bfloat16* oh = (__nv_bfloat16*)g_bth4;
    __nv_bfloat16* ol = (__nv_bfloat16*)g_btl4;
#pragma unroll
    for (int i = 0; i < 4; i++) {
        int n = n0 + ty + i * 8;
        float v = tile[tx][ty + i * 8];
        __nv_bfloat16 hh = __float2bfloat16(v);
        oh[(size_t)n * K + k0 + tx] = hh;
        ol[(size_t)n * K + k0 + tx] = __float2bfloat16(v - __bfloat162float(hh));
    }
}

// ---------------- mma wrapper ----------------
__device__ __forceinline__ void mma16816(float* c, const unsigned* a, const unsigned* b) {
    asm volatile(
        "mma.sync.aligned.m16n8k16.row.col.f32.bf16.bf16.f32 "
        "{%0,%1,%2,%3}, {%4,%5,%6,%7}, {%8,%9}, {%0,%1,%2,%3};"
        : "+f"(c[0]), "+f"(c[1]), "+f"(c[2]), "+f"(c[3])
        : "r"(a[0]), "r"(a[1]), "r"(a[2]), "r"(a[3]), "r"(b[0]), "r"(b[1]));
}

// ---------------- tensor-core GEMM: C = A @ B + bias (split bf16, fp32 accum) ----------------
// Block tile 64(M) x 128(N) x 32(K); 8 warps (2x4), warp tile 32x32.
// MODE 0: fp32 plain; MODE 1: GELU -> split bf16 to a2 pair; MODE 2: split bf16
// head-major [bh|h][s][64] to pair dpair; MODE 3: split bf16 transposed [bh][d][s].
#define SW_A_HI 0
#define SW_A_LO 1280
#define SW_B_HI 2560
#define SW_B_LO 5120

template<int MODE>
__global__ void __launch_bounds__(256)
tc_gemm_kernel(int acode, const float* __restrict__ bias, int ccode,
               float* __restrict__ Cext, int dpair, int M, int N, int K) {
    const __nv_bfloat16* Ah = ahi(acode);
    const __nv_bfloat16* Al = alo(acode);
    const __nv_bfloat16* Bh = (const __nv_bfloat16*)g_bth4;
    const __nv_bfloat16* Bl = (const __nv_bfloat16*)g_btl4;

    __shared__ unsigned S[7680];

    const int bm = blockIdx.y * 64, bn = blockIdx.x * 128;
    const int tid = threadIdx.x;

    const __nv_bfloat16* a_src[2];
    int a_dst[2];
#pragma unroll
    for (int it = 0; it < 2; it++) {
        int flat = tid + it * 256;
        int hl = flat >> 8;
        int rem = flat & 255;
        int r = rem >> 2, qq = rem & 3;
        a_src[it] = (hl ? Al : Ah) + (size_t)(bm + r) * K + qq * 8;
        a_dst[it] = (hl ? SW_A_LO : SW_A_HI) + r * 20 + qq * 4;
    }
    const __nv_bfloat16* b_src[4];
    int b_dst[4];
#pragma unroll
    for (int it = 0; it < 4; it++) {
        int flat = tid + it * 256;
        int hl = flat >> 9;
        int rem = flat & 511;
        int r = rem >> 2, qq = rem & 3;
        b_src[it] = (hl ? Bl : Bh) + (size_t)(bn + r) * K + qq * 8;
        b_dst[it] = (hl ? SW_B_LO : SW_B_HI) + r * 20 + qq * 4;
    }

    const int lane = tid & 31, g = lane >> 2, tig = lane & 3;
    const int warp = tid >> 5;
    const int wm = (warp & 1) * 32, wn = (warp >> 1) * 32;

    float acc[2][4][4] = {};
    const int nt = K >> 5;

    uint4 pa[2], pb[4];
#pragma unroll
    for (int it = 0; it < 2; it++) pa[it] = *(const uint4*)a_src[it];
#pragma unroll
    for (int it = 0; it < 4; it++) pb[it] = *(const uint4*)b_src[it];

#pragma unroll 1
    for (int t = 0; t < nt; t++) {
#pragma unroll
        for (int it = 0; it < 2; it++) *(uint4*)&S[a_dst[it]] = pa[it];
#pragma unroll
        for (int it = 0; it < 4; it++) *(uint4*)&S[b_dst[it]] = pb[it];
        __syncthreads();
        if (t + 1 < nt) {
            int ko = (t + 1) * 32;
#pragma unroll
            for (int it = 0; it < 2; it++) pa[it] = *(const uint4*)(a_src[it] + ko);
#pragma unroll
            for (int it = 0; it < 4; it++) pb[it] = *(const uint4*)(b_src[it] + ko);
        }
#pragma unroll
        for (int step = 0; step < 2; step++) {
            const int so = step * 8 + tig;
            unsigned ah[2][4], bh[4][2];
#pragma unroll
            for (int mi = 0; mi < 2; mi++) {
                unsigned base = SW_A_HI + (wm + mi * 16 + g) * 20 + so;
                ah[mi][0] = S[base];     ah[mi][1] = S[base + 160];
                ah[mi][2] = S[base + 4]; ah[mi][3] = S[base + 164];
            }
#pragma unroll
            for (int nj = 0; nj < 4; nj++) {
                unsigned base = SW_B_HI + (wn + nj * 8 + g) * 20 + so;
                bh[nj][0] = S[base];  bh[nj][1] = S[base + 4];
            }
#pragma unroll
            for (int mi = 0; mi < 2; mi++)
#pragma unroll
                for (int nj = 0; nj < 4; nj++) mma16816(acc[mi][nj], ah[mi], bh[nj]);
            {
                unsigned bl[4][2];
#pragma unroll
                for (int nj = 0; nj < 4; nj++) {
                    unsigned base = SW_B_LO + (wn + nj * 8 + g) * 20 + so;
                    bl[nj][0] = S[base];  bl[nj][1] = S[base + 4];
                }
#pragma unroll
                for (int mi = 0; mi < 2; mi++)
#pragma unroll
                    for (int nj = 0; nj < 4; nj++) mma16816(acc[mi][nj], ah[mi], bl[nj]);
            }
            {
                unsigned al[2][4];
#pragma unroll
                for (int mi = 0; mi < 2; mi++) {
                    unsigned base = SW_A_LO + (wm + mi * 16 + g) * 20 + so;
                    al[mi][0] = S[base];     al[mi][1] = S[base + 160];
                    al[mi][2] = S[base + 4]; al[mi][3] = S[base + 164];
                }
#pragma unroll
                for (int mi = 0; mi < 2; mi++)
#pragma unroll
                    for (int nj = 0; nj < 4; nj++) mma16816(acc[mi][nj], al[mi], bh[nj]);
            }
        }
        __syncthreads();
    }

    // ---- epilogue ----
    float* C = (MODE == 0) ? ((ccode < 0) ? Cext : bufptr(ccode)) : 0;
    __nv_bfloat16* Dh = 0;
    __nv_bfloat16* Dl = 0;
    if (MODE == 1) { Dh = (__nv_bfloat16*)g_a2h4; Dl = (__nv_bfloat16*)g_a2l4; }
    if (MODE == 2 || MODE == 3) { Dh = phi(dpair); Dl = plo(dpair); }
#pragma unroll
    for (int mi = 0; mi < 2; mi++) {
#pragma unroll
        for (int nj = 0; nj < 4; nj++) {
#pragma unroll
            for (int rr = 0; rr < 4; rr++) {
                int m = bm + wm + mi * 16 + g + (rr >> 1) * 8;
                int n = bn + wn + nj * 8 + tig * 2 + (rr & 1);
                float v = acc[mi][nj][rr] + bias[n];
                if (MODE == 0) {
                    C[(size_t)m * N + n] = v;
                } else if (MODE == 1) {
                    v = 0.5f * v * (1.0f + erff(v * 0.70710678118654752f));
                    split_store(v, Dh, Dl, (size_t)m * N + n);
                } else if (MODE == 2) {
                    int b = m >> 9, s2 = m & 511, h = n >> 6, d = n & 63;
                    size_t row = (M == SQ) ? (size_t)h : (size_t)(b * NHH + h);
                    split_store(v, Dh, Dl, (row * SQ + s2) * DHH + d);
                } else {  // MODE 3: vT
                    int b = m >> 9, s2 = m & 511, h = n >> 6, d = n & 63;
                    split_store(v, Dh, Dl, (((size_t)(b * NHH + h)) * DHH + d) * SQ + s2);
                }
            }
        }
    }
}

// ---------------- batched TC NT GEMM (scores): C[bh] = A[bh] @ B[bh%bmod]^T ----------------
// A,B split bf16 [rows][64]; C fp32 [512][512]. Tile 64x128x32, K=64.
__global__ void __launch_bounds__(256)
tc_bgemm_nt_kernel(int apair, int bpair, int ccode, int bmod) {
    const int bh = blockIdx.z;
    const __nv_bfloat16* Ah = phi(apair) + (size_t)bh * SQ * DHH;
    const __nv_bfloat16* Al = plo(apair) + (size_t)bh * SQ * DHH;
    const __nv_bfloat16* Bh = phi(bpair) + (size_t)(bh % bmod) * SQ * DHH;
    const __nv_bfloat16* Bl = plo(bpair) + (size_t)(bh % bmod) * SQ * DHH;
    float* Cb = (ccode == 0 ? g_s0 : (ccode == 1 ? g_c2p : g_p2c)) + (size_t)bh * SQ * SQ;

    __shared__ unsigned S[7680];
    const int bm = blockIdx.y * 64, bn = blockIdx.x * 128;
    const int tid = threadIdx.x;

    const __nv_bfloat16* a_src[2];
    int a_dst[2];
#pragma unroll
    for (int it = 0; it < 2; it++) {
        int flat = tid + it * 256;
        int hl = flat >> 8, rem = flat & 255;
        int r = rem >> 2, qq = rem & 3;
        a_src[it] = (hl ? Al : Ah) + (size_t)(bm + r) * DHH + qq * 8;
        a_dst[it] = (hl ? SW_A_LO : SW_A_HI) + r * 20 + qq * 4;
    }
    const __nv_bfloat16* b_src[4];
    int b_dst[4];
#pragma unroll
    for (int it = 0; it < 4; it++) {
        int flat = tid + it * 256;
        int hl = flat >> 9, rem = flat & 511;
        int r = rem >> 2, qq = rem & 3;
        b_src[it] = (hl ? Bl : Bh) + (size_t)(bn + r) * DHH + qq * 8;
        b_dst[it] = (hl ? SW_B_LO : SW_B_HI) + r * 20 + qq * 4;
    }

    const int lane = tid & 31, g = lane >> 2, tig = lane & 3;
    const int warp = tid >> 5;
    const int wm = (warp & 1) * 32, wn = (warp >> 1) * 32;

    float acc[2][4][4] = {};
    uint4 pa[2], pb[4];
#pragma unroll
    for (int it = 0; it < 2; it++) pa[it] = *(const uint4*)a_src[it];
#pragma unroll
    for (int it = 0; it < 4; it++) pb[it] = *(const uint4*)b_src[it];

#pragma unroll 1
    for (int t = 0; t < 2; t++) {
#pragma unroll
        for (int it = 0; it < 2; it++) *(uint4*)&S[a_dst[it]] = pa[it];
#pragma unroll
        for (int it = 0; it < 4; it++) *(uint4*)&S[b_dst[it]] = pb[it];
        __syncthreads();
        if (t == 0) {
#pragma unroll
            for (int it = 0; it < 2; it++) pa[it] = *(const uint4*)(a_src[it] + 32);
#pragma unroll
            for (int it = 0; it < 4; it++) pb[it] = *(const uint4*)(b_src[it] + 32);
        }
#pragma unroll
        for (int step = 0; step < 2; step++) {
            const int so = step * 8 + tig;
            unsigned ah[2][4], bh[4][2];
#pragma unroll
            for (int mi = 0; mi < 2; mi++) {
                unsigned base = SW_A_HI + (wm + mi * 16 + g) * 20 + so;
                ah[mi][0] = S[base];     ah[mi][1] = S[base + 160];
                ah[mi][2] = S[base + 4]; ah[mi][3] = S[base + 164];
            }
#pragma unroll
            for (int nj = 0; nj < 4; nj++) {
                unsigned base = SW_B_HI + (wn + nj * 8 + g) * 20 + so;
                bh[nj][0] = S[base];  bh[nj][1] = S[base + 4];
            }
#pragma unroll
            for (int mi = 0; mi < 2; mi++)
#pragma unroll
                for (int nj = 0; nj < 4; nj++) mma16816(acc[mi][nj], ah[mi], bh[nj]);
            {
                unsigned bl[4][2];
#pragma unroll
                for (int nj = 0; nj < 4; nj++) {
                    unsigned base = SW_B_LO + (wn + nj * 8 + g) * 20 + so;
                    bl[nj][0] = S[base];  bl[nj][1] = S[base + 4];
                }
#pragma unroll
                for (int mi = 0; mi < 2; mi++)
#pragma unroll
                    for (int nj = 0; nj < 4; nj++) mma16816(acc[mi][nj], ah[mi], bl[nj]);
            }
            {
                unsigned al[2][4];
#pragma unroll
                for (int mi = 0; mi < 2; mi++) {
                    unsigned base = SW_A_LO + (wm + mi * 16 + g) * 20 + so;
                    al[mi][0] = S[base];     al[mi][1] = S[base + 160];
                    al[mi][2] = S[base + 4]; al[mi][3] = S[base + 164];
                }
#pragma unroll
                for (int mi = 0; mi < 2; mi++)
#pragma unroll
                    for (int nj = 0; nj < 4; nj++) mma16816(acc[mi][nj], al[mi], bh[nj]);
            }
        }
        __syncthreads();
    }
#pragma unroll
    for (int mi = 0; mi < 2; mi++)
#pragma unroll
        for (int nj = 0; nj < 4; nj++)
#pragma unroll
            for (int rr = 0; rr < 4; rr++) {
                int m = bm + wm + mi * 16 + g + (rr >> 1) * 8;
                int n = bn + wn + nj * 8 + tig * 2 + (rr & 1);
                Cb[(size_t)m * SQ + n] = acc[mi][nj][rr];
            }
}

// ---------------- TC ctx GEMM: ctx[bh] = probs[bh] @ vT[bh]^T ----------------
// A = probs [512][512], B = vT [64][512]; tile 128(M)x64(N)x32; warps 4x2.
__global__ void __launch_bounds__(256)
tc_bgemm_ctx_kernel() {
    const int bh = blockIdx.y;
    const int b = bh / NHH, h = bh % NHH;
    const __nv_bfloat16* Ah = (const __nv_bfloat16*)g_ph4 + (size_t)bh * SQ * SQ;
    const __nv_bfloat16* Al = (const __nv_bfloat16*)g_pl4 + (size_t)bh * SQ * SQ;
    const __nv_bfloat16* Bh = (const __nv_bfloat16*)g_vth4 + (size_t)bh * DHH * SQ;
    const __nv_bfloat16* Bl = (const __nv_bfloat16*)g_vtl4 + (size_t)bh * DHH * SQ;

    __shared__ unsigned S[7680];   // A hi [0..2560) lo [2560..5120), B hi [5120..6400) lo [6400..7680)
    const int bm = blockIdx.x * 128;
    const int tid = threadIdx.x;

    // A: 128 rows x 16w x2 = 1024 uint4, 4/thread
    const __nv_bfloat16* a_src[4];
    int a_dst[4];
#pragma unroll
    for (int it = 0; it < 4; it++) {
        int flat = tid + it * 256;
        int hl = flat >> 9, rem = flat & 511;
        int r = rem >> 2, qq = rem & 3;
        a_src[it] = (hl ? Al : Ah) + (size_t)(bm + r) * SQ + qq * 8;
        a_dst[it] = (hl ? 2560 : 0) + r * 20 + qq * 4;
    }
    // B: 64 rows x 16w x2 = 512 uint4, 2/thread
    const __nv_bfloat16* b_src[2];
    int b_dst[2];
#pragma unroll
    for (int it = 0; it < 2; it++) {
        int flat = tid + it * 256;
        int hl = flat >> 8, rem = flat & 255;
        int r = rem >> 2, qq = rem & 3;
        b_src[it] = (hl ? Bl : Bh) + (size_t)r * SQ + qq * 8;
        b_dst[it] = (hl ? 6400 : 5120) + r * 20 + qq * 4;
    }

    const int lane = tid & 31, g = lane >> 2, tig = lane & 3;
    const int warp = tid >> 5;
    const int wm = (warp & 3) * 32, wn = (warp >> 2) * 32;

    float acc[2][4][4] = {};
    uint4 pa[4], pb[2];
#pragma unroll
    for (int it = 0; it < 4; it++) pa[it] = *(const uint4*)a_src[it];
#pragma unroll
    for (int it = 0; it < 2; it++) pb[it] = *(const uint4*)b_src[it];

#pragma unroll 1
    for (int t = 0; t < 16; t++) {
#pragma unroll
        for (int it = 0; it < 4; it++) *(uint4*)&S[a_dst[it]] = pa[it];
#pragma unroll
        for (int it = 0; it < 2; it++) *(uint4*)&S[b_dst[it]] = pb[it];
        __syncthreads();
        if (t + 1 < 16) {
            int ko = (t + 1) * 32;
#pragma unroll
            for (int it = 0; it < 4; it++) pa[it] = *(const uint4*)(a_src[it] + ko);
#pragma unroll
            for (int it = 0; it < 2; it++) pb[it] = *(const uint4*)(b_src[it] + ko);
        }
#pragma unroll
        for (int step = 0; step < 2; step++) {
            const int so = step * 8 + tig;
            unsigned ah[2][4], bh[4][2];
#pragma unroll
            for (int mi = 0; mi < 2; mi++) {
                unsigned base = 0 + (wm + mi * 16 + g) * 20 + so;
                ah[mi][0] = S[base];     ah[mi][1] = S[base + 160];
                ah[mi][2] = S[base + 4]; ah[mi][3] = S[base + 164];
            }
#pragma unroll
            for (int nj = 0; nj < 4; nj++) {
                unsigned base = 5120 + (wn + nj * 8 + g) * 20 + so;
                bh[nj][0] = S[base];  bh[nj][1] = S[base + 4];
            }
#pragma unroll
            for (int mi = 0; mi < 2; mi++)
#pragma unroll
                for (int nj = 0; nj < 4; nj++) mma16816(acc[mi][nj], ah[mi], bh[nj]);
            {
                unsigned bl[4][2];
#pragma unroll
                for (int nj = 0; nj < 4; nj++) {
                    unsigned base = 6400 + (wn + nj * 8 + g) * 20 + so;
                    bl[nj][0] = S[base];  bl[nj][1] = S[base + 4];
                }
#pragma unroll
                for (int mi = 0; mi < 2; mi++)
#pragma unroll
                    for (int nj = 0; nj < 4; nj++) mma16816(acc[mi][nj], ah[mi], bl[nj]);
            }
            {
                unsigned al[2][4];
#pragma unroll
                for (int mi = 0; mi < 2; mi++) {
                    unsigned base = 2560 + (wm + mi * 16 + g) * 20 + so;
                    al[mi][0] = S[base];     al[mi][1] = S[base + 160];
                    al[mi][2] = S[base + 4]; al[mi][3] = S[base + 164];
                }
#pragma unroll
                for (int mi = 0; mi < 2; mi++)
#pragma unroll
                    for (int nj = 0; nj < 4; nj++) mma16816(acc[mi][nj], al[mi], bh[nj]);
            }
        }
        __syncthreads();
    }
#pragma unroll
    for (int mi = 0; mi < 2; mi++)
#pragma unroll
        for (int nj = 0; nj < 4; nj++)
#pragma unroll
            for (int rr = 0; rr < 4; rr++) {
                int m = bm + wm + mi * 16 + g + (rr >> 1) * 8;
                int n = wn + nj * 8 + tig * 2 + (rr & 1);
                g_t2[((size_t)(b * SQ + m)) * HD + h * DHH + n] = acc[mi][nj][rr];
            }
}

// ---------------- SIMT SGEMM (cls head only, N=9) ----------------
template<int MODE>
__global__ void __launch_bounds__(256)
sgemm_kernel(int acode, const float* __restrict__ Bm,
             const float* __restrict__ bias, int ccode, float* __restrict__ Cext,
             int M, int N, int K) {
    const float* A = bufptr(acode);
    float* C = (ccode < 0) ? Cext : bufptr(ccode);
    __shared__ float As[16][68];
    __shared__ float Bs[16][68];
    int bm = blockIdx.y * 64, bn = blockIdx.x * 64;
    int tid = threadIdx.x;
    int tr = tid >> 4, tc = tid & 15;
    float acc[4][4] = {};
#pragma unroll 1
    for (int k0 = 0; k0 < K; k0 += 16) {
#pragma unroll
        for (int i = tid; i < 1024; i += 256) {
            int m = i >> 4, kk = i & 15;
            As[kk][m] = A[(size_t)(bm + m) * K + k0 + kk];
        }
#pragma unroll
        for (int i = tid; i < 1024; i += 256) {
            int kk = i >> 6, n = i & 63;
            Bs[kk][n] = (bn + n < N) ? Bm[(size_t)(k0 + kk) * N + bn + n] : 0.f;
        }
        __syncthreads();
#pragma unroll
        for (int kk = 0; kk < 16; kk++) {
            float4 a4 = *(const float4*)&As[kk][tr * 4];
            float4 b4 = *(const float4*)&Bs[kk][tc * 4];
            float a[4] = {a4.x, a4.y, a4.z, a4.w};
            float b[4] = {b4.x, b4.y, b4.z, b4.w};
#pragma unroll
            for (int i2 = 0; i2 < 4; i2++)
#pragma unroll
                for (int j = 0; j < 4; j++) acc[i2][j] += a[i2] * b[j];
        }
        __syncthreads();
    }
#pragma unroll
    for (int i2 = 0; i2 < 4; i2++) {
        int m = bm + tr * 4 + i2;
#pragma unroll
        for (int j = 0; j < 4; j++) {
            int n = bn + tc * 4 + j;
            if (n >= N) continue;
            C[(size_t)m * N + n] = acc[i2][j] + bias[n];
        }
    }
}

// ---------------- attention combine + gather + mask + softmax -> split bf16 probs ----------------
__global__ void attn_softmax_kernel(const int* __restrict__ mask) {
    int q = blockIdx.x, bh = blockIdx.y, b = bh / NHH;
    int tid = threadIdx.x;
    const float* row = g_s0 + ((size_t)bh * SQ + q) * SQ;
    const float* crow = g_c2p + ((size_t)bh * SQ + q) * SQ;
    const float* pbase = g_p2c + (size_t)bh * SQ * SQ;
    int mq = mask[b * SQ + q];
    float vals[2];
    float mx = -3.4028234663852886e38f;
#pragma unroll
    for (int t = 0; t < 2; t++) {
        int k = tid + t * 256;
        float v = -3.4028234663852886e38f;
        if (mq != 0 && mask[b * SQ + k] != 0) {
            v = (row[k] + crow[g_ic2p[q * SQ + k]] + pbase[(size_t)k * SQ + g_ip2c[k * SQ + q]]) * SCALEF;
        }
        vals[t] = v;
        mx = fmaxf(mx, v);
    }
    mx = blk_reduce_max(mx);
    float sum = 0.f;
#pragma unroll
    for (int t = 0; t < 2; t++) { vals[t] = expf(vals[t] - mx); sum += vals[t]; }
    sum = blk_reduce_sum(sum);
    float inv = 1.0f / sum;
    __nv_bfloat16* ph = (__nv_bfloat16*)g_ph4;
    __nv_bfloat16* pl = (__nv_bfloat16*)g_pl4;
#pragma unroll
    for (int t = 0; t < 2; t++) {
        float p = vals[t] * inv;
        size_t o = ((size_t)bh * SQ + q) * SQ + tid + t * 256;
        __nv_bfloat16 hh = __float2bfloat16(p);
        ph[o] = hh;
        pl[o] = __float2bfloat16(p - __bfloat162float(hh));
    }
}

// ---------------- launch ----------------
extern "C" void kernel_launch(void* const* d_in, const int* in_sizes, int n_in,
                              void* d_out, int out_size) {
    const int*   ids     = (const int*)d_in[0];
    const int*   mask    = (const int*)d_in[1];
    const float* we      = (const float*)d_in[2];
    const float* te      = (const float*)d_in[3];
    const float* elns    = (const float*)d_in[4];
    const float* elnb    = (const float*)d_in[5];
    const float* rel_emb = (const float*)d_in[6];
    const float* rlns    = (const float*)d_in[7];
    const float* rlnb    = (const float*)d_in[8];
    const float* qw      = (const float*)d_in[9];
    const float* qb      = (const float*)d_in[10];
    const float* kw      = (const float*)d_in[11];
    const float* kb      = (const float*)d_in[12];
    const float* vw      = (const float*)d_in[13];
    const float* vb      = (const float*)d_in[14];
    const float* aow     = (const float*)d_in[15];
    const float* aob     = (const float*)d_in[16];
    const float* alns    = (const float*)d_in[17];
    const float* alnb    = (const float*)d_in[18];
    const float* iw      = (const float*)d_in[19];
    const float* ib      = (const float*)d_in[20];
    const float* ow      = (const float*)d_in[21];
    const float* ob      = (const float*)d_in[22];
    const float* olns    = (const float*)d_in[23];
    const float* olnb    = (const float*)d_in[24];
    const float* clsw    = (const float*)d_in[25];
    const float* clsb    = (const float*)d_in[26];
    float* out = (float*)d_out;

    relidx_kernel<<<1024, 256>>>();
    rel_ln_kernel<<<SQ, 256>>>(rel_emb, rlns, rlnb);
    embed_ln_kernel<<<NTOK, 256>>>(ids, mask, we, te, elns, elnb);

    conva_kernel<<<(SQ * HD / 4 + 255) / 256, 256>>>(BUF_REL, 1, SQ * HD / 4);

    dim3 tb(32, 8);
    dim3 gTransHH(HD / 32, HD / 32);
    dim3 gTransIF(FFD / 32, HD / 32);
    dim3 gTransOF(HD / 32, FFD / 32);

    dim3 gTcProj(HD / 128, NTOK / 64);     // (6, 32)
    dim3 gTcPos(HD / 128, SQ / 64);        // (6, 8)
    dim3 gTcFF1(FFD / 128, NTOK / 64);     // (24, 32)
    dim3 gTcFF2(HD / 128, NTOK / 64);      // (6, 32)

    dim3 gScore(SQ / 128, SQ / 64, BHH);   // (4, 8, 48)
    dim3 gSm(SQ, BHH);
    dim3 gCtx(SQ / 128, BHH);              // (4, 48)
    dim3 gCls(1, 32);

    const int nX4 = NTOK * HD / 4;

    for (int l = 0; l < NLAYER; l++) {
        const float* qwl = qw + (size_t)l * HD * HD;
        const float* kwl = kw + (size_t)l * HD * HD;
        const float* vwl = vw + (size_t)l * HD * HD;
        const float* aowl = aow + (size_t)l * HD * HD;
        const float* iwl = iw + (size_t)l * HD * FFD;
        const float* owl = ow + (size_t)l * FFD * HD;
        const float* qbl = qb + (size_t)l * HD;
        const float* kbl = kb + (size_t)l * HD;
        const float* vbl = vb + (size_t)l * HD;
        const float* aobl = aob + (size_t)l * HD;
        const float* ibl = ib + (size_t)l * FFD;
        const float* obl = ob + (size_t)l * HD;

        conva_kernel<<<(nX4 + 255) / 256, 256>>>(BUF_X, 0, nX4);

        transb_kernel<<<gTransHH, tb>>>(qwl, HD, HD);
        tc_gemm_kernel<2><<<gTcProj, 256>>>(0, qbl, 0, 0, 0, NTOK, HD, HD);   // q
        tc_gemm_kernel<2><<<gTcPos, 256>>>(1, qbl, 0, 0, 3, SQ, HD, HD);      // pq

        transb_kernel<<<gTransHH, tb>>>(kwl, HD, HD);
        tc_gemm_kernel<2><<<gTcProj, 256>>>(0, kbl, 0, 0, 1, NTOK, HD, HD);   // k
        tc_gemm_kernel<2><<<gTcPos, 256>>>(1, kbl, 0, 0, 2, SQ, HD, HD);      // pk

        transb_kernel<<<gTransHH, tb>>>(vwl, HD, HD);
        tc_gemm_kernel<3><<<gTcProj, 256>>>(0, vbl, 0, 0, 4, NTOK, HD, HD);   // vT

        tc_bgemm_nt_kernel<<<gScore, 256>>>(0, 1, 0, BHH);   // q @ k^T  -> g_s0
        tc_bgemm_nt_kernel<<<gScore, 256>>>(0, 2, 1, NHH);   // q @ pk^T -> g_c2p
        tc_bgemm_nt_kernel<<<gScore, 256>>>(1, 3, 2, NHH);   // k @ pq^T -> g_p2c

        attn_softmax_kernel<<<gSm, 256>>>(mask);             // -> probs split bf16

        tc_bgemm_ctx_kernel<<<gCtx, 256>>>();                // -> g_t2 [B,S,H]

        conva_kernel<<<(nX4 + 255) / 256, 256>>>(BUF_T2, 0, nX4);
        transb_kernel<<<gTransHH, tb>>>(aowl, HD, HD);
        tc_gemm_kernel<0><<<gTcProj, 256>>>(0, aobl, BUF_T1, 0, 0, NTOK, HD, HD);
        add_ln_kernel<<<NTOK, 256>>>(BUF_T1, alns + (size_t)l * HD, alnb + (size_t)l * HD);

        conva_kernel<<<(nX4 + 255) / 256, 256>>>(BUF_X, 0, nX4);
        transb_kernel<<<gTransIF, tb>>>(iwl, HD, FFD);
        tc_gemm_kernel<1><<<gTcFF1, 256>>>(0, ibl, 0, 0, 0, NTOK, FFD, HD);   // GELU -> a2

        transb_kernel<<<gTransOF, tb>>>(owl, FFD, HD);
        tc_gemm_kernel<0><<<gTcFF2, 256>>>(2, obl, BUF_T2, 0, 0, NTOK, HD, FFD);
        add_ln_kernel<<<NTOK, 256>>>(BUF_T2, olns + (size_t)l * HD, olnb + (size_t)l * HD);
    }

    sgemm_kernel<0><<<gCls, 256>>>(BUF_X, clsw, clsb, BUF_EXT, out, NTOK, NCLS, HD);
}

// round 14
// speedup vs baseline: 1.7145x; 1.0934x over previous
#include <cuda_runtime.h>
#include <cuda_bf16.h>
#include <math.h>

#define SQ   512
#define HD   768
#define NHH  12
#define DHH  64
#define BHH  48          // B * NH
#define FFD  3072
#define NCLS 9
#define NLAYER 12
#define NTOK 2048        // B * S
#define SCALEF 0.07216878364870323f   // 1/sqrt(64*3)

// ---------------- scratch (allocation-free: __device__ globals) ----------------
__device__ float g_x[NTOK * HD];
__device__ float g_rel[SQ * HD];
__device__ float g_s0[BHH * SQ * SQ];
__device__ float g_c2p[BHH * SQ * SQ];
__device__ float g_p2c[BHH * SQ * SQ];
__device__ float g_t1[NTOK * HD];
__device__ float g_t2[NTOK * HD];
__device__ int   g_ic2p[SQ * SQ];
__device__ int   g_ip2c[SQ * SQ];

// split-bf16 operand buffers
__device__ uint4 g_ah4[NTOK * HD / 8];
__device__ uint4 g_al4[NTOK * HD / 8];
__device__ uint4 g_a2h4[NTOK * FFD / 8];
__device__ uint4 g_a2l4[NTOK * FFD / 8];
__device__ uint4 g_relh4[SQ * HD / 8];
__device__ uint4 g_rell4[SQ * HD / 8];
__device__ uint4 g_bth4[FFD * HD / 8];
__device__ uint4 g_btl4[FFD * HD / 8];
__device__ uint4 g_qh4[BHH * SQ * DHH / 8];
__device__ uint4 g_ql4[BHH * SQ * DHH / 8];
__device__ uint4 g_kh4[BHH * SQ * DHH / 8];
__device__ uint4 g_kl4[BHH * SQ * DHH / 8];
__device__ uint4 g_pkh4[NHH * SQ * DHH / 8];
__device__ uint4 g_pkl4[NHH * SQ * DHH / 8];
__device__ uint4 g_pqh4[NHH * SQ * DHH / 8];
__device__ uint4 g_pql4[NHH * SQ * DHH / 8];
__device__ uint4 g_vth4[BHH * DHH * SQ / 8];
__device__ uint4 g_vtl4[BHH * DHH * SQ / 8];
__device__ uint4 g_ph4[BHH * SQ * SQ / 8];
__device__ uint4 g_pl4[BHH * SQ * SQ / 8];

#define BUF_X   0
#define BUF_REL 6
#define BUF_T1  10
#define BUF_T2  11
#define BUF_EXT (-1)

__device__ __forceinline__ float* bufptr(int c) {
    switch (c) {
        case BUF_X:   return g_x;
        case BUF_REL: return g_rel;
        case BUF_T1:  return g_t1;
        case BUF_T2:  return g_t2;
    }
    return 0;
}

// bf16 pair selectors: 0 q, 1 k, 2 pk, 3 pq, 4 vT, 5 probs
__device__ __forceinline__ __nv_bfloat16* phi(int p) {
    switch (p) {
        case 0: return (__nv_bfloat16*)g_qh4;
        case 1: return (__nv_bfloat16*)g_kh4;
        case 2: return (__nv_bfloat16*)g_pkh4;
        case 3: return (__nv_bfloat16*)g_pqh4;
        case 4: return (__nv_bfloat16*)g_vth4;
        case 5: return (__nv_bfloat16*)g_ph4;
    }
    return 0;
}
__device__ __forceinline__ __nv_bfloat16* plo(int p) {
    switch (p) {
        case 0: return (__nv_bfloat16*)g_ql4;
        case 1: return (__nv_bfloat16*)g_kl4;
        case 2: return (__nv_bfloat16*)g_pkl4;
        case 3: return (__nv_bfloat16*)g_pql4;
        case 4: return (__nv_bfloat16*)g_vtl4;
        case 5: return (__nv_bfloat16*)g_pl4;
    }
    return 0;
}
__device__ __forceinline__ const __nv_bfloat16* ahi(int a) {
    return (const __nv_bfloat16*)(a == 0 ? g_ah4 : (a == 1 ? g_relh4 : g_a2h4));
}
__device__ __forceinline__ const __nv_bfloat16* alo(int a) {
    return (const __nv_bfloat16*)(a == 0 ? g_al4 : (a == 1 ? g_rell4 : g_a2l4));
}

// ---------------- block reductions (256 threads) ----------------
__device__ __forceinline__ float blk_reduce_sum(float v) {
    __shared__ float red[256];
    int tid = threadIdx.x;
    red[tid] = v; __syncthreads();
    for (int s = 128; s > 0; s >>= 1) {
        if (tid < s) red[tid] += red[tid + s];
        __syncthreads();
    }
    float r = red[0]; __syncthreads();
    return r;
}

__device__ __forceinline__ float blk_reduce_max(float v) {
    __shared__ float redm[256];
    int tid = threadIdx.x;
    redm[tid] = v; __syncthreads();
    for (int s = 128; s > 0; s >>= 1) {
        if (tid < s) redm[tid] = fmaxf(redm[tid], redm[tid + s]);
        __syncthreads();
    }
    float r = redm[0]; __syncthreads();
    return r;
}

// ---------------- relative position bucket indices ----------------
__global__ void relidx_kernel() {
    int idx = blockIdx.x * blockDim.x + threadIdx.x;
    if (idx >= SQ * SQ) return;
    int i = idx >> 9, j = idx & 511;
    int rel = i - j;
    int bucket;
    if (rel >= -128 && rel <= 128) {
        bucket = rel;
    } else {
        float abs_pos = fabsf((float)rel);
        float log_pos = ceilf(logf(abs_pos / 128.0f) / logf(511.0f / 128.0f) * 127.0f) + 128.0f;
        bucket = (int)(rel > 0 ? log_pos : -log_pos);
    }
    int c = bucket + 256; c = c < 0 ? 0 : (c > 511 ? 511 : c);
    int p = -bucket + 256; p = p < 0 ? 0 : (p > 511 ? 511 : p);
    g_ic2p[idx] = c;
    g_ip2c[idx] = p;
}

// ---------------- embedding gather + LN * mask ----------------
__global__ void embed_ln_kernel(const int* __restrict__ ids, const int* __restrict__ mask,
                                const float* __restrict__ we, const float* __restrict__ te,
                                const float* __restrict__ lns, const float* __restrict__ lnb) {
    int r = blockIdx.x, tid = threadIdx.x;
    size_t id = (size_t)ids[r];
    float v[3];
#pragma unroll
    for (int t = 0; t < 3; t++) {
        int c = tid + t * 256;
        v[t] = we[id * HD + c] + te[c];
    }
    float mu = blk_reduce_sum(v[0] + v[1] + v[2]) * (1.0f / HD);
    float sq = 0.f;
#pragma unroll
    for (int t = 0; t < 3; t++) { float d = v[t] - mu; sq += d * d; }
    float var = blk_reduce_sum(sq) * (1.0f / HD);
    float inv = rsqrtf(var + 1e-7f);
    float mf = (float)mask[r];
#pragma unroll
    for (int t = 0; t < 3; t++) {
        int c = tid + t * 256;
        g_x[(size_t)r * HD + c] = ((v[t] - mu) * inv * lns[c] + lnb[c]) * mf;
    }
}

// ---------------- LN of relative embeddings ----------------
__global__ void rel_ln_kernel(const float* __restrict__ re,
                              const float* __restrict__ lns, const float* __restrict__ lnb) {
    int r = blockIdx.x, tid = threadIdx.x;
    float v[3];
#pragma unroll
    for (int t = 0; t < 3; t++) v[t] = re[(size_t)r * HD + tid + t * 256];
    float mu = blk_reduce_sum(v[0] + v[1] + v[2]) * (1.0f / HD);
    float sq = 0.f;
#pragma unroll
    for (int t = 0; t < 3; t++) { float d = v[t] - mu; sq += d * d; }
    float var = blk_reduce_sum(sq) * (1.0f / HD);
    float inv = rsqrtf(var + 1e-7f);
#pragma unroll
    for (int t = 0; t < 3; t++) {
        int c = tid + t * 256;
        g_rel[(size_t)r * HD + c] = (v[t] - mu) * inv * lns[c] + lnb[c];
    }
}

// ---------------- residual + LN (in place on g_x) ----------------
__global__ void add_ln_kernel(int tcode,
                              const float* __restrict__ lns, const float* __restrict__ lnb) {
    const float* t = bufptr(tcode);
    int r = blockIdx.x, tid = threadIdx.x;
    float v[3];
#pragma unroll
    for (int c2 = 0; c2 < 3; c2++) {
        int c = tid + c2 * 256;
        v[c2] = g_x[(size_t)r * HD + c] + t[(size_t)r * HD + c];
    }
    float mu = blk_reduce_sum(v[0] + v[1] + v[2]) * (1.0f / HD);
    float sq = 0.f;
#pragma unroll
    for (int c2 = 0; c2 < 3; c2++) { float d = v[c2] - mu; sq += d * d; }
    float var = blk_reduce_sum(sq) * (1.0f / HD);
    float inv = rsqrtf(var + 1e-7f);
#pragma unroll
    for (int c2 = 0; c2 < 3; c2++) {
        int c = tid + c2 * 256;
        g_x[(size_t)r * HD + c] = (v[c2] - mu) * inv * lns[c] + lnb[c];
    }
}

// ---------------- fp32 -> bf16 hi/lo helpers ----------------
__device__ __forceinline__ void split_store(float x, __nv_bfloat16* dh, __nv_bfloat16* dl, size_t i) {
    __nv_bfloat16 hh = __float2bfloat16(x);
    dh[i] = hh;
    dl[i] = __float2bfloat16(x - __bfloat162float(hh));
}

__global__ void conva_kernel(int scode, int which, int n4) {
    int idx = blockIdx.x * blockDim.x + threadIdx.x;
    if (idx >= n4) return;
    const float* src = bufptr(scode);
    float4 v = ((const float4*)src)[idx];
    unsigned short h[4], l[4];
    float vv[4] = {v.x, v.y, v.z, v.w};
#pragma unroll
    for (int t = 0; t < 4; t++) {
        __nv_bfloat16 hh = __float2bfloat16(vv[t]);
        h[t] = __bfloat16_as_ushort(hh);
        l[t] = __bfloat16_as_ushort(__float2bfloat16(vv[t] - __bfloat162float(hh)));
    }
    uint2 hw = make_uint2((unsigned)h[0] | ((unsigned)h[1] << 16), (unsigned)h[2] | ((unsigned)h[3] << 16));
    uint2 lw = make_uint2((unsigned)l[0] | ((unsigned)l[1] << 16), (unsigned)l[2] | ((unsigned)l[3] << 16));
    uint2* dh = which ? (uint2*)g_relh4 : (uint2*)g_ah4;
    uint2* dl = which ? (uint2*)g_rell4 : (uint2*)g_al4;
    dh[idx] = hw;
    dl[idx] = lw;
}

// transpose + convert weights: W[K][N] fp32 -> BT[nofs+n][K] bf16 hi/lo
__global__ void transb_kernel(const float* __restrict__ W, int K, int N, int nofs) {
    __shared__ float tile[32][33];
    int k0 = blockIdx.y * 32, n0 = blockIdx.x * 32;
    int tx = threadIdx.x, ty = threadIdx.y;   // (32, 8)
#pragma unroll
    for (int i = 0; i < 4; i++)
        tile[ty + i * 8][tx] = W[(size_t)(k0 + ty + i * 8) * N + n0 + tx];
    __syncthreads();
    __nv_bfloat16* oh = (__nv_bfloat16*)g_bth4;
    __nv_bfloat16* ol = (__nv_bfloat16*)g_btl4;
#pragma unroll
    for (int i = 0; i < 4; i++) {
        int n = n0 + ty + i * 8;
        float v = tile[tx][ty + i * 8];
        __nv_bfloat16 hh = __float2bfloat16(v);
        oh[(size_t)(nofs + n) * K + k0 + tx] = hh;
        ol[(size_t)(nofs + n) * K + k0 + tx] = __float2bfloat16(v - __bfloat162float(hh));
    }
}

// ---------------- mma wrapper ----------------
__device__ __forceinline__ void mma16816(float* c, const unsigned* a, const unsigned* b) {
    asm volatile(
        "mma.sync.aligned.m16n8k16.row.col.f32.bf16.bf16.f32 "
        "{%0,%1,%2,%3}, {%4,%5,%6,%7}, {%8,%9}, {%0,%1,%2,%3};"
        : "+f"(c[0]), "+f"(c[1]), "+f"(c[2]), "+f"(c[3])
        : "r"(a[0]), "r"(a[1]), "r"(a[2]), "r"(a[3]), "r"(b[0]), "r"(b[1]));
}

// ---------------- tensor-core GEMM (double-buffered smem, dynamic 60KB) ----------------
// MODE 0: fp32 plain (bias b0); MODE 1: GELU -> split bf16 a2;
// MODE 4: merged qkv epilogue (n<768 q, <1536 k, else vT; bias b0/b1/b2);
// MODE 5: merged pos epilogue  (n<768 pq, else pk; bias b0/b1).
#define SW_A_HI 0
#define SW_A_LO 1280
#define SW_B_HI 2560
#define SW_B_LO 5120
#define STAGE   7680

template<int MODE>
__global__ void __launch_bounds__(256)
tc_gemm_kernel(int acode, const float* __restrict__ b0, const float* __restrict__ b1,
               const float* __restrict__ b2, int ccode, float* __restrict__ Cext,
               int M, int N, int K) {
    const __nv_bfloat16* Ah = ahi(acode);
    const __nv_bfloat16* Al = alo(acode);
    const __nv_bfloat16* Bh = (const __nv_bfloat16*)g_bth4;
    const __nv_bfloat16* Bl = (const __nv_bfloat16*)g_btl4;

    extern __shared__ unsigned S[];

    const int bm = blockIdx.y * 64, bn = blockIdx.x * 128;
    const int tid = threadIdx.x;

    const __nv_bfloat16* a_src[2];
    int a_dst[2];
#pragma unroll
    for (int it = 0; it < 2; it++) {
        int flat = tid + it * 256;
        int hl = flat >> 8, rem = flat & 255;
        int r = rem >> 2, qq = rem & 3;
        a_src[it] = (hl ? Al : Ah) + (size_t)(bm + r) * K + qq * 8;
        a_dst[it] = (hl ? SW_A_LO : SW_A_HI) + r * 20 + qq * 4;
    }
    const __nv_bfloat16* b_src[4];
    int b_dst[4];
#pragma unroll
    for (int it = 0; it < 4; it++) {
        int flat = tid + it * 256;
        int hl = flat >> 9, rem = flat & 511;
        int r = rem >> 2, qq = rem & 3;
        b_src[it] = (hl ? Bl : Bh) + (size_t)(bn + r) * K + qq * 8;
        b_dst[it] = (hl ? SW_B_LO : SW_B_HI) + r * 20 + qq * 4;
    }

    const int lane = tid & 31, g = lane >> 2, tig = lane & 3;
    const int warp = tid >> 5;
    const int wm = (warp & 1) * 32, wn = (warp >> 1) * 32;

    float acc[2][4][4] = {};
    const int nt = K >> 5;

    uint4 pa[2], pb[4];
#pragma unroll
    for (int it = 0; it < 2; it++) pa[it] = *(const uint4*)a_src[it];
#pragma unroll
    for (int it = 0; it < 4; it++) pb[it] = *(const uint4*)b_src[it];
#pragma unroll
    for (int it = 0; it < 2; it++) *(uint4*)&S[a_dst[it]] = pa[it];
#pragma unroll
    for (int it = 0; it < 4; it++) *(uint4*)&S[b_dst[it]] = pb[it];
    __syncthreads();

#pragma unroll 1
    for (int t = 0; t < nt; t++) {
        unsigned* Sc = S + (t & 1) * STAGE;
        if (t + 1 < nt) {
            int ko = (t + 1) * 32;
#pragma unroll
            for (int it = 0; it < 2; it++) pa[it] = *(const uint4*)(a_src[it] + ko);
#pragma unroll
            for (int it = 0; it < 4; it++) pb[it] = *(const uint4*)(b_src[it] + ko);
        }
#pragma unroll
        for (int step = 0; step < 2; step++) {
            const int so = step * 8 + tig;
            unsigned ah[2][4], bh[4][2];
#pragma unroll
            for (int mi = 0; mi < 2; mi++) {
                unsigned base = SW_A_HI + (wm + mi * 16 + g) * 20 + so;
                ah[mi][0] = Sc[base];     ah[mi][1] = Sc[base + 160];
                ah[mi][2] = Sc[base + 4]; ah[mi][3] = Sc[base + 164];
            }
#pragma unroll
            for (int nj = 0; nj < 4; nj++) {
                unsigned base = SW_B_HI + (wn + nj * 8 + g) * 20 + so;
                bh[nj][0] = Sc[base];  bh[nj][1] = Sc[base + 4];
            }
#pragma unroll
            for (int mi = 0; mi < 2; mi++)
#pragma unroll
                for (int nj = 0; nj < 4; nj++) mma16816(acc[mi][nj], ah[mi], bh[nj]);
            {
                unsigned bl[4][2];
#pragma unroll
                for (int nj = 0; nj < 4; nj++) {
                    unsigned base = SW_B_LO + (wn + nj * 8 + g) * 20 + so;
                    bl[nj][0] = Sc[base];  bl[nj][1] = Sc[base + 4];
                }
#pragma unroll
                for (int mi = 0; mi < 2; mi++)
#pragma unroll
                    for (int nj = 0; nj < 4; nj++) mma16816(acc[mi][nj], ah[mi], bl[nj]);
            }
            {
                unsigned al[2][4];
#pragma unroll
                for (int mi = 0; mi < 2; mi++) {
                    unsigned base = SW_A_LO + (wm + mi * 16 + g) * 20 + so;
                    al[mi][0] = Sc[base];     al[mi][1] = Sc[base + 160];
                    al[mi][2] = Sc[base + 4]; al[mi][3] = Sc[base + 164];
                }
#pragma unroll
                for (int mi = 0; mi < 2; mi++)
#pragma unroll
                    for (int nj = 0; nj < 4; nj++) mma16816(acc[mi][nj], al[mi], bh[nj]);
            }
        }
        if (t + 1 < nt) {
            unsigned* Sn = S + ((t + 1) & 1) * STAGE;
#pragma unroll
            for (int it = 0; it < 2; it++) *(uint4*)&Sn[a_dst[it]] = pa[it];
#pragma unroll
            for (int it = 0; it < 4; it++) *(uint4*)&Sn[b_dst[it]] = pb[it];
            __syncthreads();
        }
    }

    // ---- epilogue ----
#pragma unroll
    for (int mi = 0; mi < 2; mi++) {
#pragma unroll
        for (int nj = 0; nj < 4; nj++) {
#pragma unroll
            for (int rr = 0; rr < 4; rr++) {
                int m = bm + wm + mi * 16 + g + (rr >> 1) * 8;
                int n = bn + wn + nj * 8 + tig * 2 + (rr & 1);
                float v = acc[mi][nj][rr];
                if (MODE == 0) {
                    float* C = (ccode < 0) ? Cext : bufptr(ccode);
                    C[(size_t)m * N + n] = v + b0[n];
                } else if (MODE == 1) {
                    v += b0[n];
                    v = 0.5f * v * (1.0f + erff(v * 0.70710678118654752f));
                    split_store(v, (__nv_bfloat16*)g_a2h4, (__nv_bfloat16*)g_a2l4, (size_t)m * N + n);
                } else if (MODE == 4) {
                    int b = m >> 9, s2 = m & 511;
                    if (n < 768) {
                        v += b0[n];
                        int h = n >> 6, d = n & 63;
                        split_store(v, (__nv_bfloat16*)g_qh4, (__nv_bfloat16*)g_ql4,
                                    (((size_t)(b * NHH + h)) * SQ + s2) * DHH + d);
                    } else if (n < 1536) {
                        int n2 = n - 768;
                        v += b1[n2];
                        int h = n2 >> 6, d = n2 & 63;
                        split_store(v, (__nv_bfloat16*)g_kh4, (__nv_bfloat16*)g_kl4,
                                    (((size_t)(b * NHH + h)) * SQ + s2) * DHH + d);
                    } else {
                        int n2 = n - 1536;
                        v += b2[n2];
                        int h = n2 >> 6, d = n2 & 63;
                        split_store(v, (__nv_bfloat16*)g_vth4, (__nv_bfloat16*)g_vtl4,
                                    (((size_t)(b * NHH + h)) * DHH + d) * SQ + s2);
                    }
                } else {  // MODE 5: rel pos, M=512 rows
                    if (n < 768) {
                        v += b0[n];
                        int h = n >> 6, d = n & 63;
                        split_store(v, (__nv_bfloat16*)g_pqh4, (__nv_bfloat16*)g_pql4,
                                    ((size_t)h * SQ + m) * DHH + d);
                    } else {
                        int n2 = n - 768;
                        v += b1[n2];
                        int h = n2 >> 6, d = n2 & 63;
                        split_store(v, (__nv_bfloat16*)g_pkh4, (__nv_bfloat16*)g_pkl4,
                                    ((size_t)h * SQ + m) * DHH + d);
                    }
                }
            }
        }
    }
}

// ---------------- batched TC NT GEMM (scores, K=64, single-buffer) ----------------
__global__ void __launch_bounds__(256)
tc_bgemm_nt_kernel(int apair, int bpair, int ccode, int bmod) {
    const int bh = blockIdx.z;
    const __nv_bfloat16* Ah = phi(apair) + (size_t)bh * SQ * DHH;
    const __nv_bfloat16* Al = plo(apair) + (size_t)bh * SQ * DHH;
    const __nv_bfloat16* Bh = phi(bpair) + (size_t)(bh % bmod) * SQ * DHH;
    const __nv_bfloat16* Bl = plo(bpair) + (size_t)(bh % bmod) * SQ * DHH;
    float* Cb = (ccode == 0 ? g_s0 : (ccode == 1 ? g_c2p : g_p2c)) + (size_t)bh * SQ * SQ;

    __shared__ unsigned S[7680];
    const int bm = blockIdx.y * 64, bn = blockIdx.x * 128;
    const int tid = threadIdx.x;

    const __nv_bfloat16* a_src[2];
    int a_dst[2];
#pragma unroll
    for (int it = 0; it < 2; it++) {
        int flat = tid + it * 256;
        int hl = flat >> 8, rem = flat & 255;
        int r = rem >> 2, qq = rem & 3;
        a_src[it] = (hl ? Al : Ah) + (size_t)(bm + r) * DHH + qq * 8;
        a_dst[it] = (hl ? SW_A_LO : SW_A_HI) + r * 20 + qq * 4;
    }
    const __nv_bfloat16* b_src[4];
    int b_dst[4];
#pragma unroll
    for (int it = 0; it < 4; it++) {
        int flat = tid + it * 256;
        int hl = flat >> 9, rem = flat & 511;
        int r = rem >> 2, qq = rem & 3;
        b_src[it] = (hl ? Bl : Bh) + (size_t)(bn + r) * DHH + qq * 8;
        b_dst[it] = (hl ? SW_B_LO : SW_B_HI) + r * 20 + qq * 4;
    }

    const int lane = tid & 31, g = lane >> 2, tig = lane & 3;
    const int warp = tid >> 5;
    const int wm = (warp & 1) * 32, wn = (warp >> 1) * 32;

    float acc[2][4][4] = {};
    uint4 pa[2], pb[4];
#pragma unroll
    for (int it = 0; it < 2; it++) pa[it] = *(const uint4*)a_src[it];
#pragma unroll
    for (int it = 0; it < 4; it++) pb[it] = *(const uint4*)b_src[it];

#pragma unroll 1
    for (int t = 0; t < 2; t++) {
#pragma unroll
        for (int it = 0; it < 2; it++) *(uint4*)&S[a_dst[it]] = pa[it];
#pragma unroll
        for (int it = 0; it < 4; it++) *(uint4*)&S[b_dst[it]] = pb[it];
        __syncthreads();
        if (t == 0) {
#pragma unroll
            for (int it = 0; it < 2; it++) pa[it] = *(const uint4*)(a_src[it] + 32);
#pragma unroll
            for (int it = 0; it < 4; it++) pb[it] = *(const uint4*)(b_src[it] + 32);
        }
#pragma unroll
        for (int step = 0; step < 2; step++) {
            const int so = step * 8 + tig;
            unsigned ah[2][4], bh[4][2];
#pragma unroll
            for (int mi = 0; mi < 2; mi++) {
                unsigned base = SW_A_HI + (wm + mi * 16 + g) * 20 + so;
                ah[mi][0] = S[base];     ah[mi][1] = S[base + 160];
                ah[mi][2] = S[base + 4]; ah[mi][3] = S[base + 164];
            }
#pragma unroll
            for (int nj = 0; nj < 4; nj++) {
                unsigned base = SW_B_HI + (wn + nj * 8 + g) * 20 + so;
                bh[nj][0] = S[base];  bh[nj][1] = S[base + 4];
            }
#pragma unroll
            for (int mi = 0; mi < 2; mi++)
#pragma unroll
                for (int nj = 0; nj < 4; nj++) mma16816(acc[mi][nj], ah[mi], bh[nj]);
            {
                unsigned bl[4][2];
#pragma unroll
                for (int nj = 0; nj < 4; nj++) {
                    unsigned base = SW_B_LO + (wn + nj * 8 + g) * 20 + so;
                    bl[nj][0] = S[base];  bl[nj][1] = S[base + 4];
                }
#pragma unroll
                for (int mi = 0; mi < 2; mi++)
#pragma unroll
                    for (int nj = 0; nj < 4; nj++) mma16816(acc[mi][nj], ah[mi], bl[nj]);
            }
            {
                unsigned al[2][4];
#pragma unroll
                for (int mi = 0; mi < 2; mi++) {
                    unsigned base = SW_A_LO + (wm + mi * 16 + g) * 20 + so;
                    al[mi][0] = S[base];     al[mi][1] = S[base + 160];
                    al[mi][2] = S[base + 4]; al[mi][3] = S[base + 164];
                }
#pragma unroll
                for (int mi = 0; mi < 2; mi++)
#pragma unroll
                    for (int nj = 0; nj < 4; nj++) mma16816(acc[mi][nj], al[mi], bh[nj]);
            }
        }
        __syncthreads();
    }
#pragma unroll
    for (int mi = 0; mi < 2; mi++)
#pragma unroll
        for (int nj = 0; nj < 4; nj++)
#pragma unroll
            for (int rr = 0; rr < 4; rr++) {
                int m = bm + wm + mi * 16 + g + (rr >> 1) * 8;
                int n = bn + wn + nj * 8 + tig * 2 + (rr & 1);
                Cb[(size_t)m * SQ + n] = acc[mi][nj][rr];
            }
}

// ---------------- TC ctx GEMM (K=512, double-buffered dynamic smem) ----------------
__global__ void __launch_bounds__(256)
tc_bgemm_ctx_kernel() {
    const int bh = blockIdx.y;
    const int b = bh / NHH, h = bh % NHH;
    const __nv_bfloat16* Ah = (const __nv_bfloat16*)g_ph4 + (size_t)bh * SQ * SQ;
    const __nv_bfloat16* Al = (const __nv_bfloat16*)g_pl4 + (size_t)bh * SQ * SQ;
    const __nv_bfloat16* Bh = (const __nv_bfloat16*)g_vth4 + (size_t)bh * DHH * SQ;
    const __nv_bfloat16* Bl = (const __nv_bfloat16*)g_vtl4 + (size_t)bh * DHH * SQ;

    extern __shared__ unsigned S[];
    const int bm = blockIdx.x * 128;
    const int tid = threadIdx.x;

    const __nv_bfloat16* a_src[4];
    int a_dst[4];
#pragma unroll
    for (int it = 0; it < 4; it++) {
        int flat = tid + it * 256;
        int hl = flat >> 9, rem = flat & 511;
        int r = rem >> 2, qq = rem & 3;
        a_src[it] = (hl ? Al : Ah) + (size_t)(bm + r) * SQ + qq * 8;
        a_dst[it] = (hl ? 2560 : 0) + r * 20 + qq * 4;
    }
    const __nv_bfloat16* b_src[2];
    int b_dst[2];
#pragma unroll
    for (int it = 0; it < 2; it++) {
        int flat = tid + it * 256;
        int hl = flat >> 8, rem = flat & 255;
        int r = rem >> 2, qq = rem & 3;
        b_src[it] = (hl ? Bl : Bh) + (size_t)r * SQ + qq * 8;
        b_dst[it] = (hl ? 6400 : 5120) + r * 20 + qq * 4;
    }

    const int lane = tid & 31, g = lane >> 2, tig = lane & 3;
    const int warp = tid >> 5;
    const int wm = (warp & 3) * 32, wn = (warp >> 2) * 32;

    float acc[2][4][4] = {};
    uint4 pa[4], pb[2];
#pragma unroll
    for (int it = 0; it < 4; it++) pa[it] = *(const uint4*)a_src[it];
#pragma unroll
    for (int it = 0; it < 2; it++) pb[it] = *(const uint4*)b_src[it];
#pragma unroll
    for (int it = 0; it < 4; it++) *(uint4*)&S[a_dst[it]] = pa[it];
#pragma unroll
    for (int it = 0; it < 2; it++) *(uint4*)&S[b_dst[it]] = pb[it];
    __syncthreads();

#pragma unroll 1
    for (int t = 0; t < 16; t++) {
        unsigned* Sc = S + (t & 1) * STAGE;
        if (t + 1 < 16) {
            int ko = (t + 1) * 32;
#pragma unroll
            for (int it = 0; it < 4; it++) pa[it] = *(const uint4*)(a_src[it] + ko);
#pragma unroll
            for (int it = 0; it < 2; it++) pb[it] = *(const uint4*)(b_src[it] + ko);
        }
#pragma unroll
        for (int step = 0; step < 2; step++) {
            const int so = step * 8 + tig;
            unsigned ah[2][4], bh[4][2];
#pragma unroll
            for (int mi = 0; mi < 2; mi++) {
                unsigned base = 0 + (wm + mi * 16 + g) * 20 + so;
                ah[mi][0] = Sc[base];     ah[mi][1] = Sc[base + 160];
                ah[mi][2] = Sc[base + 4]; ah[mi][3] = Sc[base + 164];
            }
#pragma unroll
            for (int nj = 0; nj < 4; nj++) {
                unsigned base = 5120 + (wn + nj * 8 + g) * 20 + so;
                bh[nj][0] = Sc[base];  bh[nj][1] = Sc[base + 4];
            }
#pragma unroll
            for (int mi = 0; mi < 2; mi++)
#pragma unroll
                for (int nj = 0; nj < 4; nj++) mma16816(acc[mi][nj], ah[mi], bh[nj]);
            {
                unsigned bl[4][2];
#pragma unroll
                for (int nj = 0; nj < 4; nj++) {
                    unsigned base = 6400 + (wn + nj * 8 + g) * 20 + so;
                    bl[nj][0] = Sc[base];  bl[nj][1] = Sc[base + 4];
                }
#pragma unroll
                for (int mi = 0; mi < 2; mi++)
#pragma unroll
                    for (int nj = 0; nj < 4; nj++) mma16816(acc[mi][nj], ah[mi], bl[nj]);
            }
            {
                unsigned al[2][4];
#pragma unroll
                for (int mi = 0; mi < 2; mi++) {
                    unsigned base = 2560 + (wm + mi * 16 + g) * 20 + so;
                    al[mi][0] = Sc[base];     al[mi][1] = Sc[base + 160];
                    al[mi][2] = Sc[base + 4]; al[mi][3] = Sc[base + 164];
                }
#pragma unroll
                for (int mi = 0; mi < 2; mi++)
#pragma unroll
                    for (int nj = 0; nj < 4; nj++) mma16816(acc[mi][nj], al[mi], bh[nj]);
            }
        }
        if (t + 1 < 16) {
            unsigned* Sn = S + ((t + 1) & 1) * STAGE;
#pragma unroll
            for (int it = 0; it < 4; it++) *(uint4*)&Sn[a_dst[it]] = pa[it];
#pragma unroll
            for (int it = 0; it < 2; it++) *(uint4*)&Sn[b_dst[it]] = pb[it];
            __syncthreads();
        }
    }
#pragma unroll
    for (int mi = 0; mi < 2; mi++)
#pragma unroll
        for (int nj = 0; nj < 4; nj++)
#pragma unroll
            for (int rr = 0; rr < 4; rr++) {
                int m = bm + wm + mi * 16 + g + (rr >> 1) * 8;
                int n = wn + nj * 8 + tig * 2 + (rr & 1);
                g_t2[((size_t)(b * SQ + m)) * HD + h * DHH + n] = acc[mi][nj][rr];
            }
}

// ---------------- SIMT SGEMM (cls head only, N=9) ----------------
__global__ void __launch_bounds__(256)
sgemm_kernel(int acode, const float* __restrict__ Bm,
             const float* __restrict__ bias, float* __restrict__ Cext,
             int M, int N, int K) {
    const float* A = bufptr(acode);
    __shared__ float As[16][68];
    __shared__ float Bs[16][68];
    int bm = blockIdx.y * 64, bn = blockIdx.x * 64;
    int tid = threadIdx.x;
    int tr = tid >> 4, tc = tid & 15;
    float acc[4][4] = {};
#pragma unroll 1
    for (int k0 = 0; k0 < K; k0 += 16) {
#pragma unroll
        for (int i = tid; i < 1024; i += 256) {
            int m = i >> 4, kk = i & 15;
            As[kk][m] = A[(size_t)(bm + m) * K + k0 + kk];
        }
#pragma unroll
        for (int i = tid; i < 1024; i += 256) {
            int kk = i >> 6, n = i & 63;
            Bs[kk][n] = (bn + n < N) ? Bm[(size_t)(k0 + kk) * N + bn + n] : 0.f;
        }
        __syncthreads();
#pragma unroll
        for (int kk = 0; kk < 16; kk++) {
            float4 a4 = *(const float4*)&As[kk][tr * 4];
            float4 b4 = *(const float4*)&Bs[kk][tc * 4];
            float a[4] = {a4.x, a4.y, a4.z, a4.w};
            float b[4] = {b4.x, b4.y, b4.z, b4.w};
#pragma unroll
            for (int i2 = 0; i2 < 4; i2++)
#pragma unroll
                for (int j = 0; j < 4; j++) acc[i2][j] += a[i2] * b[j];
        }
        __syncthreads();
    }
#pragma unroll
    for (int i2 = 0; i2 < 4; i2++) {
        int m = bm + tr * 4 + i2;
#pragma unroll
        for (int j = 0; j < 4; j++) {
            int n = bn + tc * 4 + j;
            if (n >= N) continue;
            Cext[(size_t)m * N + n] = acc[i2][j] + bias[n];
        }
    }
}

// ---------------- attention combine + gather + mask + softmax -> split bf16 probs ----------------
__global__ void attn_softmax_kernel(const int* __restrict__ mask) {
    int q = blockIdx.x, bh = blockIdx.y, b = bh / NHH;
    int tid = threadIdx.x;
    const float* row = g_s0 + ((size_t)bh * SQ + q) * SQ;
    const float* crow = g_c2p + ((size_t)bh * SQ + q) * SQ;
    const float* pbase = g_p2c + (size_t)bh * SQ * SQ;
    int mq = mask[b * SQ + q];
    float vals[2];
    float mx = -3.4028234663852886e38f;
#pragma unroll
    for (int t = 0; t < 2; t++) {
        int k = tid + t * 256;
        float v = -3.4028234663852886e38f;
        if (mq != 0 && mask[b * SQ + k] != 0) {
            v = (row[k] + crow[g_ic2p[q * SQ + k]] + pbase[(size_t)k * SQ + g_ip2c[k * SQ + q]]) * SCALEF;
        }
        vals[t] = v;
        mx = fmaxf(mx, v);
    }
    mx = blk_reduce_max(mx);
    float sum = 0.f;
#pragma unroll
    for (int t = 0; t < 2; t++) { vals[t] = expf(vals[t] - mx); sum += vals[t]; }
    sum = blk_reduce_sum(sum);
    float inv = 1.0f / sum;
    __nv_bfloat16* ph = (__nv_bfloat16*)g_ph4;
    __nv_bfloat16* pl = (__nv_bfloat16*)g_pl4;
#pragma unroll
    for (int t = 0; t < 2; t++) {
        float p = vals[t] * inv;
        size_t o = ((size_t)bh * SQ + q) * SQ + tid + t * 256;
        __nv_bfloat16 hh = __float2bfloat16(p);
        ph[o] = hh;
        pl[o] = __float2bfloat16(p - __bfloat162float(hh));
    }
}

// ---------------- launch ----------------
extern "C" void kernel_launch(void* const* d_in, const int* in_sizes, int n_in,
                              void* d_out, int out_size) {
    const int*   ids     = (const int*)d_in[0];
    const int*   mask    = (const int*)d_in[1];
    const float* we      = (const float*)d_in[2];
    const float* te      = (const float*)d_in[3];
    const float* elns    = (const float*)d_in[4];
    const float* elnb    = (const float*)d_in[5];
    const float* rel_emb = (const float*)d_in[6];
    const float* rlns    = (const float*)d_in[7];
    const float* rlnb    = (const float*)d_in[8];
    const float* qw      = (const float*)d_in[9];
    const float* qb      = (const float*)d_in[10];
    const float* kw      = (const float*)d_in[11];
    const float* kb      = (const float*)d_in[12];
    const float* vw      = (const float*)d_in[13];
    const float* vb      = (const float*)d_in[14];
    const float* aow     = (const float*)d_in[15];
    const float* aob     = (const float*)d_in[16];
    const float* alns    = (const float*)d_in[17];
    const float* alnb    = (const float*)d_in[18];
    const float* iw      = (const float*)d_in[19];
    const float* ib      = (const float*)d_in[20];
    const float* ow      = (const float*)d_in[21];
    const float* ob      = (const float*)d_in[22];
    const float* olns    = (const float*)d_in[23];
    const float* olnb    = (const float*)d_in[24];
    const float* clsw    = (const float*)d_in[25];
    const float* clsb    = (const float*)d_in[26];
    float* out = (float*)d_out;

    const int DSM = 2 * STAGE * 4;  // 61440 bytes
    cudaFuncSetAttribute(tc_gemm_kernel<0>, cudaFuncAttributeMaxDynamicSharedMemorySize, DSM);
    cudaFuncSetAttribute(tc_gemm_kernel<1>, cudaFuncAttributeMaxDynamicSharedMemorySize, DSM);
    cudaFuncSetAttribute(tc_gemm_kernel<4>, cudaFuncAttributeMaxDynamicSharedMemorySize, DSM);
    cudaFuncSetAttribute(tc_gemm_kernel<5>, cudaFuncAttributeMaxDynamicSharedMemorySize, DSM);
    cudaFuncSetAttribute(tc_bgemm_ctx_kernel, cudaFuncAttributeMaxDynamicSharedMemorySize, DSM);

    relidx_kernel<<<1024, 256>>>();
    rel_ln_kernel<<<SQ, 256>>>(rel_emb, rlns, rlnb);
    embed_ln_kernel<<<NTOK, 256>>>(ids, mask, we, te, elns, elnb);

    conva_kernel<<<(SQ * HD / 4 + 255) / 256, 256>>>(BUF_REL, 1, SQ * HD / 4);

    dim3 tb(32, 8);
    dim3 gTransHH(HD / 32, HD / 32);
    dim3 gTransIF(FFD / 32, HD / 32);
    dim3 gTransOF(HD / 32, FFD / 32);

    dim3 gTcQKV(2304 / 128, NTOK / 64);    // (18, 32) = 576
    dim3 gTcPos(1536 / 128, SQ / 64);      // (12, 8)  = 96
    dim3 gTcProj(HD / 128, NTOK / 64);     // (6, 32)  = 192
    dim3 gTcFF1(FFD / 128, NTOK / 64);     // (24, 32) = 768
    dim3 gTcFF2(HD / 128, NTOK / 64);      // (6, 32)  = 192

    dim3 gScore(SQ / 128, SQ / 64, BHH);
    dim3 gSm(SQ, BHH);
    dim3 gCtx(SQ / 128, BHH);
    dim3 gCls(1, 32);

    const int nX4 = NTOK * HD / 4;

    for (int l = 0; l < NLAYER; l++) {
        const float* qwl = qw + (size_t)l * HD * HD;
        const float* kwl = kw + (size_t)l * HD * HD;
        const float* vwl = vw + (size_t)l * HD * HD;
        const float* aowl = aow + (size_t)l * HD * HD;
        const float* iwl = iw + (size_t)l * HD * FFD;
        const float* owl = ow + (size_t)l * FFD * HD;
        const float* qbl = qb + (size_t)l * HD;
        const float* kbl = kb + (size_t)l * HD;
        const float* vbl = vb + (size_t)l * HD;
        const float* aobl = aob + (size_t)l * HD;
        const float* ibl = ib + (size_t)l * FFD;
        const float* obl = ob + (size_t)l * HD;

        conva_kernel<<<(nX4 + 255) / 256, 256>>>(BUF_X, 0, nX4);

        transb_kernel<<<gTransHH, tb>>>(qwl, HD, HD, 0);
        transb_kernel<<<gTransHH, tb>>>(kwl, HD, HD, 768);
        transb_kernel<<<gTransHH, tb>>>(vwl, HD, HD, 1536);
        tc_gemm_kernel<4><<<gTcQKV, 256, DSM>>>(0, qbl, kbl, vbl, 0, 0, NTOK, 2304, HD);
        tc_gemm_kernel<5><<<gTcPos, 256, DSM>>>(1, qbl, kbl, 0, 0, 0, SQ, 1536, HD);

        tc_bgemm_nt_kernel<<<gScore, 256>>>(0, 1, 0, BHH);   // q @ k^T
        tc_bgemm_nt_kernel<<<gScore, 256>>>(0, 2, 1, NHH);   // q @ pk^T
        tc_bgemm_nt_kernel<<<gScore, 256>>>(1, 3, 2, NHH);   // k @ pq^T

        attn_softmax_kernel<<<gSm, 256>>>(mask);

        tc_bgemm_ctx_kernel<<<gCtx, 256, DSM>>>();

        conva_kernel<<<(nX4 + 255) / 256, 256>>>(BUF_T2, 0, nX4);
        transb_kernel<<<gTransHH, tb>>>(aowl, HD, HD, 0);
        tc_gemm_kernel<0><<<gTcProj, 256, DSM>>>(0, aobl, 0, 0, BUF_T1, 0, NTOK, HD, HD);
        add_ln_kernel<<<NTOK, 256>>>(BUF_T1, alns + (size_t)l * HD, alnb + (size_t)l * HD);

        conva_kernel<<<(nX4 + 255) / 256, 256>>>(BUF_X, 0, nX4);
        transb_kernel<<<gTransIF, tb>>>(iwl, HD, FFD, 0);
        tc_gemm_kernel<1><<<gTcFF1, 256, DSM>>>(0, ibl, 0, 0, 0, 0, NTOK, FFD, HD);

        transb_kernel<<<gTransOF, tb>>>(owl, FFD, HD, 0);
        tc_gemm_kernel<0><<<gTcFF2, 256, DSM>>>(2, obl, 0, 0, BUF_T2, 0, NTOK, HD, FFD);
        add_ln_kernel<<<NTOK, 256>>>(BUF_T2, olns + (size_t)l * HD, olnb + (size_t)l * HD);
    }

    sgemm_kernel<<<gCls, 256>>>(BUF_X, clsw, clsb, out, NTOK, NCLS, HD);
}

// round 17
// speedup vs baseline: 1.9546x; 1.1400x over previous
#include <cuda_runtime.h>
#include <cuda_bf16.h>
#include <math.h>

#define SQ   512
#define HD   768
#define NHH  12
#define DHH  64
#define BHH  48          // B * NH
#define FFD  3072
#define NCLS 9
#define NLAYER 12
#define NTOK 2048        // B * S
#define SCALEF 0.07216878364870323f   // 1/sqrt(64*3)

// ---------------- scratch (allocation-free: __device__ globals) ----------------
__device__ float g_x[NTOK * HD];
__device__ float g_rel[SQ * HD];
__device__ float g_s0[BHH * SQ * SQ];
__device__ float g_c2p[BHH * SQ * SQ];
__device__ float g_p2c[BHH * SQ * SQ];
__device__ float g_t1[NTOK * HD];
__device__ float g_t2[NTOK * HD];
__device__ int   g_ic2p[SQ * SQ];
__device__ int   g_ip2c[SQ * SQ];

// split-bf16 operand buffers
__device__ uint4 g_ah4[NTOK * HD / 8];
__device__ uint4 g_al4[NTOK * HD / 8];
__device__ uint4 g_a2h4[NTOK * FFD / 8];
__device__ uint4 g_a2l4[NTOK * FFD / 8];
__device__ uint4 g_relh4[SQ * HD / 8];
__device__ uint4 g_rell4[SQ * HD / 8];
__device__ uint4 g_bth4[FFD * HD / 8];
__device__ uint4 g_btl4[FFD * HD / 8];
__device__ uint4 g_qh4[BHH * SQ * DHH / 8];
__device__ uint4 g_ql4[BHH * SQ * DHH / 8];
__device__ uint4 g_kh4[BHH * SQ * DHH / 8];
__device__ uint4 g_kl4[BHH * SQ * DHH / 8];
__device__ uint4 g_pkh4[NHH * SQ * DHH / 8];
__device__ uint4 g_pkl4[NHH * SQ * DHH / 8];
__device__ uint4 g_pqh4[NHH * SQ * DHH / 8];
__device__ uint4 g_pql4[NHH * SQ * DHH / 8];
__device__ uint4 g_vth4[BHH * DHH * SQ / 8];
__device__ uint4 g_vtl4[BHH * DHH * SQ / 8];
__device__ uint4 g_ph4[BHH * SQ * SQ / 8];
__device__ uint4 g_pl4[BHH * SQ * SQ / 8];

#define BUF_X   0
#define BUF_REL 6
#define BUF_T1  10
#define BUF_T2  11

__device__ __forceinline__ float* bufptr(int c) {
    switch (c) {
        case BUF_X:   return g_x;
        case BUF_REL: return g_rel;
        case BUF_T1:  return g_t1;
        case BUF_T2:  return g_t2;
    }
    return 0;
}

// bf16 pair selectors: 0 q, 1 k, 2 pk, 3 pq
__device__ __forceinline__ __nv_bfloat16* phi(int p) {
    switch (p) {
        case 0: return (__nv_bfloat16*)g_qh4;
        case 1: return (__nv_bfloat16*)g_kh4;
        case 2: return (__nv_bfloat16*)g_pkh4;
        case 3: return (__nv_bfloat16*)g_pqh4;
    }
    return 0;
}
__device__ __forceinline__ __nv_bfloat16* plo(int p) {
    switch (p) {
        case 0: return (__nv_bfloat16*)g_ql4;
        case 1: return (__nv_bfloat16*)g_kl4;
        case 2: return (__nv_bfloat16*)g_pkl4;
        case 3: return (__nv_bfloat16*)g_pql4;
    }
    return 0;
}
// A-operand: 0 act, 1 rel, 2 ffn1-out
__device__ __forceinline__ const __nv_bfloat16* ahi(int a) {
    return (const __nv_bfloat16*)(a == 0 ? g_ah4 : (a == 1 ? g_relh4 : g_a2h4));
}
__device__ __forceinline__ const __nv_bfloat16* alo(int a) {
    return (const __nv_bfloat16*)(a == 0 ? g_al4 : (a == 1 ? g_rell4 : g_a2l4));
}

// ---------------- block reductions (256 threads) ----------------
__device__ __forceinline__ float blk_reduce_sum(float v) {
    __shared__ float red[256];
    int tid = threadIdx.x;
    red[tid] = v; __syncthreads();
    for (int s = 128; s > 0; s >>= 1) {
        if (tid < s) red[tid] += red[tid + s];
        __syncthreads();
    }
    float r = red[0]; __syncthreads();
    return r;
}

__device__ __forceinline__ float blk_reduce_max(float v) {
    __shared__ float redm[256];
    int tid = threadIdx.x;
    redm[tid] = v; __syncthreads();
    for (int s = 128; s > 0; s >>= 1) {
        if (tid < s) redm[tid] = fmaxf(redm[tid], redm[tid + s]);
        __syncthreads();
    }
    float r = redm[0]; __syncthreads();
    return r;
}

__device__ __forceinline__ void split_store(float x, __nv_bfloat16* dh, __nv_bfloat16* dl, size_t i) {
    __nv_bfloat16 hh = __float2bfloat16(x);
    dh[i] = hh;
    dl[i] = __float2bfloat16(x - __bfloat162float(hh));
}

// ---------------- relative position bucket indices ----------------
__global__ void relidx_kernel() {
    int idx = blockIdx.x * blockDim.x + threadIdx.x;
    if (idx >= SQ * SQ) return;
    int i = idx >> 9, j = idx & 511;
    int rel = i - j;
    int bucket;
    if (rel >= -128 && rel <= 128) {
        bucket = rel;
    } else {
        float abs_pos = fabsf((float)rel);
        float log_pos = ceilf(logf(abs_pos / 128.0f) / logf(511.0f / 128.0f) * 127.0f) + 128.0f;
        bucket = (int)(rel > 0 ? log_pos : -log_pos);
    }
    int c = bucket + 256; c = c < 0 ? 0 : (c > 511 ? 511 : c);
    int p = -bucket + 256; p = p < 0 ? 0 : (p > 511 ? 511 : p);
    g_ic2p[idx] = c;
    g_ip2c[idx] = p;
}

// ---------------- embedding gather + LN * mask (+ split-bf16 emit) ----------------
__global__ void embed_ln_kernel(const int* __restrict__ ids, const int* __restrict__ mask,
                                const float* __restrict__ we, const float* __restrict__ te,
                                const float* __restrict__ lns, const float* __restrict__ lnb) {
    int r = blockIdx.x, tid = threadIdx.x;
    size_t id = (size_t)ids[r];
    float v[3];
#pragma unroll
    for (int t = 0; t < 3; t++) {
        int c = tid + t * 256;
        v[t] = we[id * HD + c] + te[c];
    }
    float mu = blk_reduce_sum(v[0] + v[1] + v[2]) * (1.0f / HD);
    float sq = 0.f;
#pragma unroll
    for (int t = 0; t < 3; t++) { float d = v[t] - mu; sq += d * d; }
    float var = blk_reduce_sum(sq) * (1.0f / HD);
    float inv = rsqrtf(var + 1e-7f);
    float mf = (float)mask[r];
    __nv_bfloat16* dh = (__nv_bfloat16*)g_ah4;
    __nv_bfloat16* dl = (__nv_bfloat16*)g_al4;
#pragma unroll
    for (int t = 0; t < 3; t++) {
        int c = tid + t * 256;
        float o = ((v[t] - mu) * inv * lns[c] + lnb[c]) * mf;
        g_x[(size_t)r * HD + c] = o;
        split_store(o, dh, dl, (size_t)r * HD + c);
    }
}

// ---------------- LN of relative embeddings ----------------
__global__ void rel_ln_kernel(const float* __restrict__ re,
                              const float* __restrict__ lns, const float* __restrict__ lnb) {
    int r = blockIdx.x, tid = threadIdx.x;
    float v[3];
#pragma unroll
    for (int t = 0; t < 3; t++) v[t] = re[(size_t)r * HD + tid + t * 256];
    float mu = blk_reduce_sum(v[0] + v[1] + v[2]) * (1.0f / HD);
    float sq = 0.f;
#pragma unroll
    for (int t = 0; t < 3; t++) { float d = v[t] - mu; sq += d * d; }
    float var = blk_reduce_sum(sq) * (1.0f / HD);
    float inv = rsqrtf(var + 1e-7f);
    __nv_bfloat16* dh = (__nv_bfloat16*)g_relh4;
    __nv_bfloat16* dl = (__nv_bfloat16*)g_rell4;
#pragma unroll
    for (int t = 0; t < 3; t++) {
        int c = tid + t * 256;
        float o = (v[t] - mu) * inv * lns[c] + lnb[c];
        g_rel[(size_t)r * HD + c] = o;
        split_store(o, dh, dl, (size_t)r * HD + c);
    }
}

// ---------------- residual + LN (+ split-bf16 emit) ----------------
__global__ void add_ln_kernel(int tcode,
                              const float* __restrict__ lns, const float* __restrict__ lnb) {
    const float* t = bufptr(tcode);
    int r = blockIdx.x, tid = threadIdx.x;
    float v[3];
#pragma unroll
    for (int c2 = 0; c2 < 3; c2++) {
        int c = tid + c2 * 256;
        v[c2] = g_x[(size_t)r * HD + c] + t[(size_t)r * HD + c];
    }
    float mu = blk_reduce_sum(v[0] + v[1] + v[2]) * (1.0f / HD);
    float sq = 0.f;
#pragma unroll
    for (int c2 = 0; c2 < 3; c2++) { float d = v[c2] - mu; sq += d * d; }
    float var = blk_reduce_sum(sq) * (1.0f / HD);
    float inv = rsqrtf(var + 1e-7f);
    __nv_bfloat16* dh = (__nv_bfloat16*)g_ah4;
    __nv_bfloat16* dl = (__nv_bfloat16*)g_al4;
#pragma unroll
    for (int c2 = 0; c2 < 3; c2++) {
        int c = tid + c2 * 256;
        float o = (v[c2] - mu) * inv * lns[c] + lnb[c];
        g_x[(size_t)r * HD + c] = o;
        split_store(o, dh, dl, (size_t)r * HD + c);
    }
}

// ---------------- transpose + convert weights ----------------
__global__ void transb_kernel(const float* __restrict__ W, int K, int N, int nofs) {
    __shared__ float tile[32][33];
    int k0 = blockIdx.y * 32, n0 = blockIdx.x * 32;
    int tx = threadIdx.x, ty = threadIdx.y;   // (32, 8)
#pragma unroll
    for (int i = 0; i < 4; i++)
        tile[ty + i * 8][tx] = W[(size_t)(k0 + ty + i * 8) * N + n0 + tx];
    __syncthreads();
    __nv_bfloat16* oh = (__nv_bfloat16*)g_bth4;
    __nv_bfloat16* ol = (__nv_bfloat16*)g_btl4;
#pragma unroll
    for (int i = 0; i < 4; i++) {
        int n = n0 + ty + i * 8;
        float v = tile[tx][ty + i * 8];
        __nv_bfloat16 hh = __float2bfloat16(v);
        oh[(size_t)(nofs + n) * K + k0 + tx] = hh;
        ol[(size_t)(nofs + n) * K + k0 + tx] = __float2bfloat16(v - __bfloat162float(hh));
    }
}

// merged q/k/v transpose (z selects weight, nofs = z*768)
__global__ void transb3_kernel(const float* __restrict__ qw, const float* __restrict__ kw,
                               const float* __restrict__ vw) {
    __shared__ float tile[32][33];
    int z = blockIdx.z;
    const float* W = (z == 0) ? qw : (z == 1 ? kw : vw);
    int k0 = blockIdx.y * 32, n0 = blockIdx.x * 32;
    int tx = threadIdx.x, ty = threadIdx.y;
#pragma unroll
    for (int i = 0; i < 4; i++)
        tile[ty + i * 8][tx] = W[(size_t)(k0 + ty + i * 8) * HD + n0 + tx];
    __syncthreads();
    __nv_bfloat16* oh = (__nv_bfloat16*)g_bth4;
    __nv_bfloat16* ol = (__nv_bfloat16*)g_btl4;
    int nofs = z * HD;
#pragma unroll
    for (int i = 0; i < 4; i++) {
        int n = n0 + ty + i * 8;
        float v = tile[tx][ty + i * 8];
        __nv_bfloat16 hh = __float2bfloat16(v);
        oh[(size_t)(nofs + n) * HD + k0 + tx] = hh;
        ol[(size_t)(nofs + n) * HD + k0 + tx] = __float2bfloat16(v - __bfloat162float(hh));
    }
}

// ---------------- mma / ldmatrix wrappers ----------------
__device__ __forceinline__ void mma16816(float* c, const unsigned* a, const unsigned* b) {
    asm volatile(
        "mma.sync.aligned.m16n8k16.row.col.f32.bf16.bf16.f32 "
        "{%0,%1,%2,%3}, {%4,%5,%6,%7}, {%8,%9}, {%0,%1,%2,%3};"
        : "+f"(c[0]), "+f"(c[1]), "+f"(c[2]), "+f"(c[3])
        : "r"(a[0]), "r"(a[1]), "r"(a[2]), "r"(a[3]), "r"(b[0]), "r"(b[1]));
}

__device__ __forceinline__ void ldsm4(unsigned* r, unsigned addr) {
    asm volatile("ldmatrix.sync.aligned.m8n8.x4.shared.b16 {%0,%1,%2,%3}, [%4];"
        : "=r"(r[0]), "=r"(r[1]), "=r"(r[2]), "=r"(r[3]) : "r"(addr));
}

// One K-32 tile of split-bf16 mma for a 32(M)x32(N) warp tile against
// 64/128-row smem regions. aBase/bBase are per-lane ldmatrix byte addresses
// (hi regions); aLoOfs/bLoOfs are byte offsets to the lo regions.
__device__ __forceinline__ void tile_mma(float acc[2][4][4], unsigned aBase, unsigned bBase,
                                         unsigned aLoOfs, unsigned bLoOfs) {
#pragma unroll
    for (int step = 0; step < 2; step++) {
        const unsigned sb = step * 32;   // step*8 words
        unsigned ah[2][4], alr[2][4], bh2[2][4], bl2[2][4];
        ldsm4(ah[0], aBase + sb);
        ldsm4(ah[1], aBase + 1280 + sb);            // +16 rows * 20w * 4B
        ldsm4(alr[0], aBase + aLoOfs + sb);
        ldsm4(alr[1], aBase + aLoOfs + 1280 + sb);
        ldsm4(bh2[0], bBase + sb);
        ldsm4(bh2[1], bBase + 1280 + sb);
        ldsm4(bl2[0], bBase + bLoOfs + sb);
        ldsm4(bl2[1], bBase + bLoOfs + 1280 + sb);
#pragma unroll
        for (int mi = 0; mi < 2; mi++)
#pragma unroll
            for (int nj = 0; nj < 4; nj++)
                mma16816(acc[mi][nj], ah[mi], &bh2[nj >> 1][(nj & 1) * 2]);
#pragma unroll
        for (int mi = 0; mi < 2; mi++)
#pragma unroll
            for (int nj = 0; nj < 4; nj++)
                mma16816(acc[mi][nj], ah[mi], &bl2[nj >> 1][(nj & 1) * 2]);
#pragma unroll
        for (int mi = 0; mi < 2; mi++)
#pragma unroll
            for (int nj = 0; nj < 4; nj++)
                mma16816(acc[mi][nj], alr[mi], &bh2[nj >> 1][(nj & 1) * 2]);
    }
}

// ---------------- tensor-core GEMM (double-buffered, dynamic 60KB smem) ----------------
// MODE 0: fp32 + bias b0 -> buf[ccode]; MODE 1: GELU -> split bf16 a2;
// MODE 4: merged qkv; MODE 5: merged pos.
#define SW_A_LO 1280
#define SW_B_HI 2560
#define SW_B_LO 5120
#define STAGE   7680

template<int MODE>
__global__ void __launch_bounds__(256)
tc_gemm_kernel(int acode, const float* __restrict__ b0, const float* __restrict__ b1,
               const float* __restrict__ b2, int ccode, int M, int N, int K) {
    const __nv_bfloat16* Ah = ahi(acode);
    const __nv_bfloat16* Al = alo(acode);
    const __nv_bfloat16* Bh = (const __nv_bfloat16*)g_bth4;
    const __nv_bfloat16* Bl = (const __nv_bfloat16*)g_btl4;

    extern __shared__ unsigned S[];

    const int bm = blockIdx.y * 64, bn = blockIdx.x * 128;
    const int tid = threadIdx.x;

    const __nv_bfloat16* a_src[2];
    int a_dst[2];
#pragma unroll
    for (int it = 0; it < 2; it++) {
        int flat = tid + it * 256;
        int hl = flat >> 8, rem = flat & 255;
        int r = rem >> 2, qq = rem & 3;
        a_src[it] = (hl ? Al : Ah) + (size_t)(bm + r) * K + qq * 8;
        a_dst[it] = (hl ? SW_A_LO : 0) + r * 20 + qq * 4;
    }
    const __nv_bfloat16* b_src[4];
    int b_dst[4];
#pragma unroll
    for (int it = 0; it < 4; it++) {
        int flat = tid + it * 256;
        int hl = flat >> 9, rem = flat & 511;
        int r = rem >> 2, qq = rem & 3;
        b_src[it] = (hl ? Bl : Bh) + (size_t)(bn + r) * K + qq * 8;
        b_dst[it] = (hl ? SW_B_LO : SW_B_HI) + r * 20 + qq * 4;
    }

    const int lane = tid & 31, g = lane >> 2, tig = lane & 3;
    const int warp = tid >> 5;
    const int wm = (warp & 1) * 32, wn = (warp >> 1) * 32;

    const unsigned Sb = (unsigned)__cvta_generic_to_shared(&S[0]);
    const int lrA = lane & 15, lcA = (lane >> 4) * 4;
    const unsigned aBase0 = Sb + (((wm + lrA) * 20 + lcA) << 2);
    const int lrB = (lane & 7) | ((lane >> 4) << 3);
    const int lcB = ((lane >> 3) & 1) * 4;
    const unsigned bBase0 = Sb + ((SW_B_HI + (wn + lrB) * 20 + lcB) << 2);

    float acc[2][4][4] = {};
    const int nt = K >> 5;

    uint4 pa[2], pb[4];
#pragma unroll
    for (int it = 0; it < 2; it++) pa[it] = *(const uint4*)a_src[it];
#pragma unroll
    for (int it = 0; it < 4; it++) pb[it] = *(const uint4*)b_src[it];
#pragma unroll
    for (int it = 0; it < 2; it++) *(uint4*)&S[a_dst[it]] = pa[it];
#pragma unroll
    for (int it = 0; it < 4; it++) *(uint4*)&S[b_dst[it]] = pb[it];
    __syncthreads();

#pragma unroll 1
    for (int t = 0; t < nt; t++) {
        const unsigned stb = (t & 1) * (STAGE * 4);
        if (t + 1 < nt) {
            int ko = (t + 1) * 32;
#pragma unroll
            for (int it = 0; it < 2; it++) pa[it] = *(const uint4*)(a_src[it] + ko);
#pragma unroll
            for (int it = 0; it < 4; it++) pb[it] = *(const uint4*)(b_src[it] + ko);
        }
        tile_mma(acc, aBase0 + stb, bBase0 + stb, SW_A_LO * 4, (SW_B_LO - SW_B_HI) * 4);
        if (t + 1 < nt) {
            unsigned* Sn = S + ((t + 1) & 1) * STAGE;
#pragma unroll
            for (int it = 0; it < 2; it++) *(uint4*)&Sn[a_dst[it]] = pa[it];
#pragma unroll
            for (int it = 0; it < 4; it++) *(uint4*)&Sn[b_dst[it]] = pb[it];
            __syncthreads();
        }
    }

    // ---- epilogue ----
#pragma unroll
    for (int mi = 0; mi < 2; mi++) {
#pragma unroll
        for (int nj = 0; nj < 4; nj++) {
#pragma unroll
            for (int rr = 0; rr < 4; rr++) {
                int m = bm + wm + mi * 16 + g + (rr >> 1) * 8;
                int n = bn + wn + nj * 8 + tig * 2 + (rr & 1);
                float v = acc[mi][nj][rr];
                if (MODE == 0) {
                    bufptr(ccode)[(size_t)m * N + n] = v + b0[n];
                } else if (MODE == 1) {
                    v += b0[n];
                    v = 0.5f * v * (1.0f + erff(v * 0.70710678118654752f));
                    split_store(v, (__nv_bfloat16*)g_a2h4, (__nv_bfloat16*)g_a2l4, (size_t)m * N + n);
                } else if (MODE == 4) {
                    int b = m >> 9, s2 = m & 511;
                    if (n < 768) {
                        v += b0[n];
                        int h = n >> 6, d = n & 63;
                        split_store(v, (__nv_bfloat16*)g_qh4, (__nv_bfloat16*)g_ql4,
                                    (((size_t)(b * NHH + h)) * SQ + s2) * DHH + d);
                    } else if (n < 1536) {
                        int n2 = n - 768;
                        v += b1[n2];
                        int h = n2 >> 6, d = n2 & 63;
                        split_store(v, (__nv_bfloat16*)g_kh4, (__nv_bfloat16*)g_kl4,
                                    (((size_t)(b * NHH + h)) * SQ + s2) * DHH + d);
                    } else {
                        int n2 = n - 1536;
                        v += b2[n2];
                        int h = n2 >> 6, d = n2 & 63;
                        split_store(v, (__nv_bfloat16*)g_vth4, (__nv_bfloat16*)g_vtl4,
                                    (((size_t)(b * NHH + h)) * DHH + d) * SQ + s2);
                    }
                } else {  // MODE 5: rel pos, M=512
                    if (n < 768) {
                        v += b0[n];
                        int h = n >> 6, d = n & 63;
                        split_store(v, (__nv_bfloat16*)g_pqh4, (__nv_bfloat16*)g_pql4,
                                    ((size_t)h * SQ + m) * DHH + d);
                    } else {
                        int n2 = n - 768;
                        v += b1[n2];
                        int h = n2 >> 6, d = n2 & 63;
                        split_store(v, (__nv_bfloat16*)g_pkh4, (__nv_bfloat16*)g_pkl4,
                                    ((size_t)h * SQ + m) * DHH + d);
                    }
                }
            }
        }
    }
}

// ---------------- batched TC NT GEMM (scores, K=64) ----------------
__global__ void __launch_bounds__(256)
tc_bgemm_nt_kernel(int apair, int bpair, int ccode, int bmod) {
    const int bh = blockIdx.z;
    const __nv_bfloat16* Ah = phi(apair) + (size_t)bh * SQ * DHH;
    const __nv_bfloat16* Al = plo(apair) + (size_t)bh * SQ * DHH;
    const __nv_bfloat16* Bh = phi(bpair) + (size_t)(bh % bmod) * SQ * DHH;
    const __nv_bfloat16* Bl = plo(bpair) + (size_t)(bh % bmod) * SQ * DHH;
    float* Cb = (ccode == 0 ? g_s0 : (ccode == 1 ? g_c2p : g_p2c)) + (size_t)bh * SQ * SQ;

    __shared__ unsigned S[7680];
    const int bm = blockIdx.y * 64, bn = blockIdx.x * 128;
    const int tid = threadIdx.x;

    const __nv_bfloat16* a_src[2];
    int a_dst[2];
#pragma unroll
    for (int it = 0; it < 2; it++) {
        int flat = tid + it * 256;
        int hl = flat >> 8, rem = flat & 255;
        int r = rem >> 2, qq = rem & 3;
        a_src[it] = (hl ? Al : Ah) + (size_t)(bm + r) * DHH + qq * 8;
        a_dst[it] = (hl ? SW_A_LO : 0) + r * 20 + qq * 4;
    }
    const __nv_bfloat16* b_src[4];
    int b_dst[4];
#pragma unroll
    for (int it = 0; it < 4; it++) {
        int flat = tid + it * 256;
        int hl = flat >> 9, rem = flat & 511;
        int r = rem >> 2, qq = rem & 3;
        b_src[it] = (hl ? Bl : Bh) + (size_t)(bn + r) * DHH + qq * 8;
        b_dst[it] = (hl ? SW_B_LO : SW_B_HI) + r * 20 + qq * 4;
    }

    const int lane = tid & 31, g = lane >> 2, tig = lane & 3;
    const int warp = tid >> 5;
    const int wm = (warp & 1) * 32, wn = (warp >> 1) * 32;

    const unsigned Sb = (unsigned)__cvta_generic_to_shared(&S[0]);
    const int lrA = lane & 15, lcA = (lane >> 4) * 4;
    const unsigned aBase0 = Sb + (((wm + lrA) * 20 + lcA) << 2);
    const int lrB = (lane & 7) | ((lane >> 4) << 3);
    const int lcB = ((lane >> 3) & 1) * 4;
    const unsigned bBase0 = Sb + ((SW_B_HI + (wn + lrB) * 20 + lcB) << 2);

    float acc[2][4][4] = {};
    uint4 pa[2], pb[4];
#pragma unroll
    for (int it = 0; it < 2; it++) pa[it] = *(const uint4*)a_src[it];
#pragma unroll
    for (int it = 0; it < 4; it++) pb[it] = *(const uint4*)b_src[it];

#pragma unroll 1
    for (int t = 0; t < 2; t++) {
#pragma unroll
        for (int it = 0; it < 2; it++) *(uint4*)&S[a_dst[it]] = pa[it];
#pragma unroll
        for (int it = 0; it < 4; it++) *(uint4*)&S[b_dst[it]] = pb[it];
        __syncthreads();
        if (t == 0) {
#pragma unroll
            for (int it = 0; it < 2; it++) pa[it] = *(const uint4*)(a_src[it] + 32);
#pragma unroll
            for (int it = 0; it < 4; it++) pb[it] = *(const uint4*)(b_src[it] + 32);
        }
        tile_mma(acc, aBase0, bBase0, SW_A_LO * 4, (SW_B_LO - SW_B_HI) * 4);
        __syncthreads();
    }
#pragma unroll
    for (int mi = 0; mi < 2; mi++)
#pragma unroll
        for (int nj = 0; nj < 4; nj++)
#pragma unroll
            for (int rr = 0; rr < 4; rr++) {
                int m = bm + wm + mi * 16 + g + (rr >> 1) * 8;
                int n = bn + wn + nj * 8 + tig * 2 + (rr & 1);
                Cb[(size_t)m * SQ + n] = acc[mi][nj][rr];
            }
}

// ---------------- TC ctx GEMM (K=512, double-buffered) -> split bf16 into g_ah4 ----------------
__global__ void __launch_bounds__(256)
tc_bgemm_ctx_kernel() {
    const int bh = blockIdx.y;
    const int b = bh / NHH, h = bh % NHH;
    const __nv_bfloat16* Ah = (const __nv_bfloat16*)g_ph4 + (size_t)bh * SQ * SQ;
    const __nv_bfloat16* Al = (const __nv_bfloat16*)g_pl4 + (size_t)bh * SQ * SQ;
    const __nv_bfloat16* Bh = (const __nv_bfloat16*)g_vth4 + (size_t)bh * DHH * SQ;
    const __nv_bfloat16* Bl = (const __nv_bfloat16*)g_vtl4 + (size_t)bh * DHH * SQ;

    extern __shared__ unsigned S[];
    const int bm = blockIdx.x * 128;
    const int tid = threadIdx.x;

    const __nv_bfloat16* a_src[4];
    int a_dst[4];
#pragma unroll
    for (int it = 0; it < 4; it++) {
        int flat = tid + it * 256;
        int hl = flat >> 9, rem = flat & 511;
        int r = rem >> 2, qq = rem & 3;
        a_src[it] = (hl ? Al : Ah) + (size_t)(bm + r) * SQ + qq * 8;
        a_dst[it] = (hl ? 2560 : 0) + r * 20 + qq * 4;
    }
    const __nv_bfloat16* b_src[2];
    int b_dst[2];
#pragma unroll
    for (int it = 0; it < 2; it++) {
        int flat = tid + it * 256;
        int hl = flat >> 8, rem = flat & 255;
        int r = rem >> 2, qq = rem & 3;
        b_src[it] = (hl ? Bl : Bh) + (size_t)r * SQ + qq * 8;
        b_dst[it] = (hl ? 6400 : 5120) + r * 20 + qq * 4;
    }

    const int lane = tid & 31, g = lane >> 2, tig = lane & 3;
    const int warp = tid >> 5;
    const int wm = (warp & 3) * 32, wn = (warp >> 2) * 32;

    const unsigned Sb = (unsigned)__cvta_generic_to_shared(&S[0]);
    const int lrA = lane & 15, lcA = (lane >> 4) * 4;
    const unsigned aBase0 = Sb + (((wm + lrA) * 20 + lcA) << 2);
    const int lrB = (lane & 7) | ((lane >> 4) << 3);
    const int lcB = ((lane >> 3) & 1) * 4;
    const unsigned bBase0 = Sb + ((5120 + (wn + lrB) * 20 + lcB) << 2);

    float acc[2][4][4] = {};
    uint4 pa[4], pb[2];
#pragma unroll
    for (int it = 0; it < 4; it++) pa[it] = *(const uint4*)a_src[it];
#pragma unroll
    for (int it = 0; it < 2; it++) pb[it] = *(const uint4*)b_src[it];
#pragma unroll
    for (int it = 0; it < 4; it++) *(uint4*)&S[a_dst[it]] = pa[it];
#pragma unroll
    for (int it = 0; it < 2; it++) *(uint4*)&S[b_dst[it]] = pb[it];
    __syncthreads();

#pragma unroll 1
    for (int t = 0; t < 16; t++) {
        const unsigned stb = (t & 1) * (STAGE * 4);
        if (t + 1 < 16) {
            int ko = (t + 1) * 32;
#pragma unroll
            for (int it = 0; it < 4; it++) pa[it] = *(const uint4*)(a_src[it] + ko);
#pragma unroll
            for (int it = 0; it < 2; it++) pb[it] = *(const uint4*)(b_src[it] + ko);
        }
        tile_mma(acc, aBase0 + stb, bBase0 + stb, 2560 * 4, 1280 * 4);
        if (t + 1 < 16) {
            unsigned* Sn = S + ((t + 1) & 1) * STAGE;
#pragma unroll
            for (int it = 0; it < 4; it++) *(uint4*)&Sn[a_dst[it]] = pa[it];
#pragma unroll
            for (int it = 0; it < 2; it++) *(uint4*)&Sn[b_dst[it]] = pb[it];
            __syncthreads();
        }
    }
    __nv_bfloat16* dh = (__nv_bfloat16*)g_ah4;
    __nv_bfloat16* dl = (__nv_bfloat16*)g_al4;
#pragma unroll
    for (int mi = 0; mi < 2; mi++)
#pragma unroll
        for (int nj = 0; nj < 4; nj++)
#pragma unroll
            for (int rr = 0; rr < 4; rr++) {
                int m = bm + wm + mi * 16 + g + (rr >> 1) * 8;
                int n = wn + nj * 8 + tig * 2 + (rr & 1);
                split_store(acc[mi][nj][rr], dh, dl,
                            ((size_t)(b * SQ + m)) * HD + h * DHH + n);
            }
}

// ---------------- p2c transpose-gather-add: s0[q][k] += p2c[k][ip2c[k][q]] ----------------
__global__ void p2c_gather_kernel() {
    __shared__ float tile[32][33];
    int bh = blockIdx.z;
    int q0 = blockIdx.x * 32, k0 = blockIdx.y * 32;
    const float* pb = g_p2c + (size_t)bh * SQ * SQ;
    int tx = threadIdx.x, ty = threadIdx.y;  // (32, 8)
#pragma unroll
    for (int i = 0; i < 4; i++) {
        int k = k0 + ty + i * 8;
        int q = q0 + tx;
        int idx = g_ip2c[k * SQ + q];
        tile[ty + i * 8][tx] = pb[(size_t)k * SQ + idx];
    }
    __syncthreads();
    float* s = g_s0 + (size_t)bh * SQ * SQ;
#pragma unroll
    for (int i = 0; i < 4; i++) {
        int q = q0 + ty + i * 8;
        int k = k0 + tx;
        s[(size_t)q * SQ + k] += tile[tx][ty + i * 8];
    }
}

// ---------------- softmax (s0 already includes p2c term) -> split bf16 probs ----------------
__global__ void attn_softmax_kernel(const int* __restrict__ mask) {
    int q = blockIdx.x, bh = blockIdx.y, b = bh / NHH;
    int tid = threadIdx.x;
    const float* row = g_s0 + ((size_t)bh * SQ + q) * SQ;
    const float* crow = g_c2p + ((size_t)bh * SQ + q) * SQ;
    int mq = mask[b * SQ + q];
    float vals[2];
    float mx = -3.4028234663852886e38f;
#pragma unroll
    for (int t = 0; t < 2; t++) {
        int k = tid + t * 256;
        float v = -3.4028234663852886e38f;
        if (mq != 0 && mask[b * SQ + k] != 0) {
            v = (row[k] + crow[g_ic2p[q * SQ + k]]) * SCALEF;
        }
        vals[t] = v;
        mx = fmaxf(mx, v);
    }
    mx = blk_reduce_max(mx);
    float sum = 0.f;
#pragma unroll
    for (int t = 0; t < 2; t++) { vals[t] = expf(vals[t] - mx); sum += vals[t]; }
    sum = blk_reduce_sum(sum);
    float inv = 1.0f / sum;
    __nv_bfloat16* ph = (__nv_bfloat16*)g_ph4;
    __nv_bfloat16* pl = (__nv_bfloat16*)g_pl4;
#pragma unroll
    for (int t = 0; t < 2; t++) {
        float p = vals[t] * inv;
        size_t o = ((size_t)bh * SQ + q) * SQ + tid + t * 256;
        __nv_bfloat16 hh = __float2bfloat16(p);
        ph[o] = hh;
        pl[o] = __float2bfloat16(p - __bfloat162float(hh));
    }
}

// ---------------- SIMT SGEMM (cls head only, N=9) ----------------
__global__ void __launch_bounds__(256)
sgemm_kernel(const float* __restrict__ Bm, const float* __restrict__ bias,
             float* __restrict__ Cext, int M, int N, int K) {
    const float* A = g_x;
    __shared__ float As[16][68];
    __shared__ float Bs[16][68];
    int bm = blockIdx.y * 64, bn = blockIdx.x * 64;
    int tid = threadIdx.x;
    int tr = tid >> 4, tc = tid & 15;
    float acc[4][4] = {};
#pragma unroll 1
    for (int k0 = 0; k0 < K; k0 += 16) {
#pragma unroll
        for (int i = tid; i < 1024; i += 256) {
            int m = i >> 4, kk = i & 15;
            As[kk][m] = A[(size_t)(bm + m) * K + k0 + kk];
        }
#pragma unroll
        for (int i = tid; i < 1024; i += 256) {
            int kk = i >> 6, n = i & 63;
            Bs[kk][n] = (bn + n < N) ? Bm[(size_t)(k0 + kk) * N + bn + n] : 0.f;
        }
        __syncthreads();
#pragma unroll
        for (int kk = 0; kk < 16; kk++) {
            float4 a4 = *(const float4*)&As[kk][tr * 4];
            float4 b4 = *(const float4*)&Bs[kk][tc * 4];
            float a[4] = {a4.x, a4.y, a4.z, a4.w};
            float b[4] = {b4.x, b4.y, b4.z, b4.w};
#pragma unroll
            for (int i2 = 0; i2 < 4; i2++)
#pragma unroll
                for (int j = 0; j < 4; j++) acc[i2][j] += a[i2] * b[j];
        }
        __syncthreads();
    }
#pragma unroll
    for (int i2 = 0; i2 < 4; i2++) {
        int m = bm + tr * 4 + i2;
#pragma unroll
        for (int j = 0; j < 4; j++) {
            int n = bn + tc * 4 + j;
            if (n >= N) continue;
            Cext[(size_t)m * N + n] = acc[i2][j] + bias[n];
        }
    }
}

// ---------------- launch ----------------
extern "C" void kernel_launch(void* const* d_in, const int* in_sizes, int n_in,
                              void* d_out, int out_size) {
    const int*   ids     = (const int*)d_in[0];
    const int*   mask    = (const int*)d_in[1];
    const float* we      = (const float*)d_in[2];
    const float* te      = (const float*)d_in[3];
    const float* elns    = (const float*)d_in[4];
    const float* elnb    = (const float*)d_in[5];
    const float* rel_emb = (const float*)d_in[6];
    const float* rlns    = (const float*)d_in[7];
    const float* rlnb    = (const float*)d_in[8];
    const float* qw      = (const float*)d_in[9];
    const float* qb      = (const float*)d_in[10];
    const float* kw      = (const float*)d_in[11];
    const float* kb      = (const float*)d_in[12];
    const float* vw      = (const float*)d_in[13];
    const float* vb      = (const float*)d_in[14];
    const float* aow     = (const float*)d_in[15];
    const float* aob     = (const float*)d_in[16];
    const float* alns    = (const float*)d_in[17];
    const float* alnb    = (const float*)d_in[18];
    const float* iw      = (const float*)d_in[19];
    const float* ib      = (const float*)d_in[20];
    const float* ow      = (const float*)d_in[21];
    const float* ob      = (const float*)d_in[22];
    const float* olns    = (const float*)d_in[23];
    const float* olnb    = (const float*)d_in[24];
    const float* clsw    = (const float*)d_in[25];
    const float* clsb    = (const float*)d_in[26];
    float* out = (float*)d_out;

    const int DSM = 2 * STAGE * 4;  // 61440 bytes
    cudaFuncSetAttribute(tc_gemm_kernel<0>, cudaFuncAttributeMaxDynamicSharedMemorySize, DSM);
    cudaFuncSetAttribute(tc_gemm_kernel<1>, cudaFuncAttributeMaxDynamicSharedMemorySize, DSM);
    cudaFuncSetAttribute(tc_gemm_kernel<4>, cudaFuncAttributeMaxDynamicSharedMemorySize, DSM);
    cudaFuncSetAttribute(tc_gemm_kernel<5>, cudaFuncAttributeMaxDynamicSharedMemorySize, DSM);
    cudaFuncSetAttribute(tc_bgemm_ctx_kernel, cudaFuncAttributeMaxDynamicSharedMemorySize, DSM);

    relidx_kernel<<<1024, 256>>>();
    rel_ln_kernel<<<SQ, 256>>>(rel_emb, rlns, rlnb);       // fp32 + split bf16
    embed_ln_kernel<<<NTOK, 256>>>(ids, mask, we, te, elns, elnb);

    dim3 tb(32, 8);
    dim3 gTrans3(HD / 32, HD / 32, 3);
    dim3 gTransHH(HD / 32, HD / 32);
    dim3 gTransIF(FFD / 32, HD / 32);
    dim3 gTransOF(HD / 32, FFD / 32);

    dim3 gTcQKV(2304 / 128, NTOK / 64);
    dim3 gTcPos(1536 / 128, SQ / 64);
    dim3 gTcProj(HD / 128, NTOK / 64);
    dim3 gTcFF1(FFD / 128, NTOK / 64);
    dim3 gTcFF2(HD / 128, NTOK / 64);

    dim3 gScore(SQ / 128, SQ / 64, BHH);
    dim3 gGather(SQ / 32, SQ / 32, BHH);
    dim3 gSm(SQ, BHH);
    dim3 gCtx(SQ / 128, BHH);
    dim3 gCls(1, 32);

    for (int l = 0; l < NLAYER; l++) {
        const float* qwl = qw + (size_t)l * HD * HD;
        const float* kwl = kw + (size_t)l * HD * HD;
        const float* vwl = vw + (size_t)l * HD * HD;
        const float* aowl = aow + (size_t)l * HD * HD;
        const float* iwl = iw + (size_t)l * HD * FFD;
        const float* owl = ow + (size_t)l * FFD * HD;
        const float* qbl = qb + (size_t)l * HD;
        const float* kbl = kb + (size_t)l * HD;
        const float* vbl = vb + (size_t)l * HD;
        const float* aobl = aob + (size_t)l * HD;
        const float* ibl = ib + (size_t)l * FFD;
        const float* obl = ob + (size_t)l * HD;

        transb3_kernel<<<gTrans3, tb>>>(qwl, kwl, vwl);
        tc_gemm_kernel<4><<<gTcQKV, 256, DSM>>>(0, qbl, kbl, vbl, 0, NTOK, 2304, HD);
        tc_gemm_kernel<5><<<gTcPos, 256, DSM>>>(1, qbl, kbl, 0, 0, SQ, 1536, HD);

        tc_bgemm_nt_kernel<<<gScore, 256>>>(0, 1, 0, BHH);   // q @ k^T
        tc_bgemm_nt_kernel<<<gScore, 256>>>(0, 2, 1, NHH);   // q @ pk^T
        tc_bgemm_nt_kernel<<<gScore, 256>>>(1, 3, 2, NHH);   // k @ pq^T

        p2c_gather_kernel<<<gGather, tb>>>();
        attn_softmax_kernel<<<gSm, 256>>>(mask);

        tc_bgemm_ctx_kernel<<<gCtx, 256, DSM>>>();           // -> split bf16 ctx in g_ah4

        transb_kernel<<<gTransHH, tb>>>(aowl, HD, HD, 0);
        tc_gemm_kernel<0><<<gTcProj, 256, DSM>>>(0, aobl, 0, 0, BUF_T1, NTOK, HD, HD);
        add_ln_kernel<<<NTOK, 256>>>(BUF_T1, alns + (size_t)l * HD, alnb + (size_t)l * HD);

        transb_kernel<<<gTransIF, tb>>>(iwl, HD, FFD, 0);
        tc_gemm_kernel<1><<<gTcFF1, 256, DSM>>>(0, ibl, 0, 0, 0, NTOK, FFD, HD);

        transb_kernel<<<gTransOF, tb>>>(owl, FFD, HD, 0);
        tc_gemm_kernel<0><<<gTcFF2, 256, DSM>>>(2, obl, 0, 0, BUF_T2, NTOK, HD, FFD);
        add_ln_kernel<<<NTOK, 256>>>(BUF_T2, olns + (size_t)l * HD, olnb + (size_t)l * HD);
    }

    sgemm_kernel<<<gCls, 256>>>(clsw, clsb, out, NTOK, NCLS, HD);
}